// round 1
// baseline (speedup 1.0000x reference)
#include <cuda_runtime.h>
#include <math.h>

#define T 2048
#define H 1024
#define NH 16
#define NKV 4
#define D 64
#define E 8
#define F 1024
#define QKV_N ((NH + 2*NKV) * D)   // 1536
#define EPS 1e-5f
#define ATT_SCALE 0.125f           // D^-0.5

// ---------------- scratch (device globals; no allocation allowed) ----------
__device__ float g_h1[T * H];
__device__ float g_qkv[T * QKV_N];
__device__ float g_q[T * NH * D];
__device__ float g_k[T * NKV * D];
__device__ float g_ao[T * NH * D];
__device__ float g_h2[T * H];
__device__ float g_bufA[T * F];
__device__ float g_bufB[T * F];
__device__ int   g_eidx[T];
__device__ float g_gate[T];
__device__ int   g_perm[T];
__device__ int   g_count[E];
__device__ int   g_base[E];
__device__ int   g_offs[E];

// ---------------- small utility kernels ------------------------------------
__global__ void zero_kernel() {
    if (threadIdx.x < E) g_count[threadIdx.x] = 0;
}

__global__ void scan_kernel() {
    if (threadIdx.x == 0) {
        int b = 0;
        for (int e = 0; e < E; e++) { g_base[e] = b; b += g_count[e]; g_offs[e] = 0; }
    }
}

__global__ void scatter_kernel() {
    int t = blockIdx.x * blockDim.x + threadIdx.x;
    if (t < T) {
        int e = g_eidx[t];
        int p = g_base[e] + atomicAdd(&g_offs[e], 1);
        g_perm[p] = t;
    }
}

__global__ void silumul_kernel(float* __restrict__ a, const float* __restrict__ b, int n) {
    int i = blockIdx.x * blockDim.x + threadIdx.x;
    if (i < n) {
        float x = a[i];
        a[i] = x / (1.f + expf(-x)) * b[i];
    }
}

// ---------------- rmsnorm (row = block, 256 threads, H=1024) ---------------
__global__ void rmsnorm_kernel(const float* __restrict__ in, const float* __restrict__ w,
                               float* __restrict__ out) {
    int row = blockIdx.x, tid = threadIdx.x;
    const float* p = in + (size_t)row * H;
    float v[4];
    float s = 0.f;
#pragma unroll
    for (int i = 0; i < 4; i++) { v[i] = p[tid + i * 256]; s += v[i] * v[i]; }
#pragma unroll
    for (int off = 16; off; off >>= 1) s += __shfl_xor_sync(0xffffffffu, s, off);
    __shared__ float sw[8];
    if ((tid & 31) == 0) sw[tid >> 5] = s;
    __syncthreads();
    __shared__ float stot;
    if (tid == 0) {
        float t2 = 0.f;
        for (int i = 0; i < 8; i++) t2 += sw[i];
        stot = t2;
    }
    __syncthreads();
    float r = rsqrtf(stot / (float)H + EPS);
    float* o = out + (size_t)row * H;
#pragma unroll
    for (int i = 0; i < 4; i++) o[tid + i * 256] = v[i] * r * w[tid + i * 256];
}

// ---------------- generic tiled SGEMM: C[M,N] = A[M,K]@B[K,N] (+addsrc) ----
// block 256 threads, tile 64x64, K-tile 16, 4x4 micro-tile
__global__ void gemm64(const float* __restrict__ A, const float* __restrict__ B,
                       float* __restrict__ C, int M, int N, int K,
                       const float* __restrict__ addsrc) {
    __shared__ float As[16][64];
    __shared__ float Bs[16][64];
    int tid = threadIdx.x;
    int tx = tid & 15, ty = tid >> 4;
    int m0 = blockIdx.y * 64, n0 = blockIdx.x * 64;
    int ar = tid >> 2, ak = (tid & 3) * 4;
    int bk = tid >> 4, bc = (tid & 15) * 4;
    float acc[4][4] = {};
    for (int kk = 0; kk < K; kk += 16) {
        float4 av = *(const float4*)(A + (size_t)(m0 + ar) * K + kk + ak);
        As[ak + 0][ar] = av.x; As[ak + 1][ar] = av.y;
        As[ak + 2][ar] = av.z; As[ak + 3][ar] = av.w;
        float4 bv = *(const float4*)(B + (size_t)(kk + bk) * N + n0 + bc);
        *(float4*)&Bs[bk][bc] = bv;
        __syncthreads();
#pragma unroll
        for (int k = 0; k < 16; k++) {
            float4 a4 = *(const float4*)&As[k][ty * 4];
            float4 b4 = *(const float4*)&Bs[k][tx * 4];
            float a[4] = {a4.x, a4.y, a4.z, a4.w};
            float b[4] = {b4.x, b4.y, b4.z, b4.w};
#pragma unroll
            for (int i = 0; i < 4; i++)
#pragma unroll
                for (int j = 0; j < 4; j++) acc[i][j] += a[i] * b[j];
        }
        __syncthreads();
    }
#pragma unroll
    for (int i = 0; i < 4; i++) {
        int m = m0 + ty * 4 + i;
#pragma unroll
        for (int j = 0; j < 4; j++) {
            int n = n0 + tx * 4 + j;
            float v = acc[i][j];
            if (addsrc) v += addsrc[(size_t)m * N + n];
            C[(size_t)m * N + n] = v;
        }
    }
}

// ---------------- rope + per-head rmsnorm on q,k ---------------------------
// grid: (T, NH+NKV), block 64
__global__ void rope_rms_kernel(const int* __restrict__ pos) {
    int t = blockIdx.x, h = blockIdx.y, d = threadIdx.x;
    const float* src;
    float* dst;
    if (h < NH) {
        src = g_qkv + (size_t)t * QKV_N + h * D;
        dst = g_q + (size_t)t * (NH * D) + h * D;
    } else {
        int kh = h - NH;
        src = g_qkv + (size_t)t * QKV_N + NH * D + kh * D;
        dst = g_k + (size_t)t * (NKV * D) + kh * D;
    }
    int i = d & 31;
    float inv = powf(500000.0f, -((float)i) / 32.0f);
    float ang = (float)pos[t] * inv;
    float sn, cs;
    sincosf(ang, &sn, &cs);
    float x1 = src[i], x2 = src[i + 32];
    float val = (d < 32) ? (x1 * cs - x2 * sn) : (x2 * cs + x1 * sn);
    float sq = val * val;
#pragma unroll
    for (int off = 16; off; off >>= 1) sq += __shfl_xor_sync(0xffffffffu, sq, off);
    __shared__ float sw2[2];
    if ((d & 31) == 0) sw2[d >> 5] = sq;
    __syncthreads();
    float tot = sw2[0] + sw2[1];
    dst[d] = val * rsqrtf(tot / (float)D + EPS);
}

// ---------------- flash attention (BM=BN=64, causal, GQA) ------------------
// grid: (T/64, NH), block 256 (16x16 threads, 4x4 micro-tiles)
__global__ void attn_kernel() {
    __shared__ float QsT[D * 64];   // [d][r] (transposed: conflict-free reads)
    __shared__ float KVs[64 * D];   // K phase: [d][c] transposed; V phase: [c][oc]
    __shared__ float Ss[64 * 64];   // P tile
    int qt = blockIdx.x, head = blockIdx.y;
    int kvh = head >> 2;
    int tid = threadIdx.x;
    int tx = tid & 15, ty = tid >> 4;
    int q0 = qt * 64;
    for (int e = tid; e < 64 * 64; e += 256) {
        int r = e >> 6, d = e & 63;
        QsT[d * 64 + r] = g_q[(size_t)(q0 + r) * (NH * D) + head * D + d];
    }
    float m[4], l[4], accO[4][4];
#pragma unroll
    for (int i = 0; i < 4; i++) {
        m[i] = -INFINITY; l[i] = 0.f;
#pragma unroll
        for (int j = 0; j < 4; j++) accO[i][j] = 0.f;
    }
    for (int j0 = 0; j0 <= qt; j0++) {
        int k0 = j0 * 64;
        __syncthreads();
        for (int e = tid; e < 64 * 64; e += 256) {
            int c = e >> 6, d = e & 63;
            KVs[d * 64 + c] = g_k[(size_t)(k0 + c) * (NKV * D) + kvh * D + d];
        }
        __syncthreads();
        float sc[4][4] = {};
#pragma unroll 8
        for (int k = 0; k < 64; k++) {
            float4 a4 = *(const float4*)&QsT[k * 64 + ty * 4];
            float4 b4 = *(const float4*)&KVs[k * 64 + tx * 4];
            float a[4] = {a4.x, a4.y, a4.z, a4.w};
            float b[4] = {b4.x, b4.y, b4.z, b4.w};
#pragma unroll
            for (int i = 0; i < 4; i++)
#pragma unroll
                for (int j = 0; j < 4; j++) sc[i][j] += a[i] * b[j];
        }
#pragma unroll
        for (int i = 0; i < 4; i++) {
            int qr = q0 + ty * 4 + i;
            float rmax = -INFINITY;
#pragma unroll
            for (int j = 0; j < 4; j++) {
                int kc = k0 + tx * 4 + j;
                float v = (kc <= qr) ? sc[i][j] * ATT_SCALE : -INFINITY;
                sc[i][j] = v;
                rmax = fmaxf(rmax, v);
            }
#pragma unroll
            for (int off = 8; off; off >>= 1)
                rmax = fmaxf(rmax, __shfl_xor_sync(0xffffffffu, rmax, off));
            float nm = fmaxf(m[i], rmax);
            float corr = expf(m[i] - nm);
            m[i] = nm;
            float rs = 0.f;
#pragma unroll
            for (int j = 0; j < 4; j++) {
                float p = expf(sc[i][j] - nm);
                sc[i][j] = p;
                rs += p;
            }
#pragma unroll
            for (int off = 8; off; off >>= 1) rs += __shfl_xor_sync(0xffffffffu, rs, off);
            l[i] = l[i] * corr + rs;
#pragma unroll
            for (int j = 0; j < 4; j++) accO[i][j] *= corr;
#pragma unroll
            for (int j = 0; j < 4; j++) Ss[(ty * 4 + i) * 64 + tx * 4 + j] = sc[i][j];
        }
        __syncthreads();
        for (int e = tid; e < 64 * 64; e += 256) {
            int c = e >> 6, d = e & 63;
            KVs[c * 64 + d] = g_qkv[(size_t)(k0 + c) * QKV_N + (NH + NKV) * D + kvh * D + d];
        }
        __syncthreads();
#pragma unroll 8
        for (int c = 0; c < 64; c++) {
            float pv[4], vv[4];
#pragma unroll
            for (int i = 0; i < 4; i++) pv[i] = Ss[(ty * 4 + i) * 64 + c];
            float4 v4 = *(const float4*)&KVs[c * 64 + tx * 4];
            vv[0] = v4.x; vv[1] = v4.y; vv[2] = v4.z; vv[3] = v4.w;
#pragma unroll
            for (int i = 0; i < 4; i++)
#pragma unroll
                for (int j = 0; j < 4; j++) accO[i][j] += pv[i] * vv[j];
        }
    }
#pragma unroll
    for (int i = 0; i < 4; i++) {
        float inv = 1.f / l[i];
        int r = q0 + ty * 4 + i;
#pragma unroll
        for (int j = 0; j < 4; j++)
            g_ao[(size_t)r * (NH * D) + head * D + tx * 4 + j] = accO[i][j] * inv;
    }
}

// ---------------- router: logits + top-1 + sigmoid gate --------------------
__global__ void router_kernel(const float* __restrict__ rw) {
    int t = blockIdx.x, tid = threadIdx.x;
    float acc[E] = {};
    const float* p = g_h2 + (size_t)t * H;
    for (int h = tid; h < H; h += 256) {
        float x = p[h];
        const float* r = rw + (size_t)h * E;
#pragma unroll
        for (int e = 0; e < E; e++) acc[e] += x * r[e];
    }
#pragma unroll
    for (int e = 0; e < E; e++)
#pragma unroll
        for (int off = 16; off; off >>= 1)
            acc[e] += __shfl_xor_sync(0xffffffffu, acc[e], off);
    __shared__ float sred[8][E];
    int w = tid >> 5, lane = tid & 31;
    if (lane == 0)
        for (int e = 0; e < E; e++) sred[w][e] = acc[e];
    __syncthreads();
    if (tid == 0) {
        float best = -INFINITY;
        int bi = 0;
        for (int e = 0; e < E; e++) {
            float v = 0.f;
            for (int ww = 0; ww < 8; ww++) v += sred[ww][e];
            if (v > best) { best = v; bi = e; }   // strict >: first index wins ties (jax top_k)
        }
        g_eidx[t] = bi;
        g_gate[t] = 1.f / (1.f + expf(-best));
        atomicAdd(&g_count[bi], 1);
    }
}

// ---------------- grouped GEMM: x_in(gathered) @ W[e] -> Cbuf --------------
// grid: (F/64, T/64, E) block 256
__global__ void ggemm_proj(const float* __restrict__ Wall, float* __restrict__ Cbuf) {
    int e = blockIdx.z;
    int cnt = g_count[e];
    int m0 = blockIdx.y * 64;
    if (m0 >= cnt) return;
    int n0 = blockIdx.x * 64;
    __shared__ float As[16][64];
    __shared__ float Bs[16][64];
    __shared__ int rtok[64];
    __shared__ float rg[64];
    int tid = threadIdx.x;
    if (tid < 64) {
        int mm = m0 + tid;
        int tok = (mm < cnt) ? g_perm[g_base[e] + mm] : -1;
        rtok[tid] = tok;
        rg[tid] = (tok >= 0) ? g_gate[tok] : 0.f;
    }
    __syncthreads();
    int tx = tid & 15, ty = tid >> 4;
    int ar = tid >> 2, ak = (tid & 3) * 4;
    int bk = tid >> 4, bc = (tid & 15) * 4;
    const float* B = Wall + (size_t)e * H * F;
    int tok = rtok[ar];
    float gsc = rg[ar];
    float acc[4][4] = {};
    for (int kk = 0; kk < H; kk += 16) {
        float4 av = make_float4(0.f, 0.f, 0.f, 0.f);
        if (tok >= 0) av = *(const float4*)(g_h2 + (size_t)tok * H + kk + ak);
        As[ak + 0][ar] = av.x * gsc; As[ak + 1][ar] = av.y * gsc;
        As[ak + 2][ar] = av.z * gsc; As[ak + 3][ar] = av.w * gsc;
        float4 bv = *(const float4*)(B + (size_t)(kk + bk) * F + n0 + bc);
        *(float4*)&Bs[bk][bc] = bv;
        __syncthreads();
#pragma unroll
        for (int k = 0; k < 16; k++) {
            float4 a4 = *(const float4*)&As[k][ty * 4];
            float4 b4 = *(const float4*)&Bs[k][tx * 4];
            float a[4] = {a4.x, a4.y, a4.z, a4.w};
            float b[4] = {b4.x, b4.y, b4.z, b4.w};
#pragma unroll
            for (int i = 0; i < 4; i++)
#pragma unroll
                for (int j = 0; j < 4; j++) acc[i][j] += a[i] * b[j];
        }
        __syncthreads();
    }
#pragma unroll
    for (int i = 0; i < 4; i++) {
        int mm = m0 + ty * 4 + i;
        if (mm < cnt) {
#pragma unroll
            for (int j = 0; j < 4; j++)
                Cbuf[(size_t)(g_base[e] + mm) * F + n0 + tx * 4 + j] = acc[i][j];
        }
    }
}

// ---------------- grouped down GEMM: g(gathered-contig) @ Wd[e] += out -----
__global__ void ggemm_down(const float* __restrict__ Wall, float* __restrict__ out) {
    int e = blockIdx.z;
    int cnt = g_count[e];
    int m0 = blockIdx.y * 64;
    if (m0 >= cnt) return;
    int n0 = blockIdx.x * 64;
    __shared__ float As[16][64];
    __shared__ float Bs[16][64];
    __shared__ int rtok[64];
    int tid = threadIdx.x;
    if (tid < 64) {
        int mm = m0 + tid;
        rtok[tid] = (mm < cnt) ? g_perm[g_base[e] + mm] : -1;
    }
    __syncthreads();
    int tx = tid & 15, ty = tid >> 4;
    int ar = tid >> 2, ak = (tid & 3) * 4;
    int bk = tid >> 4, bc = (tid & 15) * 4;
    const float* B = Wall + (size_t)e * F * H;
    const float* Abase = g_bufA + (size_t)(g_base[e] + m0) * F;
    bool arow_ok = (m0 + ar) < cnt;
    float acc[4][4] = {};
    for (int kk = 0; kk < F; kk += 16) {
        float4 av = arow_ok ? *(const float4*)(Abase + (size_t)ar * F + kk + ak)
                            : make_float4(0.f, 0.f, 0.f, 0.f);
        As[ak + 0][ar] = av.x; As[ak + 1][ar] = av.y;
        As[ak + 2][ar] = av.z; As[ak + 3][ar] = av.w;
        float4 bv = *(const float4*)(B + (size_t)(kk + bk) * H + n0 + bc);
        *(float4*)&Bs[bk][bc] = bv;
        __syncthreads();
#pragma unroll
        for (int k = 0; k < 16; k++) {
            float4 a4 = *(const float4*)&As[k][ty * 4];
            float4 b4 = *(const float4*)&Bs[k][tx * 4];
            float a[4] = {a4.x, a4.y, a4.z, a4.w};
            float b[4] = {b4.x, b4.y, b4.z, b4.w};
#pragma unroll
            for (int i = 0; i < 4; i++)
#pragma unroll
                for (int j = 0; j < 4; j++) acc[i][j] += a[i] * b[j];
        }
        __syncthreads();
    }
#pragma unroll
    for (int i = 0; i < 4; i++) {
        int mm = m0 + ty * 4 + i;
        if (mm < cnt) {
            int t = rtok[ty * 4 + i];
#pragma unroll
            for (int j = 0; j < 4; j++)
                out[(size_t)t * H + n0 + tx * 4 + j] += acc[i][j];
        }
    }
}

// ---------------- launch ---------------------------------------------------
extern "C" void kernel_launch(void* const* d_in, const int* in_sizes, int n_in,
                              void* d_out, int out_size) {
    const int* pos = (const int*)d_in[0];
    const float* hidden = (const float*)d_in[1];
    const float* ln1 = (const float*)d_in[2];
    const float* ln2 = (const float*)d_in[3];
    const float* wqkv = (const float*)d_in[4];
    const float* wo = (const float*)d_in[5];
    const float* rw = (const float*)d_in[6];
    const float* wgate = (const float*)d_in[7];
    const float* wup = (const float*)d_in[8];
    const float* wdown = (const float*)d_in[9];
    const float* shg = (const float*)d_in[10];
    const float* shu = (const float*)d_in[11];
    const float* shd = (const float*)d_in[12];
    float* out = (float*)d_out;
    float* resid = out + (size_t)T * H;

    float *p_h1, *p_h2, *p_bufA, *p_bufB;
    cudaGetSymbolAddress((void**)&p_h1, g_h1);
    cudaGetSymbolAddress((void**)&p_h2, g_h2);
    cudaGetSymbolAddress((void**)&p_bufA, g_bufA);
    cudaGetSymbolAddress((void**)&p_bufB, g_bufB);
    float *p_qkv, *p_ao;
    cudaGetSymbolAddress((void**)&p_qkv, g_qkv);
    cudaGetSymbolAddress((void**)&p_ao, g_ao);

    zero_kernel<<<1, 32>>>();
    // 1) rmsnorm1
    rmsnorm_kernel<<<T, 256>>>(hidden, ln1, p_h1);
    // 2) qkv projection
    gemm64<<<dim3(QKV_N / 64, T / 64), 256>>>(p_h1, wqkv, p_qkv, T, QKV_N, H, nullptr);
    // 3) rope + qk rmsnorm
    rope_rms_kernel<<<dim3(T, NH + NKV), 64>>>(pos);
    // 4) attention
    attn_kernel<<<dim3(T / 64, NH), 256>>>();
    // 5) o-proj + residual -> resid (second half of d_out)
    gemm64<<<dim3(H / 64, T / 64), 256>>>(p_ao, wo, resid, T, H, NH * D, hidden);
    // 6) rmsnorm2
    rmsnorm_kernel<<<T, 256>>>(resid, ln2, p_h2);
    // 7) router + expert grouping
    router_kernel<<<T, 256>>>(rw);
    scan_kernel<<<1, 32>>>();
    scatter_kernel<<<T / 256, 256>>>();
    // 8) shared expert: silu(h2@shg) * (h2@shu) @ shd -> out (plain write)
    gemm64<<<dim3(F / 64, T / 64), 256>>>(p_h2, shg, p_bufA, T, F, H, nullptr);
    gemm64<<<dim3(F / 64, T / 64), 256>>>(p_h2, shu, p_bufB, T, F, H, nullptr);
    silumul_kernel<<<(T * F) / 256, 256>>>(p_bufA, p_bufB, T * F);
    gemm64<<<dim3(H / 64, T / 64), 256>>>(p_bufA, shd, out, T, H, F, nullptr);
    // 9) routed expert (grouped by expert, gathered rows, gate-scaled on load)
    ggemm_proj<<<dim3(F / 64, T / 64, E), 256>>>(wgate, p_bufA);
    ggemm_proj<<<dim3(F / 64, T / 64, E), 256>>>(wup, p_bufB);
    silumul_kernel<<<(T * F) / 256, 256>>>(p_bufA, p_bufB, T * F);
    ggemm_down<<<dim3(H / 64, T / 64, E), 256>>>(wdown, out);
    (void)in_sizes; (void)n_in; (void)out_size;
}

// round 2
// speedup vs baseline: 1.0785x; 1.0785x over previous
#include <cuda_runtime.h>
#include <math.h>

#define T 2048
#define H 1024
#define NH 16
#define NKV 4
#define D 64
#define E 8
#define F 1024
#define QKV_N ((NH + 2*NKV) * D)   // 1536
#define EPS 1e-5f
#define ATT_SCALE 0.125f           // D^-0.5

// ---------------- scratch (device globals; no allocation allowed) ----------
__device__ float g_h1[T * H];
__device__ float g_qkv[T * QKV_N];
__device__ float g_q[T * NH * D];
__device__ float g_k[T * NKV * D];
__device__ float g_ao[T * NH * D];
__device__ float g_h2[T * H];
__device__ float g_bufA[T * F];
__device__ float g_bufB[T * F];
__device__ int   g_eidx[T];
__device__ float g_gate[T];
__device__ int   g_perm[T];
__device__ int   g_count[E];
__device__ int   g_base[E];
__device__ int   g_offs[E];

// ---------------- small utility kernels ------------------------------------
__global__ void zero_kernel() {
    if (threadIdx.x < E) g_count[threadIdx.x] = 0;
}

__global__ void scan_kernel() {
    if (threadIdx.x == 0) {
        int b = 0;
        for (int e = 0; e < E; e++) { g_base[e] = b; b += g_count[e]; g_offs[e] = 0; }
    }
}

__global__ void scatter_kernel() {
    int t = blockIdx.x * blockDim.x + threadIdx.x;
    if (t < T) {
        int e = g_eidx[t];
        int p = g_base[e] + atomicAdd(&g_offs[e], 1);
        g_perm[p] = t;
    }
}

__global__ void silumul_kernel(float* __restrict__ a, const float* __restrict__ b, int n) {
    int i = blockIdx.x * blockDim.x + threadIdx.x;
    if (i < n) {
        float x = a[i];
        a[i] = x / (1.f + expf(-x)) * b[i];
    }
}

// ---------------- rmsnorm (row = block, 256 threads, H=1024) ---------------
__global__ void rmsnorm_kernel(const float* __restrict__ in, const float* __restrict__ w,
                               float* __restrict__ out) {
    int row = blockIdx.x, tid = threadIdx.x;
    const float* p = in + (size_t)row * H;
    float v[4];
    float s = 0.f;
#pragma unroll
    for (int i = 0; i < 4; i++) { v[i] = p[tid + i * 256]; s += v[i] * v[i]; }
#pragma unroll
    for (int off = 16; off; off >>= 1) s += __shfl_xor_sync(0xffffffffu, s, off);
    __shared__ float sw[8];
    if ((tid & 31) == 0) sw[tid >> 5] = s;
    __syncthreads();
    __shared__ float stot;
    if (tid == 0) {
        float t2 = 0.f;
        for (int i = 0; i < 8; i++) t2 += sw[i];
        stot = t2;
    }
    __syncthreads();
    float r = rsqrtf(stot / (float)H + EPS);
    float* o = out + (size_t)row * H;
#pragma unroll
    for (int i = 0; i < 4; i++) o[tid + i * 256] = v[i] * r * w[tid + i * 256];
}

// ============= 128x128x8 double-buffered SGEMM, 8x8 micro-tile ==============
// block 256 threads (16x16). As stored transposed [k][m], padded stride 136.
#define SMS 136
__global__ __launch_bounds__(256)
void gemm128(const float* __restrict__ A, const float* __restrict__ B,
             float* __restrict__ C, int M, int N, int K,
             const float* __restrict__ addsrc) {
    __shared__ float As[2][8 * SMS];
    __shared__ float Bs[2][8 * SMS];
    int tid = threadIdx.x;
    int m0 = blockIdx.y * 128, n0 = blockIdx.x * 128;
    int tx = tid & 15, ty = tid >> 4;
    int a_row = tid >> 1, a_col = (tid & 1) * 4;
    int b_row = tid >> 5, b_col = (tid & 31) * 4;
    float acc[8][8] = {};

    const float* Aptr = A + (size_t)(m0 + a_row) * K + a_col;
    const float* Bptr = B + (size_t)b_row * N + n0 + b_col;

    float4 av = *(const float4*)Aptr;
    float4 bv = *(const float4*)Bptr;
    As[0][(a_col + 0) * SMS + a_row] = av.x;
    As[0][(a_col + 1) * SMS + a_row] = av.y;
    As[0][(a_col + 2) * SMS + a_row] = av.z;
    As[0][(a_col + 3) * SMS + a_row] = av.w;
    *(float4*)&Bs[0][b_row * SMS + b_col] = bv;
    __syncthreads();

    int nt = K >> 3;
    int buf = 0;
    for (int kt = 0; kt < nt; kt++) {
        if (kt + 1 < nt) {
            av = *(const float4*)(Aptr + (kt + 1) * 8);
            bv = *(const float4*)(Bptr + (size_t)(kt + 1) * 8 * N);
        }
#pragma unroll
        for (int k = 0; k < 8; k++) {
            float a[8], b[8];
            *(float4*)&a[0] = *(const float4*)&As[buf][k * SMS + ty * 4];
            *(float4*)&a[4] = *(const float4*)&As[buf][k * SMS + 64 + ty * 4];
            *(float4*)&b[0] = *(const float4*)&Bs[buf][k * SMS + tx * 4];
            *(float4*)&b[4] = *(const float4*)&Bs[buf][k * SMS + 64 + tx * 4];
#pragma unroll
            for (int i = 0; i < 8; i++)
#pragma unroll
                for (int j = 0; j < 8; j++) acc[i][j] += a[i] * b[j];
        }
        if (kt + 1 < nt) {
            int nb = buf ^ 1;
            As[nb][(a_col + 0) * SMS + a_row] = av.x;
            As[nb][(a_col + 1) * SMS + a_row] = av.y;
            As[nb][(a_col + 2) * SMS + a_row] = av.z;
            As[nb][(a_col + 3) * SMS + a_row] = av.w;
            *(float4*)&Bs[nb][b_row * SMS + b_col] = bv;
        }
        __syncthreads();
        buf ^= 1;
    }
#pragma unroll
    for (int i = 0; i < 8; i++) {
        int m = m0 + ((i < 4) ? (ty * 4 + i) : (64 + ty * 4 + i - 4));
#pragma unroll
        for (int jh = 0; jh < 2; jh++) {
            int n = n0 + jh * 64 + tx * 4;
            float4 v;
            v.x = acc[i][jh * 4 + 0]; v.y = acc[i][jh * 4 + 1];
            v.z = acc[i][jh * 4 + 2]; v.w = acc[i][jh * 4 + 3];
            if (addsrc) {
                float4 r = *(const float4*)(addsrc + (size_t)m * N + n);
                v.x += r.x; v.y += r.y; v.z += r.z; v.w += r.w;
            }
            *(float4*)(C + (size_t)m * N + n) = v;
        }
    }
}

// ---------------- rope + per-head rmsnorm on q,k (4 heads / block) ---------
// grid: (T, 5), block 256
__global__ void rope_rms_kernel(const int* __restrict__ pos) {
    int t = blockIdx.x;
    int grp = threadIdx.x >> 6;          // 0..3
    int d = threadIdx.x & 63;
    int h = blockIdx.y * 4 + grp;        // 0..19
    const float* src;
    float* dst;
    if (h < NH) {
        src = g_qkv + (size_t)t * QKV_N + h * D;
        dst = g_q + (size_t)t * (NH * D) + h * D;
    } else {
        int kh = h - NH;
        src = g_qkv + (size_t)t * QKV_N + NH * D + kh * D;
        dst = g_k + (size_t)t * (NKV * D) + kh * D;
    }
    int i = d & 31;
    float inv = powf(500000.0f, -((float)i) / 32.0f);
    float ang = (float)pos[t] * inv;
    float sn, cs;
    sincosf(ang, &sn, &cs);
    float x1 = src[i], x2 = src[i + 32];
    float val = (d < 32) ? (x1 * cs - x2 * sn) : (x2 * cs + x1 * sn);
    float sq = val * val;
#pragma unroll
    for (int off = 16; off; off >>= 1) sq += __shfl_xor_sync(0xffffffffu, sq, off);
    __shared__ float sw2[4][2];
    if ((d & 31) == 0) sw2[grp][d >> 5] = sq;
    __syncthreads();
    float tot = sw2[grp][0] + sw2[grp][1];
    dst[d] = val * rsqrtf(tot / (float)D + EPS);
}

// ---------------- flash attention (BM=BN=64, causal, GQA) ------------------
// grid: (T/64, NH), block 256 (16x16 threads, 4x4 micro-tiles)
__global__ void attn_kernel() {
    __shared__ float QsT[D * 64];   // [d][r]
    __shared__ float KVs[64 * D];   // K phase: [d][c]; V phase: [c][oc]
    __shared__ float Ss[64 * 64];
    int qt = blockIdx.x, head = blockIdx.y;
    int kvh = head >> 2;
    int tid = threadIdx.x;
    int tx = tid & 15, ty = tid >> 4;
    int q0 = qt * 64;
    for (int e = tid; e < 64 * 64; e += 256) {
        int r = e >> 6, d = e & 63;
        QsT[d * 64 + r] = g_q[(size_t)(q0 + r) * (NH * D) + head * D + d];
    }
    float m[4], l[4], accO[4][4];
#pragma unroll
    for (int i = 0; i < 4; i++) {
        m[i] = -INFINITY; l[i] = 0.f;
#pragma unroll
        for (int j = 0; j < 4; j++) accO[i][j] = 0.f;
    }
    for (int j0 = 0; j0 <= qt; j0++) {
        int k0 = j0 * 64;
        __syncthreads();
        for (int e = tid; e < 64 * 64; e += 256) {
            int c = e >> 6, d = e & 63;
            KVs[d * 64 + c] = g_k[(size_t)(k0 + c) * (NKV * D) + kvh * D + d];
        }
        __syncthreads();
        float sc[4][4] = {};
#pragma unroll 8
        for (int k = 0; k < 64; k++) {
            float4 a4 = *(const float4*)&QsT[k * 64 + ty * 4];
            float4 b4 = *(const float4*)&KVs[k * 64 + tx * 4];
            float a[4] = {a4.x, a4.y, a4.z, a4.w};
            float b[4] = {b4.x, b4.y, b4.z, b4.w};
#pragma unroll
            for (int i = 0; i < 4; i++)
#pragma unroll
                for (int j = 0; j < 4; j++) sc[i][j] += a[i] * b[j];
        }
#pragma unroll
        for (int i = 0; i < 4; i++) {
            int qr = q0 + ty * 4 + i;
            float rmax = -INFINITY;
#pragma unroll
            for (int j = 0; j < 4; j++) {
                int kc = k0 + tx * 4 + j;
                float v = (kc <= qr) ? sc[i][j] * ATT_SCALE : -INFINITY;
                sc[i][j] = v;
                rmax = fmaxf(rmax, v);
            }
#pragma unroll
            for (int off = 8; off; off >>= 1)
                rmax = fmaxf(rmax, __shfl_xor_sync(0xffffffffu, rmax, off));
            float nm = fmaxf(m[i], rmax);
            float corr = expf(m[i] - nm);
            m[i] = nm;
            float rs = 0.f;
#pragma unroll
            for (int j = 0; j < 4; j++) {
                float p = expf(sc[i][j] - nm);
                sc[i][j] = p;
                rs += p;
            }
#pragma unroll
            for (int off = 8; off; off >>= 1) rs += __shfl_xor_sync(0xffffffffu, rs, off);
            l[i] = l[i] * corr + rs;
#pragma unroll
            for (int j = 0; j < 4; j++) accO[i][j] *= corr;
#pragma unroll
            for (int j = 0; j < 4; j++) Ss[(ty * 4 + i) * 64 + tx * 4 + j] = sc[i][j];
        }
        __syncthreads();
        for (int e = tid; e < 64 * 64; e += 256) {
            int c = e >> 6, d = e & 63;
            KVs[c * 64 + d] = g_qkv[(size_t)(k0 + c) * QKV_N + (NH + NKV) * D + kvh * D + d];
        }
        __syncthreads();
#pragma unroll 8
        for (int c = 0; c < 64; c++) {
            float pv[4], vv[4];
#pragma unroll
            for (int i = 0; i < 4; i++) pv[i] = Ss[(ty * 4 + i) * 64 + c];
            float4 v4 = *(const float4*)&KVs[c * 64 + tx * 4];
            vv[0] = v4.x; vv[1] = v4.y; vv[2] = v4.z; vv[3] = v4.w;
#pragma unroll
            for (int i = 0; i < 4; i++)
#pragma unroll
                for (int j = 0; j < 4; j++) accO[i][j] += pv[i] * vv[j];
        }
    }
#pragma unroll
    for (int i = 0; i < 4; i++) {
        float inv = 1.f / l[i];
        int r = q0 + ty * 4 + i;
#pragma unroll
        for (int j = 0; j < 4; j++)
            g_ao[(size_t)r * (NH * D) + head * D + tx * 4 + j] = accO[i][j] * inv;
    }
}

// ---------------- router: logits + top-1 + sigmoid gate --------------------
__global__ void router_kernel(const float* __restrict__ rw) {
    int t = blockIdx.x, tid = threadIdx.x;
    float acc[E] = {};
    const float* p = g_h2 + (size_t)t * H;
    for (int h = tid; h < H; h += 256) {
        float x = p[h];
        const float* r = rw + (size_t)h * E;
#pragma unroll
        for (int e = 0; e < E; e++) acc[e] += x * r[e];
    }
#pragma unroll
    for (int e = 0; e < E; e++)
#pragma unroll
        for (int off = 16; off; off >>= 1)
            acc[e] += __shfl_xor_sync(0xffffffffu, acc[e], off);
    __shared__ float sred[8][E];
    int w = tid >> 5, lane = tid & 31;
    if (lane == 0)
        for (int e = 0; e < E; e++) sred[w][e] = acc[e];
    __syncthreads();
    if (tid == 0) {
        float best = -INFINITY;
        int bi = 0;
        for (int e = 0; e < E; e++) {
            float v = 0.f;
            for (int ww = 0; ww < 8; ww++) v += sred[ww][e];
            if (v > best) { best = v; bi = e; }
        }
        g_eidx[t] = bi;
        g_gate[t] = 1.f / (1.f + expf(-best));
        atomicAdd(&g_count[bi], 1);
    }
}

// ============ grouped 128x128x8 GEMM: gathered rows, gate-scaled ============
// grid: (N/128, T/128, E)
__global__ __launch_bounds__(256)
void ggemm_proj128(const float* __restrict__ Wall, float* __restrict__ Cbuf) {
    int e = blockIdx.z;
    int cnt = g_count[e];
    int m0 = blockIdx.y * 128;
    if (m0 >= cnt) return;
    int n0 = blockIdx.x * 128;
    __shared__ float As[2][8 * SMS];
    __shared__ float Bs[2][8 * SMS];
    __shared__ int srcrow[128];
    int tid = threadIdx.x;
    if (tid < 128) {
        int mm = m0 + tid;
        srcrow[tid] = (mm < cnt) ? g_perm[g_base[e] + mm] : -1;
    }
    __syncthreads();
    int tx = tid & 15, ty = tid >> 4;
    int a_row = tid >> 1, a_col = (tid & 1) * 4;
    int b_row = tid >> 5, b_col = (tid & 31) * 4;
    const float* B = Wall + (size_t)e * H * F;
    int tok = srcrow[a_row];
    float gsc = (tok >= 0) ? g_gate[tok] : 0.f;
    const float* Aptr = (tok >= 0) ? (g_h2 + (size_t)tok * H + a_col) : g_h2;
    const float* Bptr = B + (size_t)b_row * F + n0 + b_col;
    float acc[8][8] = {};

    float4 av = *(const float4*)Aptr;
    float4 bv = *(const float4*)Bptr;
    As[0][(a_col + 0) * SMS + a_row] = av.x * gsc;
    As[0][(a_col + 1) * SMS + a_row] = av.y * gsc;
    As[0][(a_col + 2) * SMS + a_row] = av.z * gsc;
    As[0][(a_col + 3) * SMS + a_row] = av.w * gsc;
    *(float4*)&Bs[0][b_row * SMS + b_col] = bv;
    __syncthreads();
    int nt = H >> 3;
    int buf = 0;
    for (int kt = 0; kt < nt; kt++) {
        if (kt + 1 < nt) {
            av = *(const float4*)(Aptr + (kt + 1) * 8);
            bv = *(const float4*)(Bptr + (size_t)(kt + 1) * 8 * F);
        }
#pragma unroll
        for (int k = 0; k < 8; k++) {
            float a[8], b[8];
            *(float4*)&a[0] = *(const float4*)&As[buf][k * SMS + ty * 4];
            *(float4*)&a[4] = *(const float4*)&As[buf][k * SMS + 64 + ty * 4];
            *(float4*)&b[0] = *(const float4*)&Bs[buf][k * SMS + tx * 4];
            *(float4*)&b[4] = *(const float4*)&Bs[buf][k * SMS + 64 + tx * 4];
#pragma unroll
            for (int i = 0; i < 8; i++)
#pragma unroll
                for (int j = 0; j < 8; j++) acc[i][j] += a[i] * b[j];
        }
        if (kt + 1 < nt) {
            int nb = buf ^ 1;
            As[nb][(a_col + 0) * SMS + a_row] = av.x * gsc;
            As[nb][(a_col + 1) * SMS + a_row] = av.y * gsc;
            As[nb][(a_col + 2) * SMS + a_row] = av.z * gsc;
            As[nb][(a_col + 3) * SMS + a_row] = av.w * gsc;
            *(float4*)&Bs[nb][b_row * SMS + b_col] = bv;
        }
        __syncthreads();
        buf ^= 1;
    }
#pragma unroll
    for (int i = 0; i < 8; i++) {
        int mm = m0 + ((i < 4) ? (ty * 4 + i) : (64 + ty * 4 + i - 4));
        if (mm < cnt) {
#pragma unroll
            for (int jh = 0; jh < 2; jh++) {
                int n = n0 + jh * 64 + tx * 4;
                float4 v;
                v.x = acc[i][jh * 4 + 0]; v.y = acc[i][jh * 4 + 1];
                v.z = acc[i][jh * 4 + 2]; v.w = acc[i][jh * 4 + 3];
                *(float4*)(Cbuf + (size_t)(g_base[e] + mm) * F + n) = v;
            }
        }
    }
}

// grouped down GEMM: contiguous gathered A (g_bufA), scatter += to out
__global__ __launch_bounds__(256)
void ggemm_down128(const float* __restrict__ Wall, float* __restrict__ out) {
    int e = blockIdx.z;
    int cnt = g_count[e];
    int m0 = blockIdx.y * 128;
    if (m0 >= cnt) return;
    int n0 = blockIdx.x * 128;
    __shared__ float As[2][8 * SMS];
    __shared__ float Bs[2][8 * SMS];
    __shared__ int rtok[128];
    int tid = threadIdx.x;
    if (tid < 128) {
        int mm = m0 + tid;
        rtok[tid] = (mm < cnt) ? g_perm[g_base[e] + mm] : -1;
    }
    __syncthreads();
    int tx = tid & 15, ty = tid >> 4;
    int a_row = tid >> 1, a_col = (tid & 1) * 4;
    int b_row = tid >> 5, b_col = (tid & 31) * 4;
    const float* B = Wall + (size_t)e * F * H;
    bool arow_ok = (m0 + a_row) < cnt;
    const float* Aptr = g_bufA + (size_t)(g_base[e] + (arow_ok ? (m0 + a_row) : 0)) * F + a_col;
    const float* Bptr = B + (size_t)b_row * H + n0 + b_col;
    float amask = arow_ok ? 1.f : 0.f;
    float acc[8][8] = {};

    float4 av = *(const float4*)Aptr;
    float4 bv = *(const float4*)Bptr;
    As[0][(a_col + 0) * SMS + a_row] = av.x * amask;
    As[0][(a_col + 1) * SMS + a_row] = av.y * amask;
    As[0][(a_col + 2) * SMS + a_row] = av.z * amask;
    As[0][(a_col + 3) * SMS + a_row] = av.w * amask;
    *(float4*)&Bs[0][b_row * SMS + b_col] = bv;
    __syncthreads();
    int nt = F >> 3;
    int buf = 0;
    for (int kt = 0; kt < nt; kt++) {
        if (kt + 1 < nt) {
            av = *(const float4*)(Aptr + (kt + 1) * 8);
            bv = *(const float4*)(Bptr + (size_t)(kt + 1) * 8 * H);
        }
#pragma unroll
        for (int k = 0; k < 8; k++) {
            float a[8], b[8];
            *(float4*)&a[0] = *(const float4*)&As[buf][k * SMS + ty * 4];
            *(float4*)&a[4] = *(const float4*)&As[buf][k * SMS + 64 + ty * 4];
            *(float4*)&b[0] = *(const float4*)&Bs[buf][k * SMS + tx * 4];
            *(float4*)&b[4] = *(const float4*)&Bs[buf][k * SMS + 64 + tx * 4];
#pragma unroll
            for (int i = 0; i < 8; i++)
#pragma unroll
                for (int j = 0; j < 8; j++) acc[i][j] += a[i] * b[j];
        }
        if (kt + 1 < nt) {
            int nb = buf ^ 1;
            As[nb][(a_col + 0) * SMS + a_row] = av.x * amask;
            As[nb][(a_col + 1) * SMS + a_row] = av.y * amask;
            As[nb][(a_col + 2) * SMS + a_row] = av.z * amask;
            As[nb][(a_col + 3) * SMS + a_row] = av.w * amask;
            *(float4*)&Bs[nb][b_row * SMS + b_col] = bv;
        }
        __syncthreads();
        buf ^= 1;
    }
#pragma unroll
    for (int i = 0; i < 8; i++) {
        int mi = (i < 4) ? (ty * 4 + i) : (64 + ty * 4 + i - 4);
        int mm = m0 + mi;
        if (mm < cnt) {
            int t = rtok[mi];
#pragma unroll
            for (int jh = 0; jh < 2; jh++) {
                int n = n0 + jh * 64 + tx * 4;
                float4 r = *(const float4*)(out + (size_t)t * H + n);
                r.x += acc[i][jh * 4 + 0]; r.y += acc[i][jh * 4 + 1];
                r.z += acc[i][jh * 4 + 2]; r.w += acc[i][jh * 4 + 3];
                *(float4*)(out + (size_t)t * H + n) = r;
            }
        }
    }
}

// ---------------- launch ---------------------------------------------------
extern "C" void kernel_launch(void* const* d_in, const int* in_sizes, int n_in,
                              void* d_out, int out_size) {
    const int* pos = (const int*)d_in[0];
    const float* hidden = (const float*)d_in[1];
    const float* ln1 = (const float*)d_in[2];
    const float* ln2 = (const float*)d_in[3];
    const float* wqkv = (const float*)d_in[4];
    const float* wo = (const float*)d_in[5];
    const float* rw = (const float*)d_in[6];
    const float* wgate = (const float*)d_in[7];
    const float* wup = (const float*)d_in[8];
    const float* wdown = (const float*)d_in[9];
    const float* shg = (const float*)d_in[10];
    const float* shu = (const float*)d_in[11];
    const float* shd = (const float*)d_in[12];
    float* out = (float*)d_out;
    float* resid = out + (size_t)T * H;

    float *p_h1, *p_h2, *p_bufA, *p_bufB, *p_qkv, *p_ao;
    cudaGetSymbolAddress((void**)&p_h1, g_h1);
    cudaGetSymbolAddress((void**)&p_h2, g_h2);
    cudaGetSymbolAddress((void**)&p_bufA, g_bufA);
    cudaGetSymbolAddress((void**)&p_bufB, g_bufB);
    cudaGetSymbolAddress((void**)&p_qkv, g_qkv);
    cudaGetSymbolAddress((void**)&p_ao, g_ao);

    zero_kernel<<<1, 32>>>();
    rmsnorm_kernel<<<T, 256>>>(hidden, ln1, p_h1);
    gemm128<<<dim3(QKV_N / 128, T / 128), 256>>>(p_h1, wqkv, p_qkv, T, QKV_N, H, nullptr);
    rope_rms_kernel<<<dim3(T, 5), 256>>>(pos);
    attn_kernel<<<dim3(T / 64, NH), 256>>>();
    gemm128<<<dim3(H / 128, T / 128), 256>>>(p_ao, wo, resid, T, H, NH * D, hidden);
    rmsnorm_kernel<<<T, 256>>>(resid, ln2, p_h2);
    router_kernel<<<T, 256>>>(rw);
    scan_kernel<<<1, 32>>>();
    scatter_kernel<<<T / 256, 256>>>();
    // shared expert
    gemm128<<<dim3(F / 128, T / 128), 256>>>(p_h2, shg, p_bufA, T, F, H, nullptr);
    gemm128<<<dim3(F / 128, T / 128), 256>>>(p_h2, shu, p_bufB, T, F, H, nullptr);
    silumul_kernel<<<(T * F) / 256, 256>>>(p_bufA, p_bufB, T * F);
    gemm128<<<dim3(H / 128, T / 128), 256>>>(p_bufA, shd, out, T, H, F, nullptr);
    // routed expert
    ggemm_proj128<<<dim3(F / 128, T / 128, E), 256>>>(wgate, p_bufA);
    ggemm_proj128<<<dim3(F / 128, T / 128, E), 256>>>(wup, p_bufB);
    silumul_kernel<<<(T * F) / 256, 256>>>(p_bufA, p_bufB, T * F);
    ggemm_down128<<<dim3(H / 128, T / 128, E), 256>>>(wdown, out);
    (void)in_sizes; (void)n_in; (void)out_size;
}

// round 4
// speedup vs baseline: 1.6819x; 1.5595x over previous
#include <cuda_runtime.h>
#include <math.h>

#define T 2048
#define H 1024
#define NH 16
#define NKV 4
#define D 64
#define E 8
#define F 1024
#define QKV_N ((NH + 2*NKV) * D)   // 1536
#define EPS 1e-5f
#define ATT_SCALE 0.125f

// ---------------- scratch ---------------------------------------------------
__device__ float g_h1[T * H];
__device__ float g_qkv[T * QKV_N];
__device__ float g_q[T * NH * D];
__device__ float g_k[T * NKV * D];
__device__ float g_ao[T * NH * D];
__device__ float g_h2[T * H];
__device__ float g_bufA[T * F];
__device__ float g_bufB[T * F];
__device__ int   g_eidx[T];
__device__ float g_gate[T];
__device__ int   g_perm[T];
__device__ int   g_count[E];
__device__ int   g_base[E];
__device__ int   g_offs[E];

// ---------------- small utility kernels -------------------------------------
__global__ void zero_kernel() {
    if (threadIdx.x < E) g_count[threadIdx.x] = 0;
}
__global__ void scan_kernel() {
    if (threadIdx.x == 0) {
        int b = 0;
        for (int e = 0; e < E; e++) { g_base[e] = b; b += g_count[e]; g_offs[e] = 0; }
    }
}
__global__ void scatter_kernel() {
    int t = blockIdx.x * blockDim.x + threadIdx.x;
    if (t < T) {
        int e = g_eidx[t];
        int p = g_base[e] + atomicAdd(&g_offs[e], 1);
        g_perm[p] = t;
    }
}
__global__ void silumul_kernel(float* __restrict__ a, const float* __restrict__ b, int n) {
    int i = blockIdx.x * blockDim.x + threadIdx.x;
    if (i < n) {
        float x = a[i];
        a[i] = x / (1.f + expf(-x)) * b[i];
    }
}

// ---------------- rmsnorm ----------------------------------------------------
__global__ void rmsnorm_kernel(const float* __restrict__ in, const float* __restrict__ w,
                               float* __restrict__ out) {
    int row = blockIdx.x, tid = threadIdx.x;
    const float* p = in + (size_t)row * H;
    float v[4];
    float s = 0.f;
#pragma unroll
    for (int i = 0; i < 4; i++) { v[i] = p[tid + i * 256]; s += v[i] * v[i]; }
#pragma unroll
    for (int off = 16; off; off >>= 1) s += __shfl_xor_sync(0xffffffffu, s, off);
    __shared__ float sw[8];
    if ((tid & 31) == 0) sw[tid >> 5] = s;
    __syncthreads();
    __shared__ float stot;
    if (tid == 0) {
        float t2 = 0.f;
        for (int i = 0; i < 8; i++) t2 += sw[i];
        stot = t2;
    }
    __syncthreads();
    float r = rsqrtf(stot / (float)H + EPS);
    float* o = out + (size_t)row * H;
#pragma unroll
    for (int i = 0; i < 4; i++) o[tid + i * 256] = v[i] * r * w[tid + i * 256];
}

// =================== TF32 tensor-core GEMM machinery ========================
__device__ __forceinline__ unsigned f2tf(float x) {
    unsigned r;
    asm("cvt.rna.tf32.f32 %0, %1;" : "=r"(r) : "f"(x));
    return r;
}
__device__ __forceinline__ void mma_tf32(float* c, const unsigned* a, const unsigned* b) {
    asm volatile(
        "mma.sync.aligned.m16n8k8.row.col.f32.tf32.tf32.f32 "
        "{%0,%1,%2,%3},{%4,%5,%6,%7},{%8,%9},{%0,%1,%2,%3};"
        : "+f"(c[0]), "+f"(c[1]), "+f"(c[2]), "+f"(c[3])
        : "r"(a[0]), "r"(a[1]), "r"(a[2]), "r"(a[3]), "r"(b[0]), "r"(b[1]));
}

#define KT 16
#define SMS 136

// shared mainloop body: fragments from As [k][m] / Bs [k][n], acc[4][4][4]
#define MMA_TILE_COMPUTE(Asb, Bsb)                                             \
    _Pragma("unroll")                                                          \
    for (int k8 = 0; k8 < KT; k8 += 8) {                                       \
        unsigned af[4][4], bf[4][2];                                           \
        _Pragma("unroll")                                                      \
        for (int mt = 0; mt < 4; mt++) {                                       \
            int mb = wm + mt * 16;                                             \
            af[mt][0] = Asb[(k8 + tg) * SMS + mb + g];                         \
            af[mt][1] = Asb[(k8 + tg) * SMS + mb + g + 8];                     \
            af[mt][2] = Asb[(k8 + tg + 4) * SMS + mb + g];                     \
            af[mt][3] = Asb[(k8 + tg + 4) * SMS + mb + g + 8];                 \
        }                                                                      \
        _Pragma("unroll")                                                      \
        for (int nt2 = 0; nt2 < 4; nt2++) {                                    \
            int nb = wn + nt2 * 8;                                             \
            bf[nt2][0] = Bsb[(k8 + tg) * SMS + nb + g];                        \
            bf[nt2][1] = Bsb[(k8 + tg + 4) * SMS + nb + g];                    \
        }                                                                      \
        _Pragma("unroll")                                                      \
        for (int mt = 0; mt < 4; mt++)                                         \
            _Pragma("unroll")                                                  \
            for (int nt2 = 0; nt2 < 4; nt2++)                                  \
                mma_tf32(acc[mt][nt2], af[mt], bf[nt2]);                       \
    }

// ---------------- dense tf32 GEMM: C = A[M,K]@B[K,N] (+addsrc) --------------
__global__ __launch_bounds__(256)
void gemm_tf32(const float* __restrict__ A, const float* __restrict__ B,
               float* __restrict__ C, int M, int N, int K,
               const float* __restrict__ addsrc) {
    __shared__ unsigned As[2][KT * SMS];
    __shared__ unsigned Bs[2][KT * SMS];
    int tid = threadIdx.x;
    int warp = tid >> 5, lane = tid & 31;
    int g = lane >> 2, tg = lane & 3;
    int wm = (warp >> 2) * 64, wn = (warp & 3) * 32;
    int m0 = blockIdx.y * 128, n0 = blockIdx.x * 128;
    int arow = tid >> 1, acol = (tid & 1) * 8;
    int bk = tid >> 4, bn = (tid & 15) * 8;
    const float* Ap = A + (size_t)(m0 + arow) * K + acol;
    const float* Bp = B + (size_t)bk * N + n0 + bn;
    float acc[4][4][4] = {};

    float4 av0 = *(const float4*)Ap, av1 = *(const float4*)(Ap + 4);
    float4 bv0 = *(const float4*)Bp, bv1 = *(const float4*)(Bp + 4);
    {
        unsigned* ad = As[0];
        ad[(acol + 0) * SMS + arow] = f2tf(av0.x);
        ad[(acol + 1) * SMS + arow] = f2tf(av0.y);
        ad[(acol + 2) * SMS + arow] = f2tf(av0.z);
        ad[(acol + 3) * SMS + arow] = f2tf(av0.w);
        ad[(acol + 4) * SMS + arow] = f2tf(av1.x);
        ad[(acol + 5) * SMS + arow] = f2tf(av1.y);
        ad[(acol + 6) * SMS + arow] = f2tf(av1.z);
        ad[(acol + 7) * SMS + arow] = f2tf(av1.w);
        unsigned* bd = Bs[0] + bk * SMS + bn;
        bd[0] = f2tf(bv0.x); bd[1] = f2tf(bv0.y); bd[2] = f2tf(bv0.z); bd[3] = f2tf(bv0.w);
        bd[4] = f2tf(bv1.x); bd[5] = f2tf(bv1.y); bd[6] = f2tf(bv1.z); bd[7] = f2tf(bv1.w);
    }
    __syncthreads();
    int nt = K / KT;
    int buf = 0;
    for (int kt = 0; kt < nt; kt++) {
        if (kt + 1 < nt) {
            av0 = *(const float4*)(Ap + (kt + 1) * KT);
            av1 = *(const float4*)(Ap + (kt + 1) * KT + 4);
            bv0 = *(const float4*)(Bp + (size_t)(kt + 1) * KT * N);
            bv1 = *(const float4*)(Bp + (size_t)(kt + 1) * KT * N + 4);
        }
        const unsigned* Asb = As[buf];
        const unsigned* Bsb = Bs[buf];
        MMA_TILE_COMPUTE(Asb, Bsb)
        if (kt + 1 < nt) {
            unsigned* ad = As[buf ^ 1];
            ad[(acol + 0) * SMS + arow] = f2tf(av0.x);
            ad[(acol + 1) * SMS + arow] = f2tf(av0.y);
            ad[(acol + 2) * SMS + arow] = f2tf(av0.z);
            ad[(acol + 3) * SMS + arow] = f2tf(av0.w);
            ad[(acol + 4) * SMS + arow] = f2tf(av1.x);
            ad[(acol + 5) * SMS + arow] = f2tf(av1.y);
            ad[(acol + 6) * SMS + arow] = f2tf(av1.z);
            ad[(acol + 7) * SMS + arow] = f2tf(av1.w);
            unsigned* bd = Bs[buf ^ 1] + bk * SMS + bn;
            bd[0] = f2tf(bv0.x); bd[1] = f2tf(bv0.y); bd[2] = f2tf(bv0.z); bd[3] = f2tf(bv0.w);
            bd[4] = f2tf(bv1.x); bd[5] = f2tf(bv1.y); bd[6] = f2tf(bv1.z); bd[7] = f2tf(bv1.w);
        }
        __syncthreads();
        buf ^= 1;
    }
#pragma unroll
    for (int mt = 0; mt < 4; mt++) {
#pragma unroll
        for (int nt2 = 0; nt2 < 4; nt2++) {
            int r0 = m0 + wm + mt * 16 + g;
            int c = n0 + wn + nt2 * 8 + 2 * tg;
            float2 v0 = make_float2(acc[mt][nt2][0], acc[mt][nt2][1]);
            float2 v1 = make_float2(acc[mt][nt2][2], acc[mt][nt2][3]);
            if (addsrc) {
                float2 r = *(const float2*)(addsrc + (size_t)r0 * N + c);
                v0.x += r.x; v0.y += r.y;
                float2 r2 = *(const float2*)(addsrc + (size_t)(r0 + 8) * N + c);
                v1.x += r2.x; v1.y += r2.y;
            }
            *(float2*)(C + (size_t)r0 * N + c) = v0;
            *(float2*)(C + (size_t)(r0 + 8) * N + c) = v1;
        }
    }
}

// ---------------- grouped tf32 GEMM (gather + gate): h2[perm] @ W[e] --------
// grid (F/128, T/128, E)
__global__ __launch_bounds__(256)
void ggemm_proj_tf32(const float* __restrict__ Wall, float* __restrict__ Cbuf) {
    int e = blockIdx.z;
    int cnt = g_count[e];
    int m0 = blockIdx.y * 128;
    if (m0 >= cnt) return;
    int n0 = blockIdx.x * 128;
    __shared__ unsigned As[2][KT * SMS];
    __shared__ unsigned Bs[2][KT * SMS];
    __shared__ int srcrow[128];
    int tid = threadIdx.x;
    if (tid < 128) {
        int mm = m0 + tid;
        srcrow[tid] = (mm < cnt) ? g_perm[g_base[e] + mm] : -1;
    }
    __syncthreads();
    int warp = tid >> 5, lane = tid & 31;
    int g = lane >> 2, tg = lane & 3;
    int wm = (warp >> 2) * 64, wn = (warp & 3) * 32;
    int arow = tid >> 1, acol = (tid & 1) * 8;
    int bk = tid >> 4, bn = (tid & 15) * 8;
    int tok = srcrow[arow];
    float gsc = (tok >= 0) ? g_gate[tok] : 0.f;
    const float* Ap = g_h2 + (size_t)((tok >= 0) ? tok : 0) * H + acol;
    const float* Bp = Wall + (size_t)e * H * F + (size_t)bk * F + n0 + bn;
    float acc[4][4][4] = {};

    float4 av0 = *(const float4*)Ap, av1 = *(const float4*)(Ap + 4);
    float4 bv0 = *(const float4*)Bp, bv1 = *(const float4*)(Bp + 4);
    {
        unsigned* ad = As[0];
        ad[(acol + 0) * SMS + arow] = f2tf(av0.x * gsc);
        ad[(acol + 1) * SMS + arow] = f2tf(av0.y * gsc);
        ad[(acol + 2) * SMS + arow] = f2tf(av0.z * gsc);
        ad[(acol + 3) * SMS + arow] = f2tf(av0.w * gsc);
        ad[(acol + 4) * SMS + arow] = f2tf(av1.x * gsc);
        ad[(acol + 5) * SMS + arow] = f2tf(av1.y * gsc);
        ad[(acol + 6) * SMS + arow] = f2tf(av1.z * gsc);
        ad[(acol + 7) * SMS + arow] = f2tf(av1.w * gsc);
        unsigned* bd = Bs[0] + bk * SMS + bn;
        bd[0] = f2tf(bv0.x); bd[1] = f2tf(bv0.y); bd[2] = f2tf(bv0.z); bd[3] = f2tf(bv0.w);
        bd[4] = f2tf(bv1.x); bd[5] = f2tf(bv1.y); bd[6] = f2tf(bv1.z); bd[7] = f2tf(bv1.w);
    }
    __syncthreads();
    int nt = H / KT;
    int buf = 0;
    for (int kt = 0; kt < nt; kt++) {
        if (kt + 1 < nt) {
            av0 = *(const float4*)(Ap + (kt + 1) * KT);
            av1 = *(const float4*)(Ap + (kt + 1) * KT + 4);
            bv0 = *(const float4*)(Bp + (size_t)(kt + 1) * KT * F);
            bv1 = *(const float4*)(Bp + (size_t)(kt + 1) * KT * F + 4);
        }
        const unsigned* Asb = As[buf];
        const unsigned* Bsb = Bs[buf];
        MMA_TILE_COMPUTE(Asb, Bsb)
        if (kt + 1 < nt) {
            unsigned* ad = As[buf ^ 1];
            ad[(acol + 0) * SMS + arow] = f2tf(av0.x * gsc);
            ad[(acol + 1) * SMS + arow] = f2tf(av0.y * gsc);
            ad[(acol + 2) * SMS + arow] = f2tf(av0.z * gsc);
            ad[(acol + 3) * SMS + arow] = f2tf(av0.w * gsc);
            ad[(acol + 4) * SMS + arow] = f2tf(av1.x * gsc);
            ad[(acol + 5) * SMS + arow] = f2tf(av1.y * gsc);
            ad[(acol + 6) * SMS + arow] = f2tf(av1.z * gsc);
            ad[(acol + 7) * SMS + arow] = f2tf(av1.w * gsc);
            unsigned* bd = Bs[buf ^ 1] + bk * SMS + bn;
            bd[0] = f2tf(bv0.x); bd[1] = f2tf(bv0.y); bd[2] = f2tf(bv0.z); bd[3] = f2tf(bv0.w);
            bd[4] = f2tf(bv1.x); bd[5] = f2tf(bv1.y); bd[6] = f2tf(bv1.z); bd[7] = f2tf(bv1.w);
        }
        __syncthreads();
        buf ^= 1;
    }
#pragma unroll
    for (int mt = 0; mt < 4; mt++) {
#pragma unroll
        for (int nt2 = 0; nt2 < 4; nt2++) {
            int mi0 = wm + mt * 16 + g;
            int c = n0 + wn + nt2 * 8 + 2 * tg;
            if (m0 + mi0 < cnt)
                *(float2*)(Cbuf + (size_t)(g_base[e] + m0 + mi0) * F + c) =
                    make_float2(acc[mt][nt2][0], acc[mt][nt2][1]);
            if (m0 + mi0 + 8 < cnt)
                *(float2*)(Cbuf + (size_t)(g_base[e] + m0 + mi0 + 8) * F + c) =
                    make_float2(acc[mt][nt2][2], acc[mt][nt2][3]);
        }
    }
}

// ---------------- grouped down tf32 GEMM: bufA(contig) @ Wd[e] += out -------
__global__ __launch_bounds__(256)
void ggemm_down_tf32(const float* __restrict__ Wall, float* __restrict__ out) {
    int e = blockIdx.z;
    int cnt = g_count[e];
    int m0 = blockIdx.y * 128;
    if (m0 >= cnt) return;
    int n0 = blockIdx.x * 128;
    __shared__ unsigned As[2][KT * SMS];
    __shared__ unsigned Bs[2][KT * SMS];
    __shared__ int rtok[128];
    int tid = threadIdx.x;
    if (tid < 128) {
        int mm = m0 + tid;
        rtok[tid] = (mm < cnt) ? g_perm[g_base[e] + mm] : -1;
    }
    __syncthreads();
    int warp = tid >> 5, lane = tid & 31;
    int g = lane >> 2, tg = lane & 3;
    int wm = (warp >> 2) * 64, wn = (warp & 3) * 32;
    int arow = tid >> 1, acol = (tid & 1) * 8;
    int bk = tid >> 4, bn = (tid & 15) * 8;
    bool arow_ok = (m0 + arow) < cnt;
    float amask = arow_ok ? 1.f : 0.f;
    const float* Ap = g_bufA + (size_t)(g_base[e] + (arow_ok ? (m0 + arow) : 0)) * F + acol;
    const float* Bp = Wall + (size_t)e * F * H + (size_t)bk * H + n0 + bn;
    float acc[4][4][4] = {};

    float4 av0 = *(const float4*)Ap, av1 = *(const float4*)(Ap + 4);
    float4 bv0 = *(const float4*)Bp, bv1 = *(const float4*)(Bp + 4);
    {
        unsigned* ad = As[0];
        ad[(acol + 0) * SMS + arow] = f2tf(av0.x * amask);
        ad[(acol + 1) * SMS + arow] = f2tf(av0.y * amask);
        ad[(acol + 2) * SMS + arow] = f2tf(av0.z * amask);
        ad[(acol + 3) * SMS + arow] = f2tf(av0.w * amask);
        ad[(acol + 4) * SMS + arow] = f2tf(av1.x * amask);
        ad[(acol + 5) * SMS + arow] = f2tf(av1.y * amask);
        ad[(acol + 6) * SMS + arow] = f2tf(av1.z * amask);
        ad[(acol + 7) * SMS + arow] = f2tf(av1.w * amask);
        unsigned* bd = Bs[0] + bk * SMS + bn;
        bd[0] = f2tf(bv0.x); bd[1] = f2tf(bv0.y); bd[2] = f2tf(bv0.z); bd[3] = f2tf(bv0.w);
        bd[4] = f2tf(bv1.x); bd[5] = f2tf(bv1.y); bd[6] = f2tf(bv1.z); bd[7] = f2tf(bv1.w);
    }
    __syncthreads();
    int nt = F / KT;
    int buf = 0;
    for (int kt = 0; kt < nt; kt++) {
        if (kt + 1 < nt) {
            av0 = *(const float4*)(Ap + (kt + 1) * KT);
            av1 = *(const float4*)(Ap + (kt + 1) * KT + 4);
            bv0 = *(const float4*)(Bp + (size_t)(kt + 1) * KT * H);
            bv1 = *(const float4*)(Bp + (size_t)(kt + 1) * KT * H + 4);
        }
        const unsigned* Asb = As[buf];
        const unsigned* Bsb = Bs[buf];
        MMA_TILE_COMPUTE(Asb, Bsb)
        if (kt + 1 < nt) {
            unsigned* ad = As[buf ^ 1];
            ad[(acol + 0) * SMS + arow] = f2tf(av0.x * amask);
            ad[(acol + 1) * SMS + arow] = f2tf(av0.y * amask);
            ad[(acol + 2) * SMS + arow] = f2tf(av0.z * amask);
            ad[(acol + 3) * SMS + arow] = f2tf(av0.w * amask);
            ad[(acol + 4) * SMS + arow] = f2tf(av1.x * amask);
            ad[(acol + 5) * SMS + arow] = f2tf(av1.y * amask);
            ad[(acol + 6) * SMS + arow] = f2tf(av1.z * amask);
            ad[(acol + 7) * SMS + arow] = f2tf(av1.w * amask);
            unsigned* bd = Bs[buf ^ 1] + bk * SMS + bn;
            bd[0] = f2tf(bv0.x); bd[1] = f2tf(bv0.y); bd[2] = f2tf(bv0.z); bd[3] = f2tf(bv0.w);
            bd[4] = f2tf(bv1.x); bd[5] = f2tf(bv1.y); bd[6] = f2tf(bv1.z); bd[7] = f2tf(bv1.w);
        }
        __syncthreads();
        buf ^= 1;
    }
#pragma unroll
    for (int mt = 0; mt < 4; mt++) {
#pragma unroll
        for (int nt2 = 0; nt2 < 4; nt2++) {
            int mi0 = wm + mt * 16 + g;
            int c = n0 + wn + nt2 * 8 + 2 * tg;
            if (m0 + mi0 < cnt) {
                int t = rtok[mi0];
                float2 r = *(const float2*)(out + (size_t)t * H + c);
                r.x += acc[mt][nt2][0]; r.y += acc[mt][nt2][1];
                *(float2*)(out + (size_t)t * H + c) = r;
            }
            if (m0 + mi0 + 8 < cnt) {
                int t = rtok[mi0 + 8];
                float2 r = *(const float2*)(out + (size_t)t * H + c);
                r.x += acc[mt][nt2][2]; r.y += acc[mt][nt2][3];
                *(float2*)(out + (size_t)t * H + c) = r;
            }
        }
    }
}

// ---------------- rope + per-head rmsnorm -----------------------------------
__global__ void rope_rms_kernel(const int* __restrict__ pos) {
    int t = blockIdx.x;
    int grp = threadIdx.x >> 6;
    int d = threadIdx.x & 63;
    int h = blockIdx.y * 4 + grp;
    const float* src;
    float* dst;
    if (h < NH) {
        src = g_qkv + (size_t)t * QKV_N + h * D;
        dst = g_q + (size_t)t * (NH * D) + h * D;
    } else {
        int kh = h - NH;
        src = g_qkv + (size_t)t * QKV_N + NH * D + kh * D;
        dst = g_k + (size_t)t * (NKV * D) + kh * D;
    }
    int i = d & 31;
    float inv = powf(500000.0f, -((float)i) / 32.0f);
    float ang = (float)pos[t] * inv;
    float sn, cs;
    sincosf(ang, &sn, &cs);
    float x1 = src[i], x2 = src[i + 32];
    float val = (d < 32) ? (x1 * cs - x2 * sn) : (x2 * cs + x1 * sn);
    float sq = val * val;
#pragma unroll
    for (int off = 16; off; off >>= 1) sq += __shfl_xor_sync(0xffffffffu, sq, off);
    __shared__ float sw2[4][2];
    if ((d & 31) == 0) sw2[grp][d >> 5] = sq;
    __syncthreads();
    float tot = sw2[grp][0] + sw2[grp][1];
    dst[d] = val * rsqrtf(tot / (float)D + EPS);
}

// ---------------- flash attention (unchanged this round) --------------------
__global__ void attn_kernel() {
    __shared__ float QsT[D * 64];
    __shared__ float KVs[64 * D];
    __shared__ float Ss[64 * 64];
    int qt = blockIdx.x, head = blockIdx.y;
    int kvh = head >> 2;
    int tid = threadIdx.x;
    int tx = tid & 15, ty = tid >> 4;
    int q0 = qt * 64;
    for (int e = tid; e < 64 * 64; e += 256) {
        int r = e >> 6, d = e & 63;
        QsT[d * 64 + r] = g_q[(size_t)(q0 + r) * (NH * D) + head * D + d];
    }
    float m[4], l[4], accO[4][4];
#pragma unroll
    for (int i = 0; i < 4; i++) {
        m[i] = -INFINITY; l[i] = 0.f;
#pragma unroll
        for (int j = 0; j < 4; j++) accO[i][j] = 0.f;
    }
    for (int j0 = 0; j0 <= qt; j0++) {
        int k0 = j0 * 64;
        __syncthreads();
        for (int e = tid; e < 64 * 64; e += 256) {
            int c = e >> 6, d = e & 63;
            KVs[d * 64 + c] = g_k[(size_t)(k0 + c) * (NKV * D) + kvh * D + d];
        }
        __syncthreads();
        float sc[4][4] = {};
#pragma unroll 8
        for (int k = 0; k < 64; k++) {
            float4 a4 = *(const float4*)&QsT[k * 64 + ty * 4];
            float4 b4 = *(const float4*)&KVs[k * 64 + tx * 4];
            float a[4] = {a4.x, a4.y, a4.z, a4.w};
            float b[4] = {b4.x, b4.y, b4.z, b4.w};
#pragma unroll
            for (int i = 0; i < 4; i++)
#pragma unroll
                for (int j = 0; j < 4; j++) sc[i][j] += a[i] * b[j];
        }
#pragma unroll
        for (int i = 0; i < 4; i++) {
            int qr = q0 + ty * 4 + i;
            float rmax = -INFINITY;
#pragma unroll
            for (int j = 0; j < 4; j++) {
                int kc = k0 + tx * 4 + j;
                float v = (kc <= qr) ? sc[i][j] * ATT_SCALE : -INFINITY;
                sc[i][j] = v;
                rmax = fmaxf(rmax, v);
            }
#pragma unroll
            for (int off = 8; off; off >>= 1)
                rmax = fmaxf(rmax, __shfl_xor_sync(0xffffffffu, rmax, off));
            float nm = fmaxf(m[i], rmax);
            float corr = expf(m[i] - nm);
            m[i] = nm;
            float rs = 0.f;
#pragma unroll
            for (int j = 0; j < 4; j++) {
                float p = expf(sc[i][j] - nm);
                sc[i][j] = p;
                rs += p;
            }
#pragma unroll
            for (int off = 8; off; off >>= 1) rs += __shfl_xor_sync(0xffffffffu, rs, off);
            l[i] = l[i] * corr + rs;
#pragma unroll
            for (int j = 0; j < 4; j++) accO[i][j] *= corr;
#pragma unroll
            for (int j = 0; j < 4; j++) Ss[(ty * 4 + i) * 64 + tx * 4 + j] = sc[i][j];
        }
        __syncthreads();
        for (int e = tid; e < 64 * 64; e += 256) {
            int c = e >> 6, d = e & 63;
            KVs[c * 64 + d] = g_qkv[(size_t)(k0 + c) * QKV_N + (NH + NKV) * D + kvh * D + d];
        }
        __syncthreads();
#pragma unroll 8
        for (int c = 0; c < 64; c++) {
            float pv[4], vv[4];
#pragma unroll
            for (int i = 0; i < 4; i++) pv[i] = Ss[(ty * 4 + i) * 64 + c];
            float4 v4 = *(const float4*)&KVs[c * 64 + tx * 4];
            vv[0] = v4.x; vv[1] = v4.y; vv[2] = v4.z; vv[3] = v4.w;
#pragma unroll
            for (int i = 0; i < 4; i++)
#pragma unroll
                for (int j = 0; j < 4; j++) accO[i][j] += pv[i] * vv[j];
        }
    }
#pragma unroll
    for (int i = 0; i < 4; i++) {
        float inv = 1.f / l[i];
        int r = q0 + ty * 4 + i;
#pragma unroll
        for (int j = 0; j < 4; j++)
            g_ao[(size_t)r * (NH * D) + head * D + tx * 4 + j] = accO[i][j] * inv;
    }
}

// ---------------- router -----------------------------------------------------
__global__ void router_kernel(const float* __restrict__ rw) {
    int t = blockIdx.x, tid = threadIdx.x;
    float acc[E] = {};
    const float* p = g_h2 + (size_t)t * H;
    for (int h = tid; h < H; h += 256) {
        float x = p[h];
        const float* r = rw + (size_t)h * E;
#pragma unroll
        for (int e = 0; e < E; e++) acc[e] += x * r[e];
    }
#pragma unroll
    for (int e = 0; e < E; e++)
#pragma unroll
        for (int off = 16; off; off >>= 1)
            acc[e] += __shfl_xor_sync(0xffffffffu, acc[e], off);
    __shared__ float sred[8][E];
    int w = tid >> 5, lane = tid & 31;
    if (lane == 0)
        for (int e = 0; e < E; e++) sred[w][e] = acc[e];
    __syncthreads();
    if (tid == 0) {
        float best = -INFINITY;
        int bi = 0;
        for (int e = 0; e < E; e++) {
            float v = 0.f;
            for (int ww = 0; ww < 8; ww++) v += sred[ww][e];
            if (v > best) { best = v; bi = e; }
        }
        g_eidx[t] = bi;
        g_gate[t] = 1.f / (1.f + expf(-best));
        atomicAdd(&g_count[bi], 1);
    }
}

// ---------------- launch -----------------------------------------------------
extern "C" void kernel_launch(void* const* d_in, const int* in_sizes, int n_in,
                              void* d_out, int out_size) {
    const int* pos = (const int*)d_in[0];
    const float* hidden = (const float*)d_in[1];
    const float* ln1 = (const float*)d_in[2];
    const float* ln2 = (const float*)d_in[3];
    const float* wqkv = (const float*)d_in[4];
    const float* wo = (const float*)d_in[5];
    const float* rw = (const float*)d_in[6];
    const float* wgate = (const float*)d_in[7];
    const float* wup = (const float*)d_in[8];
    const float* wdown = (const float*)d_in[9];
    const float* shg = (const float*)d_in[10];
    const float* shu = (const float*)d_in[11];
    const float* shd = (const float*)d_in[12];
    float* out = (float*)d_out;
    float* resid = out + (size_t)T * H;

    float *p_h1, *p_h2, *p_bufA, *p_bufB, *p_qkv, *p_ao;
    cudaGetSymbolAddress((void**)&p_h1, g_h1);
    cudaGetSymbolAddress((void**)&p_h2, g_h2);
    cudaGetSymbolAddress((void**)&p_bufA, g_bufA);
    cudaGetSymbolAddress((void**)&p_bufB, g_bufB);
    cudaGetSymbolAddress((void**)&p_qkv, g_qkv);
    cudaGetSymbolAddress((void**)&p_ao, g_ao);

    zero_kernel<<<1, 32>>>();
    rmsnorm_kernel<<<T, 256>>>(hidden, ln1, p_h1);
    gemm_tf32<<<dim3(QKV_N / 128, T / 128), 256>>>(p_h1, wqkv, p_qkv, T, QKV_N, H, nullptr);
    rope_rms_kernel<<<dim3(T, 5), 256>>>(pos);
    attn_kernel<<<dim3(T / 64, NH), 256>>>();
    gemm_tf32<<<dim3(H / 128, T / 128), 256>>>(p_ao, wo, resid, T, H, NH * D, hidden);
    rmsnorm_kernel<<<T, 256>>>(resid, ln2, p_h2);
    router_kernel<<<T, 256>>>(rw);
    scan_kernel<<<1, 32>>>();
    scatter_kernel<<<T / 256, 256>>>();
    // shared expert
    gemm_tf32<<<dim3(F / 128, T / 128), 256>>>(p_h2, shg, p_bufA, T, F, H, nullptr);
    gemm_tf32<<<dim3(F / 128, T / 128), 256>>>(p_h2, shu, p_bufB, T, F, H, nullptr);
    silumul_kernel<<<(T * F) / 256, 256>>>(p_bufA, p_bufB, T * F);
    gemm_tf32<<<dim3(H / 128, T / 128), 256>>>(p_bufA, shd, out, T, H, F, nullptr);
    // routed expert
    ggemm_proj_tf32<<<dim3(F / 128, T / 128, E), 256>>>(wgate, p_bufA);
    ggemm_proj_tf32<<<dim3(F / 128, T / 128, E), 256>>>(wup, p_bufB);
    silumul_kernel<<<(T * F) / 256, 256>>>(p_bufA, p_bufB, T * F);
    ggemm_down_tf32<<<dim3(H / 128, T / 128, E), 256>>>(wdown, out);
    (void)in_sizes; (void)n_in; (void)out_size;
}

// round 5
// speedup vs baseline: 2.1860x; 1.2997x over previous
#include <cuda_runtime.h>
#include <math.h>

#define T 2048
#define H 1024
#define NH 16
#define NKV 4
#define D 64
#define E 8
#define F 1024
#define QKV_N ((NH + 2*NKV) * D)   // 1536
#define EPS 1e-5f
#define ATT_SCALE 0.125f

// ---------------- scratch ---------------------------------------------------
__device__ float    g_h1[T * H];
__device__ float    g_qkv[T * QKV_N];
__device__ unsigned g_qT[NH * D * T];    // tf32 bits, [head][d][t]
__device__ unsigned g_kT[NKV * D * T];   // tf32 bits, [kvh][d][t]
__device__ float    g_ao[T * NH * D];
__device__ float    g_h2[T * H];
__device__ float    g_bufA[T * F];
__device__ float    g_bufB[T * F];
__device__ int      g_eidx[T];
__device__ float    g_gate[T];
__device__ int      g_perm[T];
__device__ int      g_count[E];
__device__ int      g_base[E];
__device__ int      g_offs[E];

// ---------------- small utility kernels -------------------------------------
__global__ void zero_kernel() {
    if (threadIdx.x < E) g_count[threadIdx.x] = 0;
}
__global__ void scan_kernel() {
    if (threadIdx.x == 0) {
        int b = 0;
        for (int e = 0; e < E; e++) { g_base[e] = b; b += g_count[e]; g_offs[e] = 0; }
    }
}
__global__ void scatter_kernel() {
    int t = blockIdx.x * blockDim.x + threadIdx.x;
    if (t < T) {
        int e = g_eidx[t];
        int p = g_base[e] + atomicAdd(&g_offs[e], 1);
        g_perm[p] = t;
    }
}
__global__ void silumul_kernel(float* __restrict__ a, const float* __restrict__ b, int n) {
    int i = blockIdx.x * blockDim.x + threadIdx.x;
    if (i < n) {
        float x = a[i];
        a[i] = x / (1.f + expf(-x)) * b[i];
    }
}

// ---------------- rmsnorm ----------------------------------------------------
__global__ void rmsnorm_kernel(const float* __restrict__ in, const float* __restrict__ w,
                               float* __restrict__ out) {
    int row = blockIdx.x, tid = threadIdx.x;
    const float* p = in + (size_t)row * H;
    float v[4];
    float s = 0.f;
#pragma unroll
    for (int i = 0; i < 4; i++) { v[i] = p[tid + i * 256]; s += v[i] * v[i]; }
#pragma unroll
    for (int off = 16; off; off >>= 1) s += __shfl_xor_sync(0xffffffffu, s, off);
    __shared__ float sw[8];
    if ((tid & 31) == 0) sw[tid >> 5] = s;
    __syncthreads();
    __shared__ float stot;
    if (tid == 0) {
        float t2 = 0.f;
        for (int i = 0; i < 8; i++) t2 += sw[i];
        stot = t2;
    }
    __syncthreads();
    float r = rsqrtf(stot / (float)H + EPS);
    float* o = out + (size_t)row * H;
#pragma unroll
    for (int i = 0; i < 4; i++) o[tid + i * 256] = v[i] * r * w[tid + i * 256];
}

// =================== TF32 tensor-core machinery ==============================
__device__ __forceinline__ unsigned f2tf(float x) {
    unsigned r;
    asm("cvt.rna.tf32.f32 %0, %1;" : "=r"(r) : "f"(x));
    return r;
}
__device__ __forceinline__ void mma_tf32(float* c, const unsigned* a, const unsigned* b) {
    asm volatile(
        "mma.sync.aligned.m16n8k8.row.col.f32.tf32.tf32.f32 "
        "{%0,%1,%2,%3},{%4,%5,%6,%7},{%8,%9},{%0,%1,%2,%3};"
        : "+f"(c[0]), "+f"(c[1]), "+f"(c[2]), "+f"(c[3])
        : "r"(a[0]), "r"(a[1]), "r"(a[2]), "r"(a[3]), "r"(b[0]), "r"(b[1]));
}

#define KT 16
#define SMS 136

#define MMA_TILE_COMPUTE(Asb, Bsb)                                             \
    _Pragma("unroll")                                                          \
    for (int k8 = 0; k8 < KT; k8 += 8) {                                       \
        unsigned af[4][4], bf[4][2];                                           \
        _Pragma("unroll")                                                      \
        for (int mt = 0; mt < 4; mt++) {                                       \
            int mb = wm + mt * 16;                                             \
            af[mt][0] = Asb[(k8 + tg) * SMS + mb + g];                         \
            af[mt][1] = Asb[(k8 + tg) * SMS + mb + g + 8];                     \
            af[mt][2] = Asb[(k8 + tg + 4) * SMS + mb + g];                     \
            af[mt][3] = Asb[(k8 + tg + 4) * SMS + mb + g + 8];                 \
        }                                                                      \
        _Pragma("unroll")                                                      \
        for (int nt2 = 0; nt2 < 4; nt2++) {                                    \
            int nb = wn + nt2 * 8;                                             \
            bf[nt2][0] = Bsb[(k8 + tg) * SMS + nb + g];                        \
            bf[nt2][1] = Bsb[(k8 + tg + 4) * SMS + nb + g];                    \
        }                                                                      \
        _Pragma("unroll")                                                      \
        for (int mt = 0; mt < 4; mt++)                                         \
            _Pragma("unroll")                                                  \
            for (int nt2 = 0; nt2 < 4; nt2++)                                  \
                mma_tf32(acc[mt][nt2], af[mt], bf[nt2]);                       \
    }

// ---------------- dense tf32 GEMM -------------------------------------------
__global__ __launch_bounds__(256)
void gemm_tf32(const float* __restrict__ A, const float* __restrict__ B,
               float* __restrict__ C, int M, int N, int K,
               const float* __restrict__ addsrc) {
    __shared__ unsigned As[2][KT * SMS];
    __shared__ unsigned Bs[2][KT * SMS];
    int tid = threadIdx.x;
    int warp = tid >> 5, lane = tid & 31;
    int g = lane >> 2, tg = lane & 3;
    int wm = (warp >> 2) * 64, wn = (warp & 3) * 32;
    int m0 = blockIdx.y * 128, n0 = blockIdx.x * 128;
    int arow = tid >> 1, acol = (tid & 1) * 8;
    int bk = tid >> 4, bn = (tid & 15) * 8;
    const float* Ap = A + (size_t)(m0 + arow) * K + acol;
    const float* Bp = B + (size_t)bk * N + n0 + bn;
    float acc[4][4][4] = {};

    float4 av0 = *(const float4*)Ap, av1 = *(const float4*)(Ap + 4);
    float4 bv0 = *(const float4*)Bp, bv1 = *(const float4*)(Bp + 4);
    {
        unsigned* ad = As[0];
        ad[(acol + 0) * SMS + arow] = f2tf(av0.x);
        ad[(acol + 1) * SMS + arow] = f2tf(av0.y);
        ad[(acol + 2) * SMS + arow] = f2tf(av0.z);
        ad[(acol + 3) * SMS + arow] = f2tf(av0.w);
        ad[(acol + 4) * SMS + arow] = f2tf(av1.x);
        ad[(acol + 5) * SMS + arow] = f2tf(av1.y);
        ad[(acol + 6) * SMS + arow] = f2tf(av1.z);
        ad[(acol + 7) * SMS + arow] = f2tf(av1.w);
        unsigned* bd = Bs[0] + bk * SMS + bn;
        bd[0] = f2tf(bv0.x); bd[1] = f2tf(bv0.y); bd[2] = f2tf(bv0.z); bd[3] = f2tf(bv0.w);
        bd[4] = f2tf(bv1.x); bd[5] = f2tf(bv1.y); bd[6] = f2tf(bv1.z); bd[7] = f2tf(bv1.w);
    }
    __syncthreads();
    int nt = K / KT;
    int buf = 0;
    for (int kt = 0; kt < nt; kt++) {
        if (kt + 1 < nt) {
            av0 = *(const float4*)(Ap + (kt + 1) * KT);
            av1 = *(const float4*)(Ap + (kt + 1) * KT + 4);
            bv0 = *(const float4*)(Bp + (size_t)(kt + 1) * KT * N);
            bv1 = *(const float4*)(Bp + (size_t)(kt + 1) * KT * N + 4);
        }
        const unsigned* Asb = As[buf];
        const unsigned* Bsb = Bs[buf];
        MMA_TILE_COMPUTE(Asb, Bsb)
        if (kt + 1 < nt) {
            unsigned* ad = As[buf ^ 1];
            ad[(acol + 0) * SMS + arow] = f2tf(av0.x);
            ad[(acol + 1) * SMS + arow] = f2tf(av0.y);
            ad[(acol + 2) * SMS + arow] = f2tf(av0.z);
            ad[(acol + 3) * SMS + arow] = f2tf(av0.w);
            ad[(acol + 4) * SMS + arow] = f2tf(av1.x);
            ad[(acol + 5) * SMS + arow] = f2tf(av1.y);
            ad[(acol + 6) * SMS + arow] = f2tf(av1.z);
            ad[(acol + 7) * SMS + arow] = f2tf(av1.w);
            unsigned* bd = Bs[buf ^ 1] + bk * SMS + bn;
            bd[0] = f2tf(bv0.x); bd[1] = f2tf(bv0.y); bd[2] = f2tf(bv0.z); bd[3] = f2tf(bv0.w);
            bd[4] = f2tf(bv1.x); bd[5] = f2tf(bv1.y); bd[6] = f2tf(bv1.z); bd[7] = f2tf(bv1.w);
        }
        __syncthreads();
        buf ^= 1;
    }
#pragma unroll
    for (int mt = 0; mt < 4; mt++) {
#pragma unroll
        for (int nt2 = 0; nt2 < 4; nt2++) {
            int r0 = m0 + wm + mt * 16 + g;
            int c = n0 + wn + nt2 * 8 + 2 * tg;
            float2 v0 = make_float2(acc[mt][nt2][0], acc[mt][nt2][1]);
            float2 v1 = make_float2(acc[mt][nt2][2], acc[mt][nt2][3]);
            if (addsrc) {
                float2 r = *(const float2*)(addsrc + (size_t)r0 * N + c);
                v0.x += r.x; v0.y += r.y;
                float2 r2 = *(const float2*)(addsrc + (size_t)(r0 + 8) * N + c);
                v1.x += r2.x; v1.y += r2.y;
            }
            *(float2*)(C + (size_t)r0 * N + c) = v0;
            *(float2*)(C + (size_t)(r0 + 8) * N + c) = v1;
        }
    }
}

// ---------------- grouped tf32 GEMM (gather + gate) --------------------------
__global__ __launch_bounds__(256)
void ggemm_proj_tf32(const float* __restrict__ Wall, float* __restrict__ Cbuf) {
    int e = blockIdx.z;
    int cnt = g_count[e];
    int m0 = blockIdx.y * 128;
    if (m0 >= cnt) return;
    int n0 = blockIdx.x * 128;
    __shared__ unsigned As[2][KT * SMS];
    __shared__ unsigned Bs[2][KT * SMS];
    __shared__ int srcrow[128];
    int tid = threadIdx.x;
    if (tid < 128) {
        int mm = m0 + tid;
        srcrow[tid] = (mm < cnt) ? g_perm[g_base[e] + mm] : -1;
    }
    __syncthreads();
    int warp = tid >> 5, lane = tid & 31;
    int g = lane >> 2, tg = lane & 3;
    int wm = (warp >> 2) * 64, wn = (warp & 3) * 32;
    int arow = tid >> 1, acol = (tid & 1) * 8;
    int bk = tid >> 4, bn = (tid & 15) * 8;
    int tok = srcrow[arow];
    float gsc = (tok >= 0) ? g_gate[tok] : 0.f;
    const float* Ap = g_h2 + (size_t)((tok >= 0) ? tok : 0) * H + acol;
    const float* Bp = Wall + (size_t)e * H * F + (size_t)bk * F + n0 + bn;
    float acc[4][4][4] = {};

    float4 av0 = *(const float4*)Ap, av1 = *(const float4*)(Ap + 4);
    float4 bv0 = *(const float4*)Bp, bv1 = *(const float4*)(Bp + 4);
    {
        unsigned* ad = As[0];
        ad[(acol + 0) * SMS + arow] = f2tf(av0.x * gsc);
        ad[(acol + 1) * SMS + arow] = f2tf(av0.y * gsc);
        ad[(acol + 2) * SMS + arow] = f2tf(av0.z * gsc);
        ad[(acol + 3) * SMS + arow] = f2tf(av0.w * gsc);
        ad[(acol + 4) * SMS + arow] = f2tf(av1.x * gsc);
        ad[(acol + 5) * SMS + arow] = f2tf(av1.y * gsc);
        ad[(acol + 6) * SMS + arow] = f2tf(av1.z * gsc);
        ad[(acol + 7) * SMS + arow] = f2tf(av1.w * gsc);
        unsigned* bd = Bs[0] + bk * SMS + bn;
        bd[0] = f2tf(bv0.x); bd[1] = f2tf(bv0.y); bd[2] = f2tf(bv0.z); bd[3] = f2tf(bv0.w);
        bd[4] = f2tf(bv1.x); bd[5] = f2tf(bv1.y); bd[6] = f2tf(bv1.z); bd[7] = f2tf(bv1.w);
    }
    __syncthreads();
    int nt = H / KT;
    int buf = 0;
    for (int kt = 0; kt < nt; kt++) {
        if (kt + 1 < nt) {
            av0 = *(const float4*)(Ap + (kt + 1) * KT);
            av1 = *(const float4*)(Ap + (kt + 1) * KT + 4);
            bv0 = *(const float4*)(Bp + (size_t)(kt + 1) * KT * F);
            bv1 = *(const float4*)(Bp + (size_t)(kt + 1) * KT * F + 4);
        }
        const unsigned* Asb = As[buf];
        const unsigned* Bsb = Bs[buf];
        MMA_TILE_COMPUTE(Asb, Bsb)
        if (kt + 1 < nt) {
            unsigned* ad = As[buf ^ 1];
            ad[(acol + 0) * SMS + arow] = f2tf(av0.x * gsc);
            ad[(acol + 1) * SMS + arow] = f2tf(av0.y * gsc);
            ad[(acol + 2) * SMS + arow] = f2tf(av0.z * gsc);
            ad[(acol + 3) * SMS + arow] = f2tf(av0.w * gsc);
            ad[(acol + 4) * SMS + arow] = f2tf(av1.x * gsc);
            ad[(acol + 5) * SMS + arow] = f2tf(av1.y * gsc);
            ad[(acol + 6) * SMS + arow] = f2tf(av1.z * gsc);
            ad[(acol + 7) * SMS + arow] = f2tf(av1.w * gsc);
            unsigned* bd = Bs[buf ^ 1] + bk * SMS + bn;
            bd[0] = f2tf(bv0.x); bd[1] = f2tf(bv0.y); bd[2] = f2tf(bv0.z); bd[3] = f2tf(bv0.w);
            bd[4] = f2tf(bv1.x); bd[5] = f2tf(bv1.y); bd[6] = f2tf(bv1.z); bd[7] = f2tf(bv1.w);
        }
        __syncthreads();
        buf ^= 1;
    }
#pragma unroll
    for (int mt = 0; mt < 4; mt++) {
#pragma unroll
        for (int nt2 = 0; nt2 < 4; nt2++) {
            int mi0 = wm + mt * 16 + g;
            int c = n0 + wn + nt2 * 8 + 2 * tg;
            if (m0 + mi0 < cnt)
                *(float2*)(Cbuf + (size_t)(g_base[e] + m0 + mi0) * F + c) =
                    make_float2(acc[mt][nt2][0], acc[mt][nt2][1]);
            if (m0 + mi0 + 8 < cnt)
                *(float2*)(Cbuf + (size_t)(g_base[e] + m0 + mi0 + 8) * F + c) =
                    make_float2(acc[mt][nt2][2], acc[mt][nt2][3]);
        }
    }
}

// ---------------- grouped down tf32 GEMM -------------------------------------
__global__ __launch_bounds__(256)
void ggemm_down_tf32(const float* __restrict__ Wall, float* __restrict__ out) {
    int e = blockIdx.z;
    int cnt = g_count[e];
    int m0 = blockIdx.y * 128;
    if (m0 >= cnt) return;
    int n0 = blockIdx.x * 128;
    __shared__ unsigned As[2][KT * SMS];
    __shared__ unsigned Bs[2][KT * SMS];
    __shared__ int rtok[128];
    int tid = threadIdx.x;
    if (tid < 128) {
        int mm = m0 + tid;
        rtok[tid] = (mm < cnt) ? g_perm[g_base[e] + mm] : -1;
    }
    __syncthreads();
    int warp = tid >> 5, lane = tid & 31;
    int g = lane >> 2, tg = lane & 3;
    int wm = (warp >> 2) * 64, wn = (warp & 3) * 32;
    int arow = tid >> 1, acol = (tid & 1) * 8;
    int bk = tid >> 4, bn = (tid & 15) * 8;
    bool arow_ok = (m0 + arow) < cnt;
    float amask = arow_ok ? 1.f : 0.f;
    const float* Ap = g_bufA + (size_t)(g_base[e] + (arow_ok ? (m0 + arow) : 0)) * F + acol;
    const float* Bp = Wall + (size_t)e * F * H + (size_t)bk * H + n0 + bn;
    float acc[4][4][4] = {};

    float4 av0 = *(const float4*)Ap, av1 = *(const float4*)(Ap + 4);
    float4 bv0 = *(const float4*)Bp, bv1 = *(const float4*)(Bp + 4);
    {
        unsigned* ad = As[0];
        ad[(acol + 0) * SMS + arow] = f2tf(av0.x * amask);
        ad[(acol + 1) * SMS + arow] = f2tf(av0.y * amask);
        ad[(acol + 2) * SMS + arow] = f2tf(av0.z * amask);
        ad[(acol + 3) * SMS + arow] = f2tf(av0.w * amask);
        ad[(acol + 4) * SMS + arow] = f2tf(av1.x * amask);
        ad[(acol + 5) * SMS + arow] = f2tf(av1.y * amask);
        ad[(acol + 6) * SMS + arow] = f2tf(av1.z * amask);
        ad[(acol + 7) * SMS + arow] = f2tf(av1.w * amask);
        unsigned* bd = Bs[0] + bk * SMS + bn;
        bd[0] = f2tf(bv0.x); bd[1] = f2tf(bv0.y); bd[2] = f2tf(bv0.z); bd[3] = f2tf(bv0.w);
        bd[4] = f2tf(bv1.x); bd[5] = f2tf(bv1.y); bd[6] = f2tf(bv1.z); bd[7] = f2tf(bv1.w);
    }
    __syncthreads();
    int nt = F / KT;
    int buf = 0;
    for (int kt = 0; kt < nt; kt++) {
        if (kt + 1 < nt) {
            av0 = *(const float4*)(Ap + (kt + 1) * KT);
            av1 = *(const float4*)(Ap + (kt + 1) * KT + 4);
            bv0 = *(const float4*)(Bp + (size_t)(kt + 1) * KT * H);
            bv1 = *(const float4*)(Bp + (size_t)(kt + 1) * KT * H + 4);
        }
        const unsigned* Asb = As[buf];
        const unsigned* Bsb = Bs[buf];
        MMA_TILE_COMPUTE(Asb, Bsb)
        if (kt + 1 < nt) {
            unsigned* ad = As[buf ^ 1];
            ad[(acol + 0) * SMS + arow] = f2tf(av0.x * amask);
            ad[(acol + 1) * SMS + arow] = f2tf(av0.y * amask);
            ad[(acol + 2) * SMS + arow] = f2tf(av0.z * amask);
            ad[(acol + 3) * SMS + arow] = f2tf(av0.w * amask);
            ad[(acol + 4) * SMS + arow] = f2tf(av1.x * amask);
            ad[(acol + 5) * SMS + arow] = f2tf(av1.y * amask);
            ad[(acol + 6) * SMS + arow] = f2tf(av1.z * amask);
            ad[(acol + 7) * SMS + arow] = f2tf(av1.w * amask);
            unsigned* bd = Bs[buf ^ 1] + bk * SMS + bn;
            bd[0] = f2tf(bv0.x); bd[1] = f2tf(bv0.y); bd[2] = f2tf(bv0.z); bd[3] = f2tf(bv0.w);
            bd[4] = f2tf(bv1.x); bd[5] = f2tf(bv1.y); bd[6] = f2tf(bv1.z); bd[7] = f2tf(bv1.w);
        }
        __syncthreads();
        buf ^= 1;
    }
#pragma unroll
    for (int mt = 0; mt < 4; mt++) {
#pragma unroll
        for (int nt2 = 0; nt2 < 4; nt2++) {
            int mi0 = wm + mt * 16 + g;
            int c = n0 + wn + nt2 * 8 + 2 * tg;
            if (m0 + mi0 < cnt) {
                int t = rtok[mi0];
                float2 r = *(const float2*)(out + (size_t)t * H + c);
                r.x += acc[mt][nt2][0]; r.y += acc[mt][nt2][1];
                *(float2*)(out + (size_t)t * H + c) = r;
            }
            if (m0 + mi0 + 8 < cnt) {
                int t = rtok[mi0 + 8];
                float2 r = *(const float2*)(out + (size_t)t * H + c);
                r.x += acc[mt][nt2][2]; r.y += acc[mt][nt2][3];
                *(float2*)(out + (size_t)t * H + c) = r;
            }
        }
    }
}

// ---------------- rope + per-head rmsnorm → transposed tf32 ------------------
__global__ void rope_rms_kernel(const int* __restrict__ pos) {
    int t = blockIdx.x;
    int grp = threadIdx.x >> 6;
    int d = threadIdx.x & 63;
    int h = blockIdx.y * 4 + grp;
    const float* src;
    unsigned* dstT;
    if (h < NH) {
        src = g_qkv + (size_t)t * QKV_N + h * D;
        dstT = g_qT + (size_t)h * D * T;
    } else {
        int kh = h - NH;
        src = g_qkv + (size_t)t * QKV_N + NH * D + kh * D;
        dstT = g_kT + (size_t)kh * D * T;
    }
    int i = d & 31;
    float inv = powf(500000.0f, -((float)i) / 32.0f);
    float ang = (float)pos[t] * inv;
    float sn, cs;
    sincosf(ang, &sn, &cs);
    float x1 = src[i], x2 = src[i + 32];
    float val = (d < 32) ? (x1 * cs - x2 * sn) : (x2 * cs + x1 * sn);
    float sq = val * val;
#pragma unroll
    for (int off = 16; off; off >>= 1) sq += __shfl_xor_sync(0xffffffffu, sq, off);
    __shared__ float sw2[4][2];
    if ((d & 31) == 0) sw2[grp][d >> 5] = sq;
    __syncthreads();
    float tot = sw2[grp][0] + sw2[grp][1];
    dstT[(size_t)d * T + t] = f2tf(val * rsqrtf(tot / (float)D + EPS));
}

// ================= tensor-core flash attention ===============================
// 128 threads (4 warps × 16 query rows). BM=BN=64, D=64. Dynamic smem:
// Ks [d][key] | Vs [key][d] | Ps [key][query], all stride 72 (conflict-free).
#define AS 72
__global__ __launch_bounds__(128)
void attn_tc() {
    extern __shared__ unsigned usmem[];
    unsigned* Ks = usmem;                 // 64*AS
    unsigned* Vs = usmem + 64 * AS;       // 64*AS
    unsigned* Ps = usmem + 2 * 64 * AS;   // 64*AS
    int qt = (int)gridDim.x - 1 - (int)blockIdx.x;  // longest blocks first
    int head = blockIdx.y;
    int kvh = head >> 2;
    int tid = threadIdx.x, warp = tid >> 5, lane = tid & 31;
    int g = lane >> 2, tg = lane & 3;
    int q0 = qt * 64;
    int wq = warp * 16;

    // stage Q tile into Ks as [d][row], then lift A-fragments to registers
    for (int e = tid; e < 64 * 64; e += 128) {
        int d = e >> 6, r = e & 63;
        Ks[d * AS + r] = g_qT[(size_t)head * D * T + (size_t)d * T + q0 + r];
    }
    __syncthreads();
    unsigned qf[8][4];
#pragma unroll
    for (int kc = 0; kc < 8; kc++) {
        qf[kc][0] = Ks[(kc * 8 + tg) * AS + wq + g];
        qf[kc][1] = Ks[(kc * 8 + tg) * AS + wq + g + 8];
        qf[kc][2] = Ks[(kc * 8 + tg + 4) * AS + wq + g];
        qf[kc][3] = Ks[(kc * 8 + tg + 4) * AS + wq + g + 8];
    }
    int r0 = q0 + wq + g, r1 = r0 + 8;
    float m0 = -INFINITY, m1 = -INFINITY, l0 = 0.f, l1 = 0.f;
    float accO[8][4] = {};

    for (int j0 = 0; j0 <= qt; j0++) {
        int k0 = j0 * 64;
        __syncthreads();
        for (int e = tid; e < 64 * 64; e += 128) {
            int d = e >> 6, c = e & 63;
            Ks[d * AS + c] = g_kT[(size_t)kvh * D * T + (size_t)d * T + k0 + c];
        }
        for (int e = tid; e < 64 * 64; e += 128) {
            int c = e >> 6, d = e & 63;
            Vs[c * AS + d] =
                f2tf(g_qkv[(size_t)(k0 + c) * QKV_N + (NH + NKV) * D + kvh * D + d]);
        }
        __syncthreads();
        // S = Q K^T
        float sc[8][4] = {};
#pragma unroll
        for (int kc = 0; kc < 8; kc++) {
            unsigned bfr[8][2];
#pragma unroll
            for (int n = 0; n < 8; n++) {
                bfr[n][0] = Ks[(kc * 8 + tg) * AS + n * 8 + g];
                bfr[n][1] = Ks[(kc * 8 + tg + 4) * AS + n * 8 + g];
            }
#pragma unroll
            for (int n = 0; n < 8; n++) mma_tf32(sc[n], qf[kc], bfr[n]);
        }
        // mask + scale + online softmax
        float mx0 = -INFINITY, mx1 = -INFINITY;
#pragma unroll
        for (int n = 0; n < 8; n++) {
            int c0 = k0 + n * 8 + 2 * tg;
            float s0 = (c0 <= r0) ? sc[n][0] * ATT_SCALE : -INFINITY;
            float s1 = (c0 + 1 <= r0) ? sc[n][1] * ATT_SCALE : -INFINITY;
            float s2 = (c0 <= r1) ? sc[n][2] * ATT_SCALE : -INFINITY;
            float s3 = (c0 + 1 <= r1) ? sc[n][3] * ATT_SCALE : -INFINITY;
            sc[n][0] = s0; sc[n][1] = s1; sc[n][2] = s2; sc[n][3] = s3;
            mx0 = fmaxf(mx0, fmaxf(s0, s1));
            mx1 = fmaxf(mx1, fmaxf(s2, s3));
        }
        mx0 = fmaxf(mx0, __shfl_xor_sync(0xffffffffu, mx0, 1));
        mx0 = fmaxf(mx0, __shfl_xor_sync(0xffffffffu, mx0, 2));
        mx1 = fmaxf(mx1, __shfl_xor_sync(0xffffffffu, mx1, 1));
        mx1 = fmaxf(mx1, __shfl_xor_sync(0xffffffffu, mx1, 2));
        float nm0 = fmaxf(m0, mx0), nm1 = fmaxf(m1, mx1);
        float corr0 = __expf(m0 - nm0), corr1 = __expf(m1 - nm1);
        m0 = nm0; m1 = nm1;
        float rs0 = 0.f, rs1 = 0.f;
#pragma unroll
        for (int n = 0; n < 8; n++) {
            int cl = n * 8 + 2 * tg;
            float p0 = __expf(sc[n][0] - nm0);
            float p1 = __expf(sc[n][1] - nm0);
            float p2 = __expf(sc[n][2] - nm1);
            float p3 = __expf(sc[n][3] - nm1);
            rs0 += p0 + p1; rs1 += p2 + p3;
            Ps[cl * AS + wq + g] = f2tf(p0);
            Ps[(cl + 1) * AS + wq + g] = f2tf(p1);
            Ps[cl * AS + wq + g + 8] = f2tf(p2);
            Ps[(cl + 1) * AS + wq + g + 8] = f2tf(p3);
        }
        rs0 += __shfl_xor_sync(0xffffffffu, rs0, 1);
        rs0 += __shfl_xor_sync(0xffffffffu, rs0, 2);
        rs1 += __shfl_xor_sync(0xffffffffu, rs1, 1);
        rs1 += __shfl_xor_sync(0xffffffffu, rs1, 2);
        l0 = l0 * corr0 + rs0;
        l1 = l1 * corr1 + rs1;
#pragma unroll
        for (int n = 0; n < 8; n++) {
            accO[n][0] *= corr0; accO[n][1] *= corr0;
            accO[n][2] *= corr1; accO[n][3] *= corr1;
        }
        __syncwarp();
        // O += P V
#pragma unroll
        for (int kc = 0; kc < 8; kc++) {
            unsigned af[4];
            af[0] = Ps[(kc * 8 + tg) * AS + wq + g];
            af[1] = Ps[(kc * 8 + tg) * AS + wq + g + 8];
            af[2] = Ps[(kc * 8 + tg + 4) * AS + wq + g];
            af[3] = Ps[(kc * 8 + tg + 4) * AS + wq + g + 8];
#pragma unroll
            for (int n = 0; n < 8; n++) {
                unsigned bfr2[2];
                bfr2[0] = Vs[(kc * 8 + tg) * AS + n * 8 + g];
                bfr2[1] = Vs[(kc * 8 + tg + 4) * AS + n * 8 + g];
                mma_tf32(accO[n], af, bfr2);
            }
        }
    }
    float inv0 = 1.f / l0, inv1 = 1.f / l1;
#pragma unroll
    for (int n = 0; n < 8; n++) {
        int c = head * D + n * 8 + 2 * tg;
        *(float2*)&g_ao[(size_t)r0 * (NH * D) + c] =
            make_float2(accO[n][0] * inv0, accO[n][1] * inv0);
        *(float2*)&g_ao[(size_t)r1 * (NH * D) + c] =
            make_float2(accO[n][2] * inv1, accO[n][3] * inv1);
    }
}

// ---------------- router ------------------------------------------------------
__global__ void router_kernel(const float* __restrict__ rw) {
    int t = blockIdx.x, tid = threadIdx.x;
    float acc[E] = {};
    const float* p = g_h2 + (size_t)t * H;
    for (int h = tid; h < H; h += 256) {
        float x = p[h];
        const float* r = rw + (size_t)h * E;
#pragma unroll
        for (int e = 0; e < E; e++) acc[e] += x * r[e];
    }
#pragma unroll
    for (int e = 0; e < E; e++)
#pragma unroll
        for (int off = 16; off; off >>= 1)
            acc[e] += __shfl_xor_sync(0xffffffffu, acc[e], off);
    __shared__ float sred[8][E];
    int w = tid >> 5, lane = tid & 31;
    if (lane == 0)
        for (int e = 0; e < E; e++) sred[w][e] = acc[e];
    __syncthreads();
    if (tid == 0) {
        float best = -INFINITY;
        int bi = 0;
        for (int e = 0; e < E; e++) {
            float v = 0.f;
            for (int ww = 0; ww < 8; ww++) v += sred[ww][e];
            if (v > best) { best = v; bi = e; }
        }
        g_eidx[t] = bi;
        g_gate[t] = 1.f / (1.f + expf(-best));
        atomicAdd(&g_count[bi], 1);
    }
}

// ---------------- launch ------------------------------------------------------
extern "C" void kernel_launch(void* const* d_in, const int* in_sizes, int n_in,
                              void* d_out, int out_size) {
    const int* pos = (const int*)d_in[0];
    const float* hidden = (const float*)d_in[1];
    const float* ln1 = (const float*)d_in[2];
    const float* ln2 = (const float*)d_in[3];
    const float* wqkv = (const float*)d_in[4];
    const float* wo = (const float*)d_in[5];
    const float* rw = (const float*)d_in[6];
    const float* wgate = (const float*)d_in[7];
    const float* wup = (const float*)d_in[8];
    const float* wdown = (const float*)d_in[9];
    const float* shg = (const float*)d_in[10];
    const float* shu = (const float*)d_in[11];
    const float* shd = (const float*)d_in[12];
    float* out = (float*)d_out;
    float* resid = out + (size_t)T * H;

    float *p_h1, *p_h2, *p_bufA, *p_bufB, *p_qkv, *p_ao;
    cudaGetSymbolAddress((void**)&p_h1, g_h1);
    cudaGetSymbolAddress((void**)&p_h2, g_h2);
    cudaGetSymbolAddress((void**)&p_bufA, g_bufA);
    cudaGetSymbolAddress((void**)&p_bufB, g_bufB);
    cudaGetSymbolAddress((void**)&p_qkv, g_qkv);
    cudaGetSymbolAddress((void**)&p_ao, g_ao);

    static int attn_smem_set = 0;
    const int ATTN_SMEM = 3 * 64 * AS * 4;   // 55296 B
    if (!attn_smem_set) {
        cudaFuncSetAttribute(attn_tc, cudaFuncAttributeMaxDynamicSharedMemorySize, ATTN_SMEM);
        attn_smem_set = 1;
    }

    zero_kernel<<<1, 32>>>();
    rmsnorm_kernel<<<T, 256>>>(hidden, ln1, p_h1);
    gemm_tf32<<<dim3(QKV_N / 128, T / 128), 256>>>(p_h1, wqkv, p_qkv, T, QKV_N, H, nullptr);
    rope_rms_kernel<<<dim3(T, 5), 256>>>(pos);
    attn_tc<<<dim3(T / 64, NH), 128, ATTN_SMEM>>>();
    gemm_tf32<<<dim3(H / 128, T / 128), 256>>>(p_ao, wo, resid, T, H, NH * D, hidden);
    rmsnorm_kernel<<<T, 256>>>(resid, ln2, p_h2);
    router_kernel<<<T, 256>>>(rw);
    scan_kernel<<<1, 32>>>();
    scatter_kernel<<<T / 256, 256>>>();
    // shared expert
    gemm_tf32<<<dim3(F / 128, T / 128), 256>>>(p_h2, shg, p_bufA, T, F, H, nullptr);
    gemm_tf32<<<dim3(F / 128, T / 128), 256>>>(p_h2, shu, p_bufB, T, F, H, nullptr);
    silumul_kernel<<<(T * F) / 256, 256>>>(p_bufA, p_bufB, T * F);
    gemm_tf32<<<dim3(H / 128, T / 128), 256>>>(p_bufA, shd, out, T, H, F, nullptr);
    // routed expert
    ggemm_proj_tf32<<<dim3(F / 128, T / 128, E), 256>>>(wgate, p_bufA);
    ggemm_proj_tf32<<<dim3(F / 128, T / 128, E), 256>>>(wup, p_bufB);
    silumul_kernel<<<(T * F) / 256, 256>>>(p_bufA, p_bufB, T * F);
    ggemm_down_tf32<<<dim3(H / 128, T / 128, E), 256>>>(wdown, out);
    (void)in_sizes; (void)n_in; (void)out_size;
}

// round 9
// speedup vs baseline: 2.7210x; 1.2447x over previous
#include <cuda_runtime.h>
#include <math.h>

#define T 2048
#define H 1024
#define NH 16
#define NKV 4
#define D 64
#define E 8
#define F 1024
#define QKV_N ((NH + 2*NKV) * D)   // 1536
#define EPS 1e-5f
#define ATT_SCALE 0.125f

// ---------------- scratch ---------------------------------------------------
__device__ float    g_h1[T * H];
__device__ float    g_qkv[T * QKV_N];
__device__ unsigned g_qT[NH * D * T];    // tf32 bits, [head][d][t]
__device__ unsigned g_kT[NKV * D * T];   // tf32 bits, [kvh][d][t]
__device__ unsigned g_vT[NKV * T * D];   // tf32 bits, [kvh][t][d]
__device__ float    g_ao[T * NH * D];
__device__ float    g_h2[T * H];
__device__ float    g_bufA[T * F];       // shared gate
__device__ float    g_bufB[T * F];       // shared up
__device__ float    g_bufC[T * F];       // routed gate (expert-grouped rows)
__device__ float    g_bufD[T * F];       // routed up
__device__ float    g_routed[T * H];     // routed expert output (dense by token)
__device__ int      g_eidx[T];
__device__ float    g_gate[T];
__device__ int      g_perm[T];
__device__ int      g_count[E];
__device__ int      g_base[E];
__device__ int      g_offs[E];

// ---------------- small utility kernels -------------------------------------
__global__ void zero_kernel() {
    if (threadIdx.x < E) g_count[threadIdx.x] = 0;
}
__global__ void scan_kernel() {
    if (threadIdx.x == 0) {
        int b = 0;
        for (int e = 0; e < E; e++) { g_base[e] = b; b += g_count[e]; g_offs[e] = 0; }
    }
}
__global__ void scatter_kernel() {
    int t = blockIdx.x * blockDim.x + threadIdx.x;
    if (t < T) {
        int e = g_eidx[t];
        int p = g_base[e] + atomicAdd(&g_offs[e], 1);
        g_perm[p] = t;
    }
}
// silu(a)*b for both expert pairs in one launch: y=0 shared, y=1 routed
__global__ void silumul2_kernel() {
    int i = blockIdx.x * blockDim.x + threadIdx.x;
    float* a = blockIdx.y ? g_bufC : g_bufA;
    const float* b = blockIdx.y ? g_bufD : g_bufB;
    float x = a[i];
    a[i] = x / (1.f + __expf(-x)) * b[i];
}
// out += routed
__global__ void add_routed_kernel(float* __restrict__ out) {
    int i = blockIdx.x * blockDim.x + threadIdx.x;
    out[i] += g_routed[i];
}

// ---------------- rmsnorm (plain) -------------------------------------------
__global__ void rmsnorm_kernel(const float* __restrict__ in, const float* __restrict__ w,
                               float* __restrict__ out) {
    int row = blockIdx.x, tid = threadIdx.x;
    const float* p = in + (size_t)row * H;
    float v[4];
    float s = 0.f;
#pragma unroll
    for (int i = 0; i < 4; i++) { v[i] = p[tid + i * 256]; s += v[i] * v[i]; }
#pragma unroll
    for (int off = 16; off; off >>= 1) s += __shfl_xor_sync(0xffffffffu, s, off);
    __shared__ float sw[8];
    if ((tid & 31) == 0) sw[tid >> 5] = s;
    __syncthreads();
    __shared__ float stot;
    if (tid == 0) {
        float t2 = 0.f;
        for (int i = 0; i < 8; i++) t2 += sw[i];
        stot = t2;
    }
    __syncthreads();
    float r = rsqrtf(stot / (float)H + EPS);
    float* o = out + (size_t)row * H;
#pragma unroll
    for (int i = 0; i < 4; i++) o[tid + i * 256] = v[i] * r * w[tid + i * 256];
}

// ---------------- rmsnorm2 + router fused -----------------------------------
__global__ void rmsnorm_router_kernel(const float* __restrict__ in,
                                      const float* __restrict__ w,
                                      const float* __restrict__ rw,
                                      float* __restrict__ out) {
    int row = blockIdx.x, tid = threadIdx.x;
    const float* p = in + (size_t)row * H;
    float v[4];
    float s = 0.f;
#pragma unroll
    for (int i = 0; i < 4; i++) { v[i] = p[tid + i * 256]; s += v[i] * v[i]; }
#pragma unroll
    for (int off = 16; off; off >>= 1) s += __shfl_xor_sync(0xffffffffu, s, off);
    __shared__ float sw[8];
    if ((tid & 31) == 0) sw[tid >> 5] = s;
    __syncthreads();
    __shared__ float stot;
    if (tid == 0) {
        float t2 = 0.f;
        for (int i = 0; i < 8; i++) t2 += sw[i];
        stot = t2;
    }
    __syncthreads();
    float r = rsqrtf(stot / (float)H + EPS);
    float* o = out + (size_t)row * H;
    float acc[E] = {};
#pragma unroll
    for (int i = 0; i < 4; i++) {
        int h = tid + i * 256;
        float hv = v[i] * r * w[h];
        o[h] = hv;
        const float* rr = rw + (size_t)h * E;
#pragma unroll
        for (int e = 0; e < E; e++) acc[e] += hv * rr[e];
    }
#pragma unroll
    for (int e = 0; e < E; e++)
#pragma unroll
        for (int off = 16; off; off >>= 1)
            acc[e] += __shfl_xor_sync(0xffffffffu, acc[e], off);
    __shared__ float sred[8][E];
    int wp = tid >> 5, lane = tid & 31;
    if (lane == 0)
        for (int e = 0; e < E; e++) sred[wp][e] = acc[e];
    __syncthreads();
    if (tid == 0) {
        float best = -INFINITY;
        int bi = 0;
        for (int e = 0; e < E; e++) {
            float vv = 0.f;
            for (int ww = 0; ww < 8; ww++) vv += sred[ww][e];
            if (vv > best) { best = vv; bi = e; }
        }
        g_eidx[row] = bi;
        g_gate[row] = 1.f / (1.f + expf(-best));
        atomicAdd(&g_count[bi], 1);
    }
}

// =================== TF32 tensor-core machinery ==============================
__device__ __forceinline__ unsigned f2tf(float x) {
    unsigned r;
    asm("cvt.rna.tf32.f32 %0, %1;" : "=r"(r) : "f"(x));
    return r;
}
__device__ __forceinline__ void mma_tf32(float* c, const unsigned* a, const unsigned* b) {
    asm volatile(
        "mma.sync.aligned.m16n8k8.row.col.f32.tf32.tf32.f32 "
        "{%0,%1,%2,%3},{%4,%5,%6,%7},{%8,%9},{%0,%1,%2,%3};"
        : "+f"(c[0]), "+f"(c[1]), "+f"(c[2]), "+f"(c[3])
        : "r"(a[0]), "r"(a[1]), "r"(a[2]), "r"(a[3]), "r"(b[0]), "r"(b[1]));
}

#define KT 16
#define SMS 136

#define MMA_TILE_COMPUTE(Asb, Bsb)                                             \
    _Pragma("unroll")                                                          \
    for (int k8 = 0; k8 < KT; k8 += 8) {                                       \
        unsigned af[4][4], bf[4][2];                                           \
        _Pragma("unroll")                                                      \
        for (int mt = 0; mt < 4; mt++) {                                       \
            int mb = wm + mt * 16;                                             \
            af[mt][0] = Asb[(k8 + tg) * SMS + mb + g];                         \
            af[mt][1] = Asb[(k8 + tg) * SMS + mb + g + 8];                     \
            af[mt][2] = Asb[(k8 + tg + 4) * SMS + mb + g];                     \
            af[mt][3] = Asb[(k8 + tg + 4) * SMS + mb + g + 8];                 \
        }                                                                      \
        _Pragma("unroll")                                                      \
        for (int nt2 = 0; nt2 < 4; nt2++) {                                    \
            int nb = wn + nt2 * 8;                                             \
            bf[nt2][0] = Bsb[(k8 + tg) * SMS + nb + g];                        \
            bf[nt2][1] = Bsb[(k8 + tg + 4) * SMS + nb + g];                    \
        }                                                                      \
        _Pragma("unroll")                                                      \
        for (int mt = 0; mt < 4; mt++)                                         \
            _Pragma("unroll")                                                  \
            for (int nt2 = 0; nt2 < 4; nt2++)                                  \
                mma_tf32(acc[mt][nt2], af[mt], bf[nt2]);                       \
    }

#define FILL_A(dst, v0, v1, scale)                                             \
    do {                                                                       \
        (dst)[(acol + 0) * SMS + arow] = f2tf((v0).x * (scale));               \
        (dst)[(acol + 1) * SMS + arow] = f2tf((v0).y * (scale));               \
        (dst)[(acol + 2) * SMS + arow] = f2tf((v0).z * (scale));               \
        (dst)[(acol + 3) * SMS + arow] = f2tf((v0).w * (scale));               \
        (dst)[(acol + 4) * SMS + arow] = f2tf((v1).x * (scale));               \
        (dst)[(acol + 5) * SMS + arow] = f2tf((v1).y * (scale));               \
        (dst)[(acol + 6) * SMS + arow] = f2tf((v1).z * (scale));               \
        (dst)[(acol + 7) * SMS + arow] = f2tf((v1).w * (scale));               \
    } while (0)

#define FILL_B(dst, v0, v1)                                                    \
    do {                                                                       \
        unsigned* bd_ = (dst) + bk * SMS + bn;                                 \
        bd_[0] = f2tf((v0).x); bd_[1] = f2tf((v0).y);                          \
        bd_[2] = f2tf((v0).z); bd_[3] = f2tf((v0).w);                          \
        bd_[4] = f2tf((v1).x); bd_[5] = f2tf((v1).y);                          \
        bd_[6] = f2tf((v1).z); bd_[7] = f2tf((v1).w);                          \
    } while (0)

// ---------------- dense tf32 GEMM -------------------------------------------
__global__ __launch_bounds__(256)
void gemm_tf32(const float* __restrict__ A, const float* __restrict__ B,
               float* __restrict__ C, int M, int N, int K,
               const float* __restrict__ addsrc) {
    __shared__ unsigned As[2][KT * SMS];
    __shared__ unsigned Bs[2][KT * SMS];
    int tid = threadIdx.x;
    int warp = tid >> 5, lane = tid & 31;
    int g = lane >> 2, tg = lane & 3;
    int wm = (warp >> 2) * 64, wn = (warp & 3) * 32;
    int m0 = blockIdx.y * 128, n0 = blockIdx.x * 128;
    int arow = tid >> 1, acol = (tid & 1) * 8;
    int bk = tid >> 4, bn = (tid & 15) * 8;
    const float* Ap = A + (size_t)(m0 + arow) * K + acol;
    const float* Bp = B + (size_t)bk * N + n0 + bn;
    float acc[4][4][4] = {};

    float4 av0 = *(const float4*)Ap, av1 = *(const float4*)(Ap + 4);
    float4 bv0 = *(const float4*)Bp, bv1 = *(const float4*)(Bp + 4);
    FILL_A(As[0], av0, av1, 1.f);
    FILL_B(Bs[0], bv0, bv1);
    __syncthreads();
    int nt = K / KT;
    int buf = 0;
    for (int kt = 0; kt < nt; kt++) {
        if (kt + 1 < nt) {
            av0 = *(const float4*)(Ap + (kt + 1) * KT);
            av1 = *(const float4*)(Ap + (kt + 1) * KT + 4);
            bv0 = *(const float4*)(Bp + (size_t)(kt + 1) * KT * N);
            bv1 = *(const float4*)(Bp + (size_t)(kt + 1) * KT * N + 4);
        }
        const unsigned* Asb = As[buf];
        const unsigned* Bsb = Bs[buf];
        MMA_TILE_COMPUTE(Asb, Bsb)
        if (kt + 1 < nt) {
            FILL_A(As[buf ^ 1], av0, av1, 1.f);
            FILL_B(Bs[buf ^ 1], bv0, bv1);
        }
        __syncthreads();
        buf ^= 1;
    }
#pragma unroll
    for (int mt = 0; mt < 4; mt++) {
#pragma unroll
        for (int nt2 = 0; nt2 < 4; nt2++) {
            int r0 = m0 + wm + mt * 16 + g;
            int c = n0 + wn + nt2 * 8 + 2 * tg;
            float2 v0 = make_float2(acc[mt][nt2][0], acc[mt][nt2][1]);
            float2 v1 = make_float2(acc[mt][nt2][2], acc[mt][nt2][3]);
            if (addsrc) {
                float2 r = *(const float2*)(addsrc + (size_t)r0 * N + c);
                v0.x += r.x; v0.y += r.y;
                float2 r2 = *(const float2*)(addsrc + (size_t)(r0 + 8) * N + c);
                v1.x += r2.x; v1.y += r2.y;
            }
            *(float2*)(C + (size_t)r0 * N + c) = v0;
            *(float2*)(C + (size_t)(r0 + 8) * N + c) = v1;
        }
    }
}

// ------------- MoE up-projections mega-GEMM (z = 0..17) ---------------------
// z=0: h2 @ shg -> bufA ; z=1: h2 @ shu -> bufB
// z>=2: e=(z-2)/2, kind=(z-2)&1: gathered gate-scaled h2 @ w[e] -> bufC/bufD
__global__ __launch_bounds__(256)
void moe_proj_tf32(const float* __restrict__ shg, const float* __restrict__ shu,
                   const float* __restrict__ wgate, const float* __restrict__ wup) {
    int z = blockIdx.z;
    int m0 = blockIdx.y * 128;
    int cnt, obase;
    const float* B;
    float* Cbuf;
    bool gathered;
    if (z < 2) {
        B = z ? shu : shg;
        Cbuf = z ? g_bufB : g_bufA;
        cnt = T; obase = 0; gathered = false;
    } else {
        int e = (z - 2) >> 1, kind = (z - 2) & 1;
        cnt = g_count[e];
        if (m0 >= cnt) return;
        B = (kind ? wup : wgate) + (size_t)e * H * F;
        Cbuf = kind ? g_bufD : g_bufC;
        obase = g_base[e]; gathered = true;
    }
    int n0 = blockIdx.x * 128;
    __shared__ unsigned As[2][KT * SMS];
    __shared__ unsigned Bs[2][KT * SMS];
    __shared__ int srcrow[128];
    int tid = threadIdx.x;
    if (tid < 128) {
        int mm = m0 + tid;
        srcrow[tid] = gathered ? ((mm < cnt) ? g_perm[obase + mm] : -1) : mm;
    }
    __syncthreads();
    int warp = tid >> 5, lane = tid & 31;
    int g = lane >> 2, tg = lane & 3;
    int wm = (warp >> 2) * 64, wn = (warp & 3) * 32;
    int arow = tid >> 1, acol = (tid & 1) * 8;
    int bk = tid >> 4, bn = (tid & 15) * 8;
    int tok = srcrow[arow];
    float gsc = gathered ? ((tok >= 0) ? g_gate[tok] : 0.f) : 1.f;
    const float* Ap = g_h2 + (size_t)((tok >= 0) ? tok : 0) * H + acol;
    const float* Bp = B + (size_t)bk * F + n0 + bn;
    float acc[4][4][4] = {};

    float4 av0 = *(const float4*)Ap, av1 = *(const float4*)(Ap + 4);
    float4 bv0 = *(const float4*)Bp, bv1 = *(const float4*)(Bp + 4);
    FILL_A(As[0], av0, av1, gsc);
    FILL_B(Bs[0], bv0, bv1);
    __syncthreads();
    int nt = H / KT;
    int buf = 0;
    for (int kt = 0; kt < nt; kt++) {
        if (kt + 1 < nt) {
            av0 = *(const float4*)(Ap + (kt + 1) * KT);
            av1 = *(const float4*)(Ap + (kt + 1) * KT + 4);
            bv0 = *(const float4*)(Bp + (size_t)(kt + 1) * KT * F);
            bv1 = *(const float4*)(Bp + (size_t)(kt + 1) * KT * F + 4);
        }
        const unsigned* Asb = As[buf];
        const unsigned* Bsb = Bs[buf];
        MMA_TILE_COMPUTE(Asb, Bsb)
        if (kt + 1 < nt) {
            FILL_A(As[buf ^ 1], av0, av1, gsc);
            FILL_B(Bs[buf ^ 1], bv0, bv1);
        }
        __syncthreads();
        buf ^= 1;
    }
#pragma unroll
    for (int mt = 0; mt < 4; mt++) {
#pragma unroll
        for (int nt2 = 0; nt2 < 4; nt2++) {
            int mi0 = wm + mt * 16 + g;
            int c = n0 + wn + nt2 * 8 + 2 * tg;
            if (m0 + mi0 < cnt)
                *(float2*)(Cbuf + (size_t)(obase + m0 + mi0) * F + c) =
                    make_float2(acc[mt][nt2][0], acc[mt][nt2][1]);
            if (m0 + mi0 + 8 < cnt)
                *(float2*)(Cbuf + (size_t)(obase + m0 + mi0 + 8) * F + c) =
                    make_float2(acc[mt][nt2][2], acc[mt][nt2][3]);
        }
    }
}

// ------------- MoE down-projections mega-GEMM (z = 0..8) --------------------
// z=0: bufA @ shd -> out (dense). z>=1: e=z-1: bufC[grouped] @ wdown[e] -> g_routed[token]
__global__ __launch_bounds__(256)
void moe_down_tf32(const float* __restrict__ shd, const float* __restrict__ wdown,
                   float* __restrict__ out) {
    int z = blockIdx.z;
    int m0 = blockIdx.y * 128;
    int cnt, abase;
    const float* B;
    const float* Asrc;
    float* Dst;
    if (z == 0) {
        cnt = T; abase = 0;
        B = shd; Asrc = g_bufA; Dst = out;
    } else {
        int e = z - 1;
        cnt = g_count[e];
        if (m0 >= cnt) return;
        abase = g_base[e];
        B = wdown + (size_t)e * F * H;
        Asrc = g_bufC; Dst = g_routed;
    }
    int n0 = blockIdx.x * 128;
    __shared__ unsigned As[2][KT * SMS];
    __shared__ unsigned Bs[2][KT * SMS];
    __shared__ int rtok[128];
    int tid = threadIdx.x;
    if (tid < 128) {
        int mm = m0 + tid;
        rtok[tid] = (z == 0) ? mm : ((mm < cnt) ? g_perm[abase + mm] : -1);
    }
    __syncthreads();
    int warp = tid >> 5, lane = tid & 31;
    int g = lane >> 2, tg = lane & 3;
    int wm = (warp >> 2) * 64, wn = (warp & 3) * 32;
    int arow = tid >> 1, acol = (tid & 1) * 8;
    int bk = tid >> 4, bn = (tid & 15) * 8;
    bool arow_ok = (m0 + arow) < cnt;
    float amask = arow_ok ? 1.f : 0.f;
    const float* Ap = Asrc + (size_t)(abase + (arow_ok ? (m0 + arow) : 0)) * F + acol;
    const float* Bp = B + (size_t)bk * H + n0 + bn;
    float acc[4][4][4] = {};

    float4 av0 = *(const float4*)Ap, av1 = *(const float4*)(Ap + 4);
    float4 bv0 = *(const float4*)Bp, bv1 = *(const float4*)(Bp + 4);
    FILL_A(As[0], av0, av1, amask);
    FILL_B(Bs[0], bv0, bv1);
    __syncthreads();
    int nt = F / KT;
    int buf = 0;
    for (int kt = 0; kt < nt; kt++) {
        if (kt + 1 < nt) {
            av0 = *(const float4*)(Ap + (kt + 1) * KT);
            av1 = *(const float4*)(Ap + (kt + 1) * KT + 4);
            bv0 = *(const float4*)(Bp + (size_t)(kt + 1) * KT * H);
            bv1 = *(const float4*)(Bp + (size_t)(kt + 1) * KT * H + 4);
        }
        const unsigned* Asb = As[buf];
        const unsigned* Bsb = Bs[buf];
        MMA_TILE_COMPUTE(Asb, Bsb)
        if (kt + 1 < nt) {
            FILL_A(As[buf ^ 1], av0, av1, amask);
            FILL_B(Bs[buf ^ 1], bv0, bv1);
        }
        __syncthreads();
        buf ^= 1;
    }
#pragma unroll
    for (int mt = 0; mt < 4; mt++) {
#pragma unroll
        for (int nt2 = 0; nt2 < 4; nt2++) {
            int mi0 = wm + mt * 16 + g;
            int c = n0 + wn + nt2 * 8 + 2 * tg;
            if (m0 + mi0 < cnt) {
                int t = rtok[mi0];
                *(float2*)(Dst + (size_t)t * H + c) =
                    make_float2(acc[mt][nt2][0], acc[mt][nt2][1]);
            }
            if (m0 + mi0 + 8 < cnt) {
                int t = rtok[mi0 + 8];
                *(float2*)(Dst + (size_t)t * H + c) =
                    make_float2(acc[mt][nt2][2], acc[mt][nt2][3]);
            }
        }
    }
}

// ---------------- rope + per-head rmsnorm → transposed tf32 (+V convert) ----
// grid (T, 6): h = 0..15 q (rope+rms), 16..19 k (rope+rms), 20..23 v (convert)
__global__ void rope_rms_kernel(const int* __restrict__ pos) {
    int t = blockIdx.x;
    int grp = threadIdx.x >> 6;
    int d = threadIdx.x & 63;
    int h = blockIdx.y * 4 + grp;
    if (h >= NH + NKV) {
        int kh = h - NH - NKV;
        float v = g_qkv[(size_t)t * QKV_N + (NH + NKV) * D + kh * D + d];
        g_vT[((size_t)kh * T + t) * D + d] = f2tf(v);
        return;
    }
    const float* src;
    unsigned* dstT;
    if (h < NH) {
        src = g_qkv + (size_t)t * QKV_N + h * D;
        dstT = g_qT + (size_t)h * D * T;
    } else {
        int kh = h - NH;
        src = g_qkv + (size_t)t * QKV_N + NH * D + kh * D;
        dstT = g_kT + (size_t)kh * D * T;
    }
    int i = d & 31;
    float inv = powf(500000.0f, -((float)i) / 32.0f);
    float ang = (float)pos[t] * inv;
    float sn, cs;
    sincosf(ang, &sn, &cs);
    float x1 = src[i], x2 = src[i + 32];
    float val = (d < 32) ? (x1 * cs - x2 * sn) : (x2 * cs + x1 * sn);
    float sq = val * val;
#pragma unroll
    for (int off = 16; off; off >>= 1) sq += __shfl_xor_sync(0xffffffffu, sq, off);
    __shared__ float sw2[4][2];
    if ((d & 31) == 0) sw2[grp][d >> 5] = sq;
    __syncthreads();
    float tot = sw2[grp][0] + sw2[grp][1];
    dstT[(size_t)d * T + t] = f2tf(val * rsqrtf(tot / (float)D + EPS));
}

// ================= tensor-core flash attention ===============================
#define AS 72
__global__ __launch_bounds__(128)
void attn_tc() {
    extern __shared__ unsigned usmem[];
    unsigned* Ks = usmem;
    unsigned* Vs = usmem + 64 * AS;
    unsigned* Ps = usmem + 2 * 64 * AS;
    int qt = (int)gridDim.x - 1 - (int)blockIdx.x;
    int head = blockIdx.y;
    int kvh = head >> 2;
    int tid = threadIdx.x, warp = tid >> 5, lane = tid & 31;
    int g = lane >> 2, tg = lane & 3;
    int q0 = qt * 64;
    int wq = warp * 16;

    for (int e = tid; e < 64 * 64; e += 128) {
        int d = e >> 6, r = e & 63;
        Ks[d * AS + r] = g_qT[(size_t)head * D * T + (size_t)d * T + q0 + r];
    }
    __syncthreads();
    unsigned qf[8][4];
#pragma unroll
    for (int kc = 0; kc < 8; kc++) {
        qf[kc][0] = Ks[(kc * 8 + tg) * AS + wq + g];
        qf[kc][1] = Ks[(kc * 8 + tg) * AS + wq + g + 8];
        qf[kc][2] = Ks[(kc * 8 + tg + 4) * AS + wq + g];
        qf[kc][3] = Ks[(kc * 8 + tg + 4) * AS + wq + g + 8];
    }
    int r0 = q0 + wq + g, r1 = r0 + 8;
    float m0 = -INFINITY, m1 = -INFINITY, l0 = 0.f, l1 = 0.f;
    float accO[8][4] = {};

    for (int j0 = 0; j0 <= qt; j0++) {
        int k0 = j0 * 64;
        __syncthreads();
        for (int e = tid; e < 64 * 64; e += 128) {
            int d = e >> 6, c = e & 63;
            Ks[d * AS + c] = g_kT[(size_t)kvh * D * T + (size_t)d * T + k0 + c];
        }
        for (int e = tid; e < 64 * 64; e += 128) {
            int c = e >> 6, d = e & 63;
            Vs[c * AS + d] = g_vT[((size_t)kvh * T + k0 + c) * D + d];
        }
        __syncthreads();
        float sc[8][4] = {};
#pragma unroll
        for (int kc = 0; kc < 8; kc++) {
            unsigned bfr[8][2];
#pragma unroll
            for (int n = 0; n < 8; n++) {
                bfr[n][0] = Ks[(kc * 8 + tg) * AS + n * 8 + g];
                bfr[n][1] = Ks[(kc * 8 + tg + 4) * AS + n * 8 + g];
            }
#pragma unroll
            for (int n = 0; n < 8; n++) mma_tf32(sc[n], qf[kc], bfr[n]);
        }
        float mx0 = -INFINITY, mx1 = -INFINITY;
#pragma unroll
        for (int n = 0; n < 8; n++) {
            int c0 = k0 + n * 8 + 2 * tg;
            float s0 = (c0 <= r0) ? sc[n][0] * ATT_SCALE : -INFINITY;
            float s1 = (c0 + 1 <= r0) ? sc[n][1] * ATT_SCALE : -INFINITY;
            float s2 = (c0 <= r1) ? sc[n][2] * ATT_SCALE : -INFINITY;
            float s3 = (c0 + 1 <= r1) ? sc[n][3] * ATT_SCALE : -INFINITY;
            sc[n][0] = s0; sc[n][1] = s1; sc[n][2] = s2; sc[n][3] = s3;
            mx0 = fmaxf(mx0, fmaxf(s0, s1));
            mx1 = fmaxf(mx1, fmaxf(s2, s3));
        }
        mx0 = fmaxf(mx0, __shfl_xor_sync(0xffffffffu, mx0, 1));
        mx0 = fmaxf(mx0, __shfl_xor_sync(0xffffffffu, mx0, 2));
        mx1 = fmaxf(mx1, __shfl_xor_sync(0xffffffffu, mx1, 1));
        mx1 = fmaxf(mx1, __shfl_xor_sync(0xffffffffu, mx1, 2));
        float nm0 = fmaxf(m0, mx0), nm1 = fmaxf(m1, mx1);
        float corr0 = __expf(m0 - nm0), corr1 = __expf(m1 - nm1);
        m0 = nm0; m1 = nm1;
        float rs0 = 0.f, rs1 = 0.f;
#pragma unroll
        for (int n = 0; n < 8; n++) {
            int cl = n * 8 + 2 * tg;
            float p0 = __expf(sc[n][0] - nm0);
            float p1 = __expf(sc[n][1] - nm0);
            float p2 = __expf(sc[n][2] - nm1);
            float p3 = __expf(sc[n][3] - nm1);
            rs0 += p0 + p1; rs1 += p2 + p3;
            Ps[cl * AS + wq + g] = f2tf(p0);
            Ps[(cl + 1) * AS + wq + g] = f2tf(p1);
            Ps[cl * AS + wq + g + 8] = f2tf(p2);
            Ps[(cl + 1) * AS + wq + g + 8] = f2tf(p3);
        }
        rs0 += __shfl_xor_sync(0xffffffffu, rs0, 1);
        rs0 += __shfl_xor_sync(0xffffffffu, rs0, 2);
        rs1 += __shfl_xor_sync(0xffffffffu, rs1, 1);
        rs1 += __shfl_xor_sync(0xffffffffu, rs1, 2);
        l0 = l0 * corr0 + rs0;
        l1 = l1 * corr1 + rs1;
#pragma unroll
        for (int n = 0; n < 8; n++) {
            accO[n][0] *= corr0; accO[n][1] *= corr0;
            accO[n][2] *= corr1; accO[n][3] *= corr1;
        }
        __syncwarp();
#pragma unroll
        for (int kc = 0; kc < 8; kc++) {
            unsigned af[4];
            af[0] = Ps[(kc * 8 + tg) * AS + wq + g];
            af[1] = Ps[(kc * 8 + tg) * AS + wq + g + 8];
            af[2] = Ps[(kc * 8 + tg + 4) * AS + wq + g];
            af[3] = Ps[(kc * 8 + tg + 4) * AS + wq + g + 8];
#pragma unroll
            for (int n = 0; n < 8; n++) {
                unsigned bfr2[2];
                bfr2[0] = Vs[(kc * 8 + tg) * AS + n * 8 + g];
                bfr2[1] = Vs[(kc * 8 + tg + 4) * AS + n * 8 + g];
                mma_tf32(accO[n], af, bfr2);
            }
        }
    }
    float inv0 = 1.f / l0, inv1 = 1.f / l1;
#pragma unroll
    for (int n = 0; n < 8; n++) {
        int c = head * D + n * 8 + 2 * tg;
        *(float2*)&g_ao[(size_t)r0 * (NH * D) + c] =
            make_float2(accO[n][0] * inv0, accO[n][1] * inv0);
        *(float2*)&g_ao[(size_t)r1 * (NH * D) + c] =
            make_float2(accO[n][2] * inv1, accO[n][3] * inv1);
    }
}

// ---------------- launch ------------------------------------------------------
extern "C" void kernel_launch(void* const* d_in, const int* in_sizes, int n_in,
                              void* d_out, int out_size) {
    const int* pos = (const int*)d_in[0];
    const float* hidden = (const float*)d_in[1];
    const float* ln1 = (const float*)d_in[2];
    const float* ln2 = (const float*)d_in[3];
    const float* wqkv = (const float*)d_in[4];
    const float* wo = (const float*)d_in[5];
    const float* rw = (const float*)d_in[6];
    const float* wgate = (const float*)d_in[7];
    const float* wup = (const float*)d_in[8];
    const float* wdown = (const float*)d_in[9];
    const float* shg = (const float*)d_in[10];
    const float* shu = (const float*)d_in[11];
    const float* shd = (const float*)d_in[12];
    float* out = (float*)d_out;
    float* resid = out + (size_t)T * H;

    float *p_h1, *p_h2, *p_qkv, *p_ao;
    cudaGetSymbolAddress((void**)&p_h1, g_h1);
    cudaGetSymbolAddress((void**)&p_h2, g_h2);
    cudaGetSymbolAddress((void**)&p_qkv, g_qkv);
    cudaGetSymbolAddress((void**)&p_ao, g_ao);

    static int attn_smem_set = 0;
    const int ATTN_SMEM = 3 * 64 * AS * 4;
    if (!attn_smem_set) {
        cudaFuncSetAttribute(attn_tc, cudaFuncAttributeMaxDynamicSharedMemorySize, ATTN_SMEM);
        attn_smem_set = 1;
    }

    zero_kernel<<<1, 32>>>();
    rmsnorm_kernel<<<T, 256>>>(hidden, ln1, p_h1);
    gemm_tf32<<<dim3(QKV_N / 128, T / 128), 256>>>(p_h1, wqkv, p_qkv, T, QKV_N, H, nullptr);
    rope_rms_kernel<<<dim3(T, 6), 256>>>(pos);
    attn_tc<<<dim3(T / 64, NH), 128, ATTN_SMEM>>>();
    gemm_tf32<<<dim3(H / 128, T / 128), 256>>>(p_ao, wo, resid, T, H, NH * D, hidden);
    rmsnorm_router_kernel<<<T, 256>>>(resid, ln2, rw, p_h2);
    scan_kernel<<<1, 32>>>();
    scatter_kernel<<<T / 256, 256>>>();
    // all 18 MoE up-projections in one launch
    moe_proj_tf32<<<dim3(F / 128, T / 128, 2 + 2 * E), 256>>>(shg, shu, wgate, wup);
    // silu*mul for both pairs
    silumul2_kernel<<<dim3((T * F) / 256, 2), 256>>>();
    // both down projections in one launch
    moe_down_tf32<<<dim3(H / 128, T / 128, 1 + E), 256>>>(shd, wdown, out);
    add_routed_kernel<<<(T * H) / 256, 256>>>(out);
    (void)in_sizes; (void)n_in; (void)out_size;
}

// round 10
// speedup vs baseline: 2.9533x; 1.0854x over previous
#include <cuda_runtime.h>
#include <math.h>

#define T 2048
#define H 1024
#define NH 16
#define NKV 4
#define D 64
#define E 8
#define F 1024
#define QKV_N ((NH + 2*NKV) * D)   // 1536
#define EPS 1e-5f
#define ATT_SCALE 0.125f

// ---------------- scratch ---------------------------------------------------
__device__ float    g_h1[T * H];
__device__ float    g_qkv[T * QKV_N];
__device__ unsigned g_qT[NH * D * T];    // tf32 bits, [head][d][t]
__device__ unsigned g_kT[NKV * D * T];   // tf32 bits, [kvh][d][t]
__device__ unsigned g_vT[NKV * T * D];   // tf32 bits, [kvh][t][d]
__device__ float    g_ao[T * NH * D];
__device__ float    g_h2[T * H];
__device__ float    g_bufA[T * F];       // shared gate
__device__ float    g_bufB[T * F];       // shared up
__device__ float    g_bufC[T * F];       // routed gate (expert-grouped rows)
__device__ float    g_bufD[T * F];       // routed up
__device__ float    g_routed[T * H];     // routed expert output (dense by token)
__device__ float2   g_cs[T * 32];        // rope cos/sin table
__device__ int      g_eidx[T];
__device__ float    g_gate[T];
__device__ int      g_perm[T];
__device__ int      g_count[E];
__device__ int      g_base[E];
__device__ int      g_offs[E];

// ---------------- small utility kernels -------------------------------------
// rope table (T*32 entries) + zero g_count
__global__ void rope_table_kernel(const int* __restrict__ pos) {
    int idx = blockIdx.x * blockDim.x + threadIdx.x;   // 0..65535
    if (idx < E) g_count[idx] = 0;
    int t = idx >> 5, i = idx & 31;
    float inv = powf(500000.0f, -((float)i) / 32.0f);
    float ang = (float)pos[t] * inv;
    float sn, cs;
    sincosf(ang, &sn, &cs);
    g_cs[idx] = make_float2(cs, sn);
}
__global__ void scan_kernel() {
    if (threadIdx.x == 0) {
        int b = 0;
        for (int e = 0; e < E; e++) { g_base[e] = b; b += g_count[e]; g_offs[e] = 0; }
    }
}
__global__ void scatter_kernel() {
    int t = blockIdx.x * blockDim.x + threadIdx.x;
    if (t < T) {
        int e = g_eidx[t];
        int p = g_base[e] + atomicAdd(&g_offs[e], 1);
        g_perm[p] = t;
    }
}
// out += routed
__global__ void add_routed_kernel(float* __restrict__ out) {
    int i = blockIdx.x * blockDim.x + threadIdx.x;
    out[i] += g_routed[i];
}

// ---------------- rmsnorm (plain) -------------------------------------------
__global__ void rmsnorm_kernel(const float* __restrict__ in, const float* __restrict__ w,
                               float* __restrict__ out) {
    int row = blockIdx.x, tid = threadIdx.x;
    const float* p = in + (size_t)row * H;
    float v[4];
    float s = 0.f;
#pragma unroll
    for (int i = 0; i < 4; i++) { v[i] = p[tid + i * 256]; s += v[i] * v[i]; }
#pragma unroll
    for (int off = 16; off; off >>= 1) s += __shfl_xor_sync(0xffffffffu, s, off);
    __shared__ float sw[8];
    if ((tid & 31) == 0) sw[tid >> 5] = s;
    __syncthreads();
    __shared__ float stot;
    if (tid == 0) {
        float t2 = 0.f;
        for (int i = 0; i < 8; i++) t2 += sw[i];
        stot = t2;
    }
    __syncthreads();
    float r = rsqrtf(stot / (float)H + EPS);
    float* o = out + (size_t)row * H;
#pragma unroll
    for (int i = 0; i < 4; i++) o[tid + i * 256] = v[i] * r * w[tid + i * 256];
}

// ---------------- rmsnorm2 + router fused -----------------------------------
__global__ void rmsnorm_router_kernel(const float* __restrict__ in,
                                      const float* __restrict__ w,
                                      const float* __restrict__ rw,
                                      float* __restrict__ out) {
    int row = blockIdx.x, tid = threadIdx.x;
    const float* p = in + (size_t)row * H;
    float v[4];
    float s = 0.f;
#pragma unroll
    for (int i = 0; i < 4; i++) { v[i] = p[tid + i * 256]; s += v[i] * v[i]; }
#pragma unroll
    for (int off = 16; off; off >>= 1) s += __shfl_xor_sync(0xffffffffu, s, off);
    __shared__ float sw[8];
    if ((tid & 31) == 0) sw[tid >> 5] = s;
    __syncthreads();
    __shared__ float stot;
    if (tid == 0) {
        float t2 = 0.f;
        for (int i = 0; i < 8; i++) t2 += sw[i];
        stot = t2;
    }
    __syncthreads();
    float r = rsqrtf(stot / (float)H + EPS);
    float* o = out + (size_t)row * H;
    float acc[E] = {};
#pragma unroll
    for (int i = 0; i < 4; i++) {
        int h = tid + i * 256;
        float hv = v[i] * r * w[h];
        o[h] = hv;
        const float* rr = rw + (size_t)h * E;
#pragma unroll
        for (int e = 0; e < E; e++) acc[e] += hv * rr[e];
    }
#pragma unroll
    for (int e = 0; e < E; e++)
#pragma unroll
        for (int off = 16; off; off >>= 1)
            acc[e] += __shfl_xor_sync(0xffffffffu, acc[e], off);
    __shared__ float sred[8][E];
    int wp = tid >> 5, lane = tid & 31;
    if (lane == 0)
        for (int e = 0; e < E; e++) sred[wp][e] = acc[e];
    __syncthreads();
    if (tid == 0) {
        float best = -INFINITY;
        int bi = 0;
        for (int e = 0; e < E; e++) {
            float vv = 0.f;
            for (int ww = 0; ww < 8; ww++) vv += sred[ww][e];
            if (vv > best) { best = vv; bi = e; }
        }
        g_eidx[row] = bi;
        g_gate[row] = 1.f / (1.f + expf(-best));
        atomicAdd(&g_count[bi], 1);
    }
}

// =================== TF32 tensor-core machinery ==============================
__device__ __forceinline__ unsigned f2tf(float x) {
    unsigned r;
    asm("cvt.rna.tf32.f32 %0, %1;" : "=r"(r) : "f"(x));
    return r;
}
__device__ __forceinline__ void mma_tf32(float* c, const unsigned* a, const unsigned* b) {
    asm volatile(
        "mma.sync.aligned.m16n8k8.row.col.f32.tf32.tf32.f32 "
        "{%0,%1,%2,%3},{%4,%5,%6,%7},{%8,%9},{%0,%1,%2,%3};"
        : "+f"(c[0]), "+f"(c[1]), "+f"(c[2]), "+f"(c[3])
        : "r"(a[0]), "r"(a[1]), "r"(a[2]), "r"(a[3]), "r"(b[0]), "r"(b[1]));
}

#define KT 16
#define SMS 136

#define MMA_TILE_COMPUTE(Asb, Bsb)                                             \
    _Pragma("unroll")                                                          \
    for (int k8 = 0; k8 < KT; k8 += 8) {                                       \
        unsigned af[4][4], bf[4][2];                                           \
        _Pragma("unroll")                                                      \
        for (int mt = 0; mt < 4; mt++) {                                       \
            int mb = wm + mt * 16;                                             \
            af[mt][0] = Asb[(k8 + tg) * SMS + mb + g];                         \
            af[mt][1] = Asb[(k8 + tg) * SMS + mb + g + 8];                     \
            af[mt][2] = Asb[(k8 + tg + 4) * SMS + mb + g];                     \
            af[mt][3] = Asb[(k8 + tg + 4) * SMS + mb + g + 8];                 \
        }                                                                      \
        _Pragma("unroll")                                                      \
        for (int nt2 = 0; nt2 < 4; nt2++) {                                    \
            int nb = wn + nt2 * 8;                                             \
            bf[nt2][0] = Bsb[(k8 + tg) * SMS + nb + g];                        \
            bf[nt2][1] = Bsb[(k8 + tg + 4) * SMS + nb + g];                    \
        }                                                                      \
        _Pragma("unroll")                                                      \
        for (int mt = 0; mt < 4; mt++)                                         \
            _Pragma("unroll")                                                  \
            for (int nt2 = 0; nt2 < 4; nt2++)                                  \
                mma_tf32(acc[mt][nt2], af[mt], bf[nt2]);                       \
    }

#define FILL_A(dst, v0, v1, scale)                                             \
    do {                                                                       \
        (dst)[(acol + 0) * SMS + arow] = f2tf((v0).x * (scale));               \
        (dst)[(acol + 1) * SMS + arow] = f2tf((v0).y * (scale));               \
        (dst)[(acol + 2) * SMS + arow] = f2tf((v0).z * (scale));               \
        (dst)[(acol + 3) * SMS + arow] = f2tf((v0).w * (scale));               \
        (dst)[(acol + 4) * SMS + arow] = f2tf((v1).x * (scale));               \
        (dst)[(acol + 5) * SMS + arow] = f2tf((v1).y * (scale));               \
        (dst)[(acol + 6) * SMS + arow] = f2tf((v1).z * (scale));               \
        (dst)[(acol + 7) * SMS + arow] = f2tf((v1).w * (scale));               \
    } while (0)

// silu(gate)*up fused A-fill (moe_down)
#define SILU1(x) ((x) / (1.f + __expf(-(x))))
#define FILL_A_SILU(dst, gv0, gv1, uv0, uv1, mask)                             \
    do {                                                                       \
        (dst)[(acol + 0) * SMS + arow] = f2tf(SILU1((gv0).x) * (uv0).x * (mask)); \
        (dst)[(acol + 1) * SMS + arow] = f2tf(SILU1((gv0).y) * (uv0).y * (mask)); \
        (dst)[(acol + 2) * SMS + arow] = f2tf(SILU1((gv0).z) * (uv0).z * (mask)); \
        (dst)[(acol + 3) * SMS + arow] = f2tf(SILU1((gv0).w) * (uv0).w * (mask)); \
        (dst)[(acol + 4) * SMS + arow] = f2tf(SILU1((gv1).x) * (uv1).x * (mask)); \
        (dst)[(acol + 5) * SMS + arow] = f2tf(SILU1((gv1).y) * (uv1).y * (mask)); \
        (dst)[(acol + 6) * SMS + arow] = f2tf(SILU1((gv1).z) * (uv1).z * (mask)); \
        (dst)[(acol + 7) * SMS + arow] = f2tf(SILU1((gv1).w) * (uv1).w * (mask)); \
    } while (0)

#define FILL_B(dst, v0, v1)                                                    \
    do {                                                                       \
        unsigned* bd_ = (dst) + bk * SMS + bn;                                 \
        bd_[0] = f2tf((v0).x); bd_[1] = f2tf((v0).y);                          \
        bd_[2] = f2tf((v0).z); bd_[3] = f2tf((v0).w);                          \
        bd_[4] = f2tf((v1).x); bd_[5] = f2tf((v1).y);                          \
        bd_[6] = f2tf((v1).z); bd_[7] = f2tf((v1).w);                          \
    } while (0)

// ---------------- dense tf32 GEMM -------------------------------------------
__global__ __launch_bounds__(256)
void gemm_tf32(const float* __restrict__ A, const float* __restrict__ B,
               float* __restrict__ C, int M, int N, int K,
               const float* __restrict__ addsrc) {
    __shared__ unsigned As[2][KT * SMS];
    __shared__ unsigned Bs[2][KT * SMS];
    int tid = threadIdx.x;
    int warp = tid >> 5, lane = tid & 31;
    int g = lane >> 2, tg = lane & 3;
    int wm = (warp >> 2) * 64, wn = (warp & 3) * 32;
    int m0 = blockIdx.y * 128, n0 = blockIdx.x * 128;
    int arow = tid >> 1, acol = (tid & 1) * 8;
    int bk = tid >> 4, bn = (tid & 15) * 8;
    const float* Ap = A + (size_t)(m0 + arow) * K + acol;
    const float* Bp = B + (size_t)bk * N + n0 + bn;
    float acc[4][4][4] = {};

    float4 av0 = *(const float4*)Ap, av1 = *(const float4*)(Ap + 4);
    float4 bv0 = *(const float4*)Bp, bv1 = *(const float4*)(Bp + 4);
    FILL_A(As[0], av0, av1, 1.f);
    FILL_B(Bs[0], bv0, bv1);
    __syncthreads();
    int nt = K / KT;
    int buf = 0;
    for (int kt = 0; kt < nt; kt++) {
        if (kt + 1 < nt) {
            av0 = *(const float4*)(Ap + (kt + 1) * KT);
            av1 = *(const float4*)(Ap + (kt + 1) * KT + 4);
            bv0 = *(const float4*)(Bp + (size_t)(kt + 1) * KT * N);
            bv1 = *(const float4*)(Bp + (size_t)(kt + 1) * KT * N + 4);
        }
        const unsigned* Asb = As[buf];
        const unsigned* Bsb = Bs[buf];
        MMA_TILE_COMPUTE(Asb, Bsb)
        if (kt + 1 < nt) {
            FILL_A(As[buf ^ 1], av0, av1, 1.f);
            FILL_B(Bs[buf ^ 1], bv0, bv1);
        }
        __syncthreads();
        buf ^= 1;
    }
#pragma unroll
    for (int mt = 0; mt < 4; mt++) {
#pragma unroll
        for (int nt2 = 0; nt2 < 4; nt2++) {
            int r0 = m0 + wm + mt * 16 + g;
            int c = n0 + wn + nt2 * 8 + 2 * tg;
            float2 v0 = make_float2(acc[mt][nt2][0], acc[mt][nt2][1]);
            float2 v1 = make_float2(acc[mt][nt2][2], acc[mt][nt2][3]);
            if (addsrc) {
                float2 r = *(const float2*)(addsrc + (size_t)r0 * N + c);
                v0.x += r.x; v0.y += r.y;
                float2 r2 = *(const float2*)(addsrc + (size_t)(r0 + 8) * N + c);
                v1.x += r2.x; v1.y += r2.y;
            }
            *(float2*)(C + (size_t)r0 * N + c) = v0;
            *(float2*)(C + (size_t)(r0 + 8) * N + c) = v1;
        }
    }
}

// ------------- MoE up-projections mega-GEMM (z = 0..17) ---------------------
__global__ __launch_bounds__(256)
void moe_proj_tf32(const float* __restrict__ shg, const float* __restrict__ shu,
                   const float* __restrict__ wgate, const float* __restrict__ wup) {
    int z = blockIdx.z;
    int m0 = blockIdx.y * 128;
    int cnt, obase;
    const float* B;
    float* Cbuf;
    bool gathered;
    if (z < 2) {
        B = z ? shu : shg;
        Cbuf = z ? g_bufB : g_bufA;
        cnt = T; obase = 0; gathered = false;
    } else {
        int e = (z - 2) >> 1, kind = (z - 2) & 1;
        cnt = g_count[e];
        if (m0 >= cnt) return;
        B = (kind ? wup : wgate) + (size_t)e * H * F;
        Cbuf = kind ? g_bufD : g_bufC;
        obase = g_base[e]; gathered = true;
    }
    int n0 = blockIdx.x * 128;
    __shared__ unsigned As[2][KT * SMS];
    __shared__ unsigned Bs[2][KT * SMS];
    __shared__ int srcrow[128];
    int tid = threadIdx.x;
    if (tid < 128) {
        int mm = m0 + tid;
        srcrow[tid] = gathered ? ((mm < cnt) ? g_perm[obase + mm] : -1) : mm;
    }
    __syncthreads();
    int warp = tid >> 5, lane = tid & 31;
    int g = lane >> 2, tg = lane & 3;
    int wm = (warp >> 2) * 64, wn = (warp & 3) * 32;
    int arow = tid >> 1, acol = (tid & 1) * 8;
    int bk = tid >> 4, bn = (tid & 15) * 8;
    int tok = srcrow[arow];
    float gsc = gathered ? ((tok >= 0) ? g_gate[tok] : 0.f) : 1.f;
    const float* Ap = g_h2 + (size_t)((tok >= 0) ? tok : 0) * H + acol;
    const float* Bp = B + (size_t)bk * F + n0 + bn;
    float acc[4][4][4] = {};

    float4 av0 = *(const float4*)Ap, av1 = *(const float4*)(Ap + 4);
    float4 bv0 = *(const float4*)Bp, bv1 = *(const float4*)(Bp + 4);
    FILL_A(As[0], av0, av1, gsc);
    FILL_B(Bs[0], bv0, bv1);
    __syncthreads();
    int nt = H / KT;
    int buf = 0;
    for (int kt = 0; kt < nt; kt++) {
        if (kt + 1 < nt) {
            av0 = *(const float4*)(Ap + (kt + 1) * KT);
            av1 = *(const float4*)(Ap + (kt + 1) * KT + 4);
            bv0 = *(const float4*)(Bp + (size_t)(kt + 1) * KT * F);
            bv1 = *(const float4*)(Bp + (size_t)(kt + 1) * KT * F + 4);
        }
        const unsigned* Asb = As[buf];
        const unsigned* Bsb = Bs[buf];
        MMA_TILE_COMPUTE(Asb, Bsb)
        if (kt + 1 < nt) {
            FILL_A(As[buf ^ 1], av0, av1, gsc);
            FILL_B(Bs[buf ^ 1], bv0, bv1);
        }
        __syncthreads();
        buf ^= 1;
    }
#pragma unroll
    for (int mt = 0; mt < 4; mt++) {
#pragma unroll
        for (int nt2 = 0; nt2 < 4; nt2++) {
            int mi0 = wm + mt * 16 + g;
            int c = n0 + wn + nt2 * 8 + 2 * tg;
            if (m0 + mi0 < cnt)
                *(float2*)(Cbuf + (size_t)(obase + m0 + mi0) * F + c) =
                    make_float2(acc[mt][nt2][0], acc[mt][nt2][1]);
            if (m0 + mi0 + 8 < cnt)
                *(float2*)(Cbuf + (size_t)(obase + m0 + mi0 + 8) * F + c) =
                    make_float2(acc[mt][nt2][2], acc[mt][nt2][3]);
        }
    }
}

// ------------- MoE down-projections mega-GEMM (z = 0..8), silu fused --------
// z=0: silu(bufA)*bufB @ shd -> out. z>=1: silu(bufC)*bufD @ wdown[e] -> g_routed
__global__ __launch_bounds__(256, 2)
void moe_down_tf32(const float* __restrict__ shd, const float* __restrict__ wdown,
                   float* __restrict__ out) {
    int z = blockIdx.z;
    int m0 = blockIdx.y * 128;
    int cnt, abase;
    const float* B;
    const float* Agate;
    const float* Aup;
    float* Dst;
    if (z == 0) {
        cnt = T; abase = 0;
        B = shd; Agate = g_bufA; Aup = g_bufB; Dst = out;
    } else {
        int e = z - 1;
        cnt = g_count[e];
        if (m0 >= cnt) return;
        abase = g_base[e];
        B = wdown + (size_t)e * F * H;
        Agate = g_bufC; Aup = g_bufD; Dst = g_routed;
    }
    int n0 = blockIdx.x * 128;
    __shared__ unsigned As[2][KT * SMS];
    __shared__ unsigned Bs[2][KT * SMS];
    __shared__ int rtok[128];
    int tid = threadIdx.x;
    if (tid < 128) {
        int mm = m0 + tid;
        rtok[tid] = (z == 0) ? mm : ((mm < cnt) ? g_perm[abase + mm] : -1);
    }
    __syncthreads();
    int warp = tid >> 5, lane = tid & 31;
    int g = lane >> 2, tg = lane & 3;
    int wm = (warp >> 2) * 64, wn = (warp & 3) * 32;
    int arow = tid >> 1, acol = (tid & 1) * 8;
    int bk = tid >> 4, bn = (tid & 15) * 8;
    bool arow_ok = (m0 + arow) < cnt;
    float amask = arow_ok ? 1.f : 0.f;
    size_t aoff = (size_t)(abase + (arow_ok ? (m0 + arow) : 0)) * F + acol;
    const float* Apg = Agate + aoff;
    const float* Apu = Aup + aoff;
    const float* Bp = B + (size_t)bk * H + n0 + bn;
    float acc[4][4][4] = {};

    float4 gv0 = *(const float4*)Apg, gv1 = *(const float4*)(Apg + 4);
    float4 uv0 = *(const float4*)Apu, uv1 = *(const float4*)(Apu + 4);
    float4 bv0 = *(const float4*)Bp, bv1 = *(const float4*)(Bp + 4);
    FILL_A_SILU(As[0], gv0, gv1, uv0, uv1, amask);
    FILL_B(Bs[0], bv0, bv1);
    __syncthreads();
    int nt = F / KT;
    int buf = 0;
    for (int kt = 0; kt < nt; kt++) {
        if (kt + 1 < nt) {
            gv0 = *(const float4*)(Apg + (kt + 1) * KT);
            gv1 = *(const float4*)(Apg + (kt + 1) * KT + 4);
            uv0 = *(const float4*)(Apu + (kt + 1) * KT);
            uv1 = *(const float4*)(Apu + (kt + 1) * KT + 4);
            bv0 = *(const float4*)(Bp + (size_t)(kt + 1) * KT * H);
            bv1 = *(const float4*)(Bp + (size_t)(kt + 1) * KT * H + 4);
        }
        const unsigned* Asb = As[buf];
        const unsigned* Bsb = Bs[buf];
        MMA_TILE_COMPUTE(Asb, Bsb)
        if (kt + 1 < nt) {
            FILL_A_SILU(As[buf ^ 1], gv0, gv1, uv0, uv1, amask);
            FILL_B(Bs[buf ^ 1], bv0, bv1);
        }
        __syncthreads();
        buf ^= 1;
    }
#pragma unroll
    for (int mt = 0; mt < 4; mt++) {
#pragma unroll
        for (int nt2 = 0; nt2 < 4; nt2++) {
            int mi0 = wm + mt * 16 + g;
            int c = n0 + wn + nt2 * 8 + 2 * tg;
            if (m0 + mi0 < cnt) {
                int t = rtok[mi0];
                *(float2*)(Dst + (size_t)t * H + c) =
                    make_float2(acc[mt][nt2][0], acc[mt][nt2][1]);
            }
            if (m0 + mi0 + 8 < cnt) {
                int t = rtok[mi0 + 8];
                *(float2*)(Dst + (size_t)t * H + c) =
                    make_float2(acc[mt][nt2][2], acc[mt][nt2][3]);
            }
        }
    }
}

// ---------------- rope + per-head rmsnorm → transposed tf32 (+V convert) ----
// grid (T, 6): h = 0..15 q (rope+rms), 16..19 k (rope+rms), 20..23 v (convert)
__global__ void rope_rms_kernel() {
    int t = blockIdx.x;
    int grp = threadIdx.x >> 6;
    int d = threadIdx.x & 63;
    int h = blockIdx.y * 4 + grp;
    if (h >= NH + NKV) {
        int kh = h - NH - NKV;
        float v = g_qkv[(size_t)t * QKV_N + (NH + NKV) * D + kh * D + d];
        g_vT[((size_t)kh * T + t) * D + d] = f2tf(v);
        return;
    }
    const float* src;
    unsigned* dstT;
    if (h < NH) {
        src = g_qkv + (size_t)t * QKV_N + h * D;
        dstT = g_qT + (size_t)h * D * T;
    } else {
        int kh = h - NH;
        src = g_qkv + (size_t)t * QKV_N + NH * D + kh * D;
        dstT = g_kT + (size_t)kh * D * T;
    }
    int i = d & 31;
    float2 cspair = g_cs[t * 32 + i];
    float cs = cspair.x, sn = cspair.y;
    float x1 = src[i], x2 = src[i + 32];
    float val = (d < 32) ? (x1 * cs - x2 * sn) : (x2 * cs + x1 * sn);
    float sq = val * val;
#pragma unroll
    for (int off = 16; off; off >>= 1) sq += __shfl_xor_sync(0xffffffffu, sq, off);
    __shared__ float sw2[4][2];
    if ((d & 31) == 0) sw2[grp][d >> 5] = sq;
    __syncthreads();
    float tot = sw2[grp][0] + sw2[grp][1];
    dstT[(size_t)d * T + t] = f2tf(val * rsqrtf(tot / (float)D + EPS));
}

// ================= tensor-core flash attention ===============================
#define AS 72
__global__ __launch_bounds__(128)
void attn_tc() {
    extern __shared__ unsigned usmem[];
    unsigned* Ks = usmem;
    unsigned* Vs = usmem + 64 * AS;
    unsigned* Ps = usmem + 2 * 64 * AS;
    int qt = (int)gridDim.x - 1 - (int)blockIdx.x;
    int head = blockIdx.y;
    int kvh = head >> 2;
    int tid = threadIdx.x, warp = tid >> 5, lane = tid & 31;
    int g = lane >> 2, tg = lane & 3;
    int q0 = qt * 64;
    int wq = warp * 16;

    // stage Q tile [d][row] via uint4
    {
        const unsigned* qsrc = g_qT + (size_t)head * D * T + q0;
        for (int e4 = tid; e4 < 64 * 16; e4 += 128) {
            int d = e4 >> 4, r4 = (e4 & 15) * 4;
            uint4 v = *(const uint4*)(qsrc + (size_t)d * T + r4);
            *(uint4*)&Ks[d * AS + r4] = v;
        }
    }
    __syncthreads();
    unsigned qf[8][4];
#pragma unroll
    for (int kc = 0; kc < 8; kc++) {
        qf[kc][0] = Ks[(kc * 8 + tg) * AS + wq + g];
        qf[kc][1] = Ks[(kc * 8 + tg) * AS + wq + g + 8];
        qf[kc][2] = Ks[(kc * 8 + tg + 4) * AS + wq + g];
        qf[kc][3] = Ks[(kc * 8 + tg + 4) * AS + wq + g + 8];
    }
    int r0 = q0 + wq + g, r1 = r0 + 8;
    float m0 = -INFINITY, m1 = -INFINITY, l0 = 0.f, l1 = 0.f;
    float accO[8][4] = {};

    const unsigned* ksrc = g_kT + (size_t)kvh * D * T;
    const unsigned* vsrc = g_vT + (size_t)kvh * T * D;

    for (int j0 = 0; j0 <= qt; j0++) {
        int k0 = j0 * 64;
        __syncthreads();
        for (int e4 = tid; e4 < 64 * 16; e4 += 128) {
            int d = e4 >> 4, c4 = (e4 & 15) * 4;
            uint4 v = *(const uint4*)(ksrc + (size_t)d * T + k0 + c4);
            *(uint4*)&Ks[d * AS + c4] = v;
        }
        for (int e4 = tid; e4 < 64 * 16; e4 += 128) {
            int c = e4 >> 4, d4 = (e4 & 15) * 4;
            uint4 v = *(const uint4*)(vsrc + (size_t)(k0 + c) * D + d4);
            *(uint4*)&Vs[c * AS + d4] = v;
        }
        __syncthreads();
        float sc[8][4] = {};
#pragma unroll
        for (int kc = 0; kc < 8; kc++) {
            unsigned bfr[8][2];
#pragma unroll
            for (int n = 0; n < 8; n++) {
                bfr[n][0] = Ks[(kc * 8 + tg) * AS + n * 8 + g];
                bfr[n][1] = Ks[(kc * 8 + tg + 4) * AS + n * 8 + g];
            }
#pragma unroll
            for (int n = 0; n < 8; n++) mma_tf32(sc[n], qf[kc], bfr[n]);
        }
        float mx0 = -INFINITY, mx1 = -INFINITY;
#pragma unroll
        for (int n = 0; n < 8; n++) {
            int c0 = k0 + n * 8 + 2 * tg;
            float s0 = (c0 <= r0) ? sc[n][0] * ATT_SCALE : -INFINITY;
            float s1 = (c0 + 1 <= r0) ? sc[n][1] * ATT_SCALE : -INFINITY;
            float s2 = (c0 <= r1) ? sc[n][2] * ATT_SCALE : -INFINITY;
            float s3 = (c0 + 1 <= r1) ? sc[n][3] * ATT_SCALE : -INFINITY;
            sc[n][0] = s0; sc[n][1] = s1; sc[n][2] = s2; sc[n][3] = s3;
            mx0 = fmaxf(mx0, fmaxf(s0, s1));
            mx1 = fmaxf(mx1, fmaxf(s2, s3));
        }
        mx0 = fmaxf(mx0, __shfl_xor_sync(0xffffffffu, mx0, 1));
        mx0 = fmaxf(mx0, __shfl_xor_sync(0xffffffffu, mx0, 2));
        mx1 = fmaxf(mx1, __shfl_xor_sync(0xffffffffu, mx1, 1));
        mx1 = fmaxf(mx1, __shfl_xor_sync(0xffffffffu, mx1, 2));
        float nm0 = fmaxf(m0, mx0), nm1 = fmaxf(m1, mx1);
        float corr0 = __expf(m0 - nm0), corr1 = __expf(m1 - nm1);
        m0 = nm0; m1 = nm1;
        float rs0 = 0.f, rs1 = 0.f;
#pragma unroll
        for (int n = 0; n < 8; n++) {
            int cl = n * 8 + 2 * tg;
            float p0 = __expf(sc[n][0] - nm0);
            float p1 = __expf(sc[n][1] - nm0);
            float p2 = __expf(sc[n][2] - nm1);
            float p3 = __expf(sc[n][3] - nm1);
            rs0 += p0 + p1; rs1 += p2 + p3;
            Ps[cl * AS + wq + g] = f2tf(p0);
            Ps[(cl + 1) * AS + wq + g] = f2tf(p1);
            Ps[cl * AS + wq + g + 8] = f2tf(p2);
            Ps[(cl + 1) * AS + wq + g + 8] = f2tf(p3);
        }
        rs0 += __shfl_xor_sync(0xffffffffu, rs0, 1);
        rs0 += __shfl_xor_sync(0xffffffffu, rs0, 2);
        rs1 += __shfl_xor_sync(0xffffffffu, rs1, 1);
        rs1 += __shfl_xor_sync(0xffffffffu, rs1, 2);
        l0 = l0 * corr0 + rs0;
        l1 = l1 * corr1 + rs1;
#pragma unroll
        for (int n = 0; n < 8; n++) {
            accO[n][0] *= corr0; accO[n][1] *= corr0;
            accO[n][2] *= corr1; accO[n][3] *= corr1;
        }
        __syncwarp();
#pragma unroll
        for (int kc = 0; kc < 8; kc++) {
            unsigned af[4];
            af[0] = Ps[(kc * 8 + tg) * AS + wq + g];
            af[1] = Ps[(kc * 8 + tg) * AS + wq + g + 8];
            af[2] = Ps[(kc * 8 + tg + 4) * AS + wq + g];
            af[3] = Ps[(kc * 8 + tg + 4) * AS + wq + g + 8];
#pragma unroll
            for (int n = 0; n < 8; n++) {
                unsigned bfr2[2];
                bfr2[0] = Vs[(kc * 8 + tg) * AS + n * 8 + g];
                bfr2[1] = Vs[(kc * 8 + tg + 4) * AS + n * 8 + g];
                mma_tf32(accO[n], af, bfr2);
            }
        }
    }
    float inv0 = 1.f / l0, inv1 = 1.f / l1;
#pragma unroll
    for (int n = 0; n < 8; n++) {
        int c = head * D + n * 8 + 2 * tg;
        *(float2*)&g_ao[(size_t)r0 * (NH * D) + c] =
            make_float2(accO[n][0] * inv0, accO[n][1] * inv0);
        *(float2*)&g_ao[(size_t)r1 * (NH * D) + c] =
            make_float2(accO[n][2] * inv1, accO[n][3] * inv1);
    }
}

// ---------------- launch ------------------------------------------------------
extern "C" void kernel_launch(void* const* d_in, const int* in_sizes, int n_in,
                              void* d_out, int out_size) {
    const int* pos = (const int*)d_in[0];
    const float* hidden = (const float*)d_in[1];
    const float* ln1 = (const float*)d_in[2];
    const float* ln2 = (const float*)d_in[3];
    const float* wqkv = (const float*)d_in[4];
    const float* wo = (const float*)d_in[5];
    const float* rw = (const float*)d_in[6];
    const float* wgate = (const float*)d_in[7];
    const float* wup = (const float*)d_in[8];
    const float* wdown = (const float*)d_in[9];
    const float* shg = (const float*)d_in[10];
    const float* shu = (const float*)d_in[11];
    const float* shd = (const float*)d_in[12];
    float* out = (float*)d_out;
    float* resid = out + (size_t)T * H;

    float *p_h1, *p_h2, *p_qkv, *p_ao;
    cudaGetSymbolAddress((void**)&p_h1, g_h1);
    cudaGetSymbolAddress((void**)&p_h2, g_h2);
    cudaGetSymbolAddress((void**)&p_qkv, g_qkv);
    cudaGetSymbolAddress((void**)&p_ao, g_ao);

    static int attn_smem_set = 0;
    const int ATTN_SMEM = 3 * 64 * AS * 4;
    if (!attn_smem_set) {
        cudaFuncSetAttribute(attn_tc, cudaFuncAttributeMaxDynamicSharedMemorySize, ATTN_SMEM);
        attn_smem_set = 1;
    }

    rope_table_kernel<<<256, 256>>>(pos);   // also zeroes g_count
    rmsnorm_kernel<<<T, 256>>>(hidden, ln1, p_h1);
    gemm_tf32<<<dim3(QKV_N / 128, T / 128), 256>>>(p_h1, wqkv, p_qkv, T, QKV_N, H, nullptr);
    rope_rms_kernel<<<dim3(T, 6), 256>>>();
    attn_tc<<<dim3(T / 64, NH), 128, ATTN_SMEM>>>();
    gemm_tf32<<<dim3(H / 128, T / 128), 256>>>(p_ao, wo, resid, T, H, NH * D, hidden);
    rmsnorm_router_kernel<<<T, 256>>>(resid, ln2, rw, p_h2);
    scan_kernel<<<1, 32>>>();
    scatter_kernel<<<T / 256, 256>>>();
    // all 18 MoE up-projections in one launch
    moe_proj_tf32<<<dim3(F / 128, T / 128, 2 + 2 * E), 256>>>(shg, shu, wgate, wup);
    // both down projections (silu fused) in one launch
    moe_down_tf32<<<dim3(H / 128, T / 128, 1 + E), 256>>>(shd, wdown, out);
    add_routed_kernel<<<(T * H) / 256, 256>>>(out);
    (void)in_sizes; (void)n_in; (void)out_size;
}

// round 11
// speedup vs baseline: 3.0885x; 1.0458x over previous
#include <cuda_runtime.h>
#include <math.h>

#define T 2048
#define H 1024
#define NH 16
#define NKV 4
#define D 64
#define E 8
#define F 1024
#define QKV_N ((NH + 2*NKV) * D)   // 1536
#define EPS 1e-5f
#define ATT_SCALE 0.125f

// ---------------- scratch ---------------------------------------------------
__device__ float    g_h1[T * H];
__device__ float    g_qkv[T * QKV_N];
__device__ unsigned g_qT[NH * D * T];    // tf32 bits, [head][d][t]
__device__ unsigned g_kT[NKV * D * T];   // tf32 bits, [kvh][d][t]
__device__ unsigned g_vT[NKV * T * D];   // tf32 bits, [kvh][t][d]
__device__ float    g_ao[T * NH * D];
__device__ float    g_h2[T * H];
__device__ float    g_bufA[T * F];       // shared gate
__device__ float    g_bufB[T * F];       // shared up
__device__ float    g_bufC[T * F];       // routed gate (expert-grouped rows)
__device__ float    g_bufD[T * F];       // routed up
__device__ float    g_routed[T * H];     // routed expert output (dense by token)
__device__ float2   g_cs[T * 32];        // rope cos/sin table
__device__ int      g_eidx[T];
__device__ float    g_gate[T];
__device__ int      g_perm[T];
__device__ int      g_count[E];
__device__ int      g_base[E];

// ---------------- small utility kernels -------------------------------------
// rope table (T*32 entries) + zero g_count
__global__ void rope_table_kernel(const int* __restrict__ pos) {
    int idx = blockIdx.x * blockDim.x + threadIdx.x;   // 0..65535
    if (idx < E) g_count[idx] = 0;
    int t = idx >> 5, i = idx & 31;
    float inv = powf(500000.0f, -((float)i) / 32.0f);
    float ang = (float)pos[t] * inv;
    float sn, cs;
    sincosf(ang, &sn, &cs);
    g_cs[idx] = make_float2(cs, sn);
}
// fused scan + scatter (single block; smem atomics)
__global__ void scan_scatter_kernel() {
    __shared__ int sbase[E];
    __shared__ int soffs[E];
    int tid = threadIdx.x;
    if (tid == 0) {
        int b = 0;
        for (int e = 0; e < E; e++) { sbase[e] = b; g_base[e] = b; b += g_count[e]; }
    }
    if (tid < E) soffs[tid] = 0;
    __syncthreads();
    for (int t = tid; t < T; t += 256) {
        int e = g_eidx[t];
        int p = sbase[e] + atomicAdd(&soffs[e], 1);
        g_perm[p] = t;
    }
}
// out += routed
__global__ void add_routed_kernel(float* __restrict__ out) {
    int i = blockIdx.x * blockDim.x + threadIdx.x;
    out[i] += g_routed[i];
}

// ---------------- rmsnorm (plain) -------------------------------------------
__global__ void rmsnorm_kernel(const float* __restrict__ in, const float* __restrict__ w,
                               float* __restrict__ out) {
    int row = blockIdx.x, tid = threadIdx.x;
    const float* p = in + (size_t)row * H;
    float v[4];
    float s = 0.f;
#pragma unroll
    for (int i = 0; i < 4; i++) { v[i] = p[tid + i * 256]; s += v[i] * v[i]; }
#pragma unroll
    for (int off = 16; off; off >>= 1) s += __shfl_xor_sync(0xffffffffu, s, off);
    __shared__ float sw[8];
    if ((tid & 31) == 0) sw[tid >> 5] = s;
    __syncthreads();
    __shared__ float stot;
    if (tid == 0) {
        float t2 = 0.f;
        for (int i = 0; i < 8; i++) t2 += sw[i];
        stot = t2;
    }
    __syncthreads();
    float r = rsqrtf(stot / (float)H + EPS);
    float* o = out + (size_t)row * H;
#pragma unroll
    for (int i = 0; i < 4; i++) o[tid + i * 256] = v[i] * r * w[tid + i * 256];
}

// ---------------- rmsnorm2 + router fused -----------------------------------
__global__ void rmsnorm_router_kernel(const float* __restrict__ in,
                                      const float* __restrict__ w,
                                      const float* __restrict__ rw,
                                      float* __restrict__ out) {
    int row = blockIdx.x, tid = threadIdx.x;
    const float* p = in + (size_t)row * H;
    float v[4];
    float s = 0.f;
#pragma unroll
    for (int i = 0; i < 4; i++) { v[i] = p[tid + i * 256]; s += v[i] * v[i]; }
#pragma unroll
    for (int off = 16; off; off >>= 1) s += __shfl_xor_sync(0xffffffffu, s, off);
    __shared__ float sw[8];
    if ((tid & 31) == 0) sw[tid >> 5] = s;
    __syncthreads();
    __shared__ float stot;
    if (tid == 0) {
        float t2 = 0.f;
        for (int i = 0; i < 8; i++) t2 += sw[i];
        stot = t2;
    }
    __syncthreads();
    float r = rsqrtf(stot / (float)H + EPS);
    float* o = out + (size_t)row * H;
    float acc[E] = {};
#pragma unroll
    for (int i = 0; i < 4; i++) {
        int h = tid + i * 256;
        float hv = v[i] * r * w[h];
        o[h] = hv;
        const float* rr = rw + (size_t)h * E;
#pragma unroll
        for (int e = 0; e < E; e++) acc[e] += hv * rr[e];
    }
#pragma unroll
    for (int e = 0; e < E; e++)
#pragma unroll
        for (int off = 16; off; off >>= 1)
            acc[e] += __shfl_xor_sync(0xffffffffu, acc[e], off);
    __shared__ float sred[8][E];
    int wp = tid >> 5, lane = tid & 31;
    if (lane == 0)
        for (int e = 0; e < E; e++) sred[wp][e] = acc[e];
    __syncthreads();
    if (tid == 0) {
        float best = -INFINITY;
        int bi = 0;
        for (int e = 0; e < E; e++) {
            float vv = 0.f;
            for (int ww = 0; ww < 8; ww++) vv += sred[ww][e];
            if (vv > best) { best = vv; bi = e; }
        }
        g_eidx[row] = bi;
        g_gate[row] = 1.f / (1.f + expf(-best));
        atomicAdd(&g_count[bi], 1);
    }
}

// =================== TF32 tensor-core machinery ==============================
__device__ __forceinline__ unsigned f2tf(float x) {
    unsigned r;
    asm("cvt.rna.tf32.f32 %0, %1;" : "=r"(r) : "f"(x));
    return r;
}
__device__ __forceinline__ void mma_tf32(float* c, const unsigned* a, const unsigned* b) {
    asm volatile(
        "mma.sync.aligned.m16n8k8.row.col.f32.tf32.tf32.f32 "
        "{%0,%1,%2,%3},{%4,%5,%6,%7},{%8,%9},{%0,%1,%2,%3};"
        : "+f"(c[0]), "+f"(c[1]), "+f"(c[2]), "+f"(c[3])
        : "r"(a[0]), "r"(a[1]), "r"(a[2]), "r"(a[3]), "r"(b[0]), "r"(b[1]));
}
__device__ __forceinline__ void cp16(unsigned smem_addr, const void* gptr) {
    asm volatile("cp.async.ca.shared.global [%0], [%1], 16;" :: "r"(smem_addr), "l"(gptr));
}
#define CP_COMMIT() asm volatile("cp.async.commit_group;")
#define CP_WAIT0()  asm volatile("cp.async.wait_group 0;")

#define KT 16
#define SMS 136

#define MMA_TILE_COMPUTE(Asb, Bsb)                                             \
    _Pragma("unroll")                                                          \
    for (int k8 = 0; k8 < KT; k8 += 8) {                                       \
        unsigned af[4][4], bf[4][2];                                           \
        _Pragma("unroll")                                                      \
        for (int mt = 0; mt < 4; mt++) {                                       \
            int mb = wm + mt * 16;                                             \
            af[mt][0] = Asb[(k8 + tg) * SMS + mb + g];                         \
            af[mt][1] = Asb[(k8 + tg) * SMS + mb + g + 8];                     \
            af[mt][2] = Asb[(k8 + tg + 4) * SMS + mb + g];                     \
            af[mt][3] = Asb[(k8 + tg + 4) * SMS + mb + g + 8];                 \
        }                                                                      \
        _Pragma("unroll")                                                      \
        for (int nt2 = 0; nt2 < 4; nt2++) {                                    \
            int nb = wn + nt2 * 8;                                             \
            bf[nt2][0] = Bsb[(k8 + tg) * SMS + nb + g];                        \
            bf[nt2][1] = Bsb[(k8 + tg + 4) * SMS + nb + g];                    \
        }                                                                      \
        _Pragma("unroll")                                                      \
        for (int mt = 0; mt < 4; mt++)                                         \
            _Pragma("unroll")                                                  \
            for (int nt2 = 0; nt2 < 4; nt2++)                                  \
                mma_tf32(acc[mt][nt2], af[mt], bf[nt2]);                       \
    }

#define FILL_A(dst, v0, v1, scale)                                             \
    do {                                                                       \
        (dst)[(acol + 0) * SMS + arow] = f2tf((v0).x * (scale));               \
        (dst)[(acol + 1) * SMS + arow] = f2tf((v0).y * (scale));               \
        (dst)[(acol + 2) * SMS + arow] = f2tf((v0).z * (scale));               \
        (dst)[(acol + 3) * SMS + arow] = f2tf((v0).w * (scale));               \
        (dst)[(acol + 4) * SMS + arow] = f2tf((v1).x * (scale));               \
        (dst)[(acol + 5) * SMS + arow] = f2tf((v1).y * (scale));               \
        (dst)[(acol + 6) * SMS + arow] = f2tf((v1).z * (scale));               \
        (dst)[(acol + 7) * SMS + arow] = f2tf((v1).w * (scale));               \
    } while (0)

// silu(gate)*up fused A-fill (moe_down)
#define SILU1(x) ((x) / (1.f + __expf(-(x))))
#define FILL_A_SILU(dst, gv0, gv1, uv0, uv1, mask)                             \
    do {                                                                       \
        (dst)[(acol + 0) * SMS + arow] = f2tf(SILU1((gv0).x) * (uv0).x * (mask)); \
        (dst)[(acol + 1) * SMS + arow] = f2tf(SILU1((gv0).y) * (uv0).y * (mask)); \
        (dst)[(acol + 2) * SMS + arow] = f2tf(SILU1((gv0).z) * (uv0).z * (mask)); \
        (dst)[(acol + 3) * SMS + arow] = f2tf(SILU1((gv0).w) * (uv0).w * (mask)); \
        (dst)[(acol + 4) * SMS + arow] = f2tf(SILU1((gv1).x) * (uv1).x * (mask)); \
        (dst)[(acol + 5) * SMS + arow] = f2tf(SILU1((gv1).y) * (uv1).y * (mask)); \
        (dst)[(acol + 6) * SMS + arow] = f2tf(SILU1((gv1).z) * (uv1).z * (mask)); \
        (dst)[(acol + 7) * SMS + arow] = f2tf(SILU1((gv1).w) * (uv1).w * (mask)); \
    } while (0)

#define FILL_B(dst, v0, v1)                                                    \
    do {                                                                       \
        unsigned* bd_ = (dst) + bk * SMS + bn;                                 \
        bd_[0] = f2tf((v0).x); bd_[1] = f2tf((v0).y);                          \
        bd_[2] = f2tf((v0).z); bd_[3] = f2tf((v0).w);                          \
        bd_[4] = f2tf((v1).x); bd_[5] = f2tf((v1).y);                          \
        bd_[6] = f2tf((v1).z); bd_[7] = f2tf((v1).w);                          \
    } while (0)

// ---------------- dense tf32 GEMM -------------------------------------------
__global__ __launch_bounds__(256)
void gemm_tf32(const float* __restrict__ A, const float* __restrict__ B,
               float* __restrict__ C, int M, int N, int K,
               const float* __restrict__ addsrc) {
    __shared__ unsigned As[2][KT * SMS];
    __shared__ unsigned Bs[2][KT * SMS];
    int tid = threadIdx.x;
    int warp = tid >> 5, lane = tid & 31;
    int g = lane >> 2, tg = lane & 3;
    int wm = (warp >> 2) * 64, wn = (warp & 3) * 32;
    int m0 = blockIdx.y * 128, n0 = blockIdx.x * 128;
    int arow = tid >> 1, acol = (tid & 1) * 8;
    int bk = tid >> 4, bn = (tid & 15) * 8;
    const float* Ap = A + (size_t)(m0 + arow) * K + acol;
    const float* Bp = B + (size_t)bk * N + n0 + bn;
    float acc[4][4][4] = {};

    float4 av0 = *(const float4*)Ap, av1 = *(const float4*)(Ap + 4);
    float4 bv0 = *(const float4*)Bp, bv1 = *(const float4*)(Bp + 4);
    FILL_A(As[0], av0, av1, 1.f);
    FILL_B(Bs[0], bv0, bv1);
    __syncthreads();
    int nt = K / KT;
    int buf = 0;
    for (int kt = 0; kt < nt; kt++) {
        if (kt + 1 < nt) {
            av0 = *(const float4*)(Ap + (kt + 1) * KT);
            av1 = *(const float4*)(Ap + (kt + 1) * KT + 4);
            bv0 = *(const float4*)(Bp + (size_t)(kt + 1) * KT * N);
            bv1 = *(const float4*)(Bp + (size_t)(kt + 1) * KT * N + 4);
        }
        const unsigned* Asb = As[buf];
        const unsigned* Bsb = Bs[buf];
        MMA_TILE_COMPUTE(Asb, Bsb)
        if (kt + 1 < nt) {
            FILL_A(As[buf ^ 1], av0, av1, 1.f);
            FILL_B(Bs[buf ^ 1], bv0, bv1);
        }
        __syncthreads();
        buf ^= 1;
    }
#pragma unroll
    for (int mt = 0; mt < 4; mt++) {
#pragma unroll
        for (int nt2 = 0; nt2 < 4; nt2++) {
            int r0 = m0 + wm + mt * 16 + g;
            int c = n0 + wn + nt2 * 8 + 2 * tg;
            float2 v0 = make_float2(acc[mt][nt2][0], acc[mt][nt2][1]);
            float2 v1 = make_float2(acc[mt][nt2][2], acc[mt][nt2][3]);
            if (addsrc) {
                float2 r = *(const float2*)(addsrc + (size_t)r0 * N + c);
                v0.x += r.x; v0.y += r.y;
                float2 r2 = *(const float2*)(addsrc + (size_t)(r0 + 8) * N + c);
                v1.x += r2.x; v1.y += r2.y;
            }
            *(float2*)(C + (size_t)r0 * N + c) = v0;
            *(float2*)(C + (size_t)(r0 + 8) * N + c) = v1;
        }
    }
}

// ------------- MoE up-projections mega-GEMM (z = 0..17) ---------------------
__global__ __launch_bounds__(256)
void moe_proj_tf32(const float* __restrict__ shg, const float* __restrict__ shu,
                   const float* __restrict__ wgate, const float* __restrict__ wup) {
    int z = blockIdx.z;
    int m0 = blockIdx.y * 128;
    int cnt, obase;
    const float* B;
    float* Cbuf;
    bool gathered;
    if (z < 2) {
        B = z ? shu : shg;
        Cbuf = z ? g_bufB : g_bufA;
        cnt = T; obase = 0; gathered = false;
    } else {
        int e = (z - 2) >> 1, kind = (z - 2) & 1;
        cnt = g_count[e];
        if (m0 >= cnt) return;
        B = (kind ? wup : wgate) + (size_t)e * H * F;
        Cbuf = kind ? g_bufD : g_bufC;
        obase = g_base[e]; gathered = true;
    }
    int n0 = blockIdx.x * 128;
    __shared__ unsigned As[2][KT * SMS];
    __shared__ unsigned Bs[2][KT * SMS];
    __shared__ int srcrow[128];
    int tid = threadIdx.x;
    if (tid < 128) {
        int mm = m0 + tid;
        srcrow[tid] = gathered ? ((mm < cnt) ? g_perm[obase + mm] : -1) : mm;
    }
    __syncthreads();
    int warp = tid >> 5, lane = tid & 31;
    int g = lane >> 2, tg = lane & 3;
    int wm = (warp >> 2) * 64, wn = (warp & 3) * 32;
    int arow = tid >> 1, acol = (tid & 1) * 8;
    int bk = tid >> 4, bn = (tid & 15) * 8;
    int tok = srcrow[arow];
    float gsc = gathered ? ((tok >= 0) ? g_gate[tok] : 0.f) : 1.f;
    const float* Ap = g_h2 + (size_t)((tok >= 0) ? tok : 0) * H + acol;
    const float* Bp = B + (size_t)bk * F + n0 + bn;
    float acc[4][4][4] = {};

    float4 av0 = *(const float4*)Ap, av1 = *(const float4*)(Ap + 4);
    float4 bv0 = *(const float4*)Bp, bv1 = *(const float4*)(Bp + 4);
    FILL_A(As[0], av0, av1, gsc);
    FILL_B(Bs[0], bv0, bv1);
    __syncthreads();
    int nt = H / KT;
    int buf = 0;
    for (int kt = 0; kt < nt; kt++) {
        if (kt + 1 < nt) {
            av0 = *(const float4*)(Ap + (kt + 1) * KT);
            av1 = *(const float4*)(Ap + (kt + 1) * KT + 4);
            bv0 = *(const float4*)(Bp + (size_t)(kt + 1) * KT * F);
            bv1 = *(const float4*)(Bp + (size_t)(kt + 1) * KT * F + 4);
        }
        const unsigned* Asb = As[buf];
        const unsigned* Bsb = Bs[buf];
        MMA_TILE_COMPUTE(Asb, Bsb)
        if (kt + 1 < nt) {
            FILL_A(As[buf ^ 1], av0, av1, gsc);
            FILL_B(Bs[buf ^ 1], bv0, bv1);
        }
        __syncthreads();
        buf ^= 1;
    }
#pragma unroll
    for (int mt = 0; mt < 4; mt++) {
#pragma unroll
        for (int nt2 = 0; nt2 < 4; nt2++) {
            int mi0 = wm + mt * 16 + g;
            int c = n0 + wn + nt2 * 8 + 2 * tg;
            if (m0 + mi0 < cnt)
                *(float2*)(Cbuf + (size_t)(obase + m0 + mi0) * F + c) =
                    make_float2(acc[mt][nt2][0], acc[mt][nt2][1]);
            if (m0 + mi0 + 8 < cnt)
                *(float2*)(Cbuf + (size_t)(obase + m0 + mi0 + 8) * F + c) =
                    make_float2(acc[mt][nt2][2], acc[mt][nt2][3]);
        }
    }
}

// ------------- MoE down-projections mega-GEMM (z = 0..8), silu fused --------
__global__ __launch_bounds__(256, 2)
void moe_down_tf32(const float* __restrict__ shd, const float* __restrict__ wdown,
                   float* __restrict__ out) {
    int z = blockIdx.z;
    int m0 = blockIdx.y * 128;
    int cnt, abase;
    const float* B;
    const float* Agate;
    const float* Aup;
    float* Dst;
    if (z == 0) {
        cnt = T; abase = 0;
        B = shd; Agate = g_bufA; Aup = g_bufB; Dst = out;
    } else {
        int e = z - 1;
        cnt = g_count[e];
        if (m0 >= cnt) return;
        abase = g_base[e];
        B = wdown + (size_t)e * F * H;
        Agate = g_bufC; Aup = g_bufD; Dst = g_routed;
    }
    int n0 = blockIdx.x * 128;
    __shared__ unsigned As[2][KT * SMS];
    __shared__ unsigned Bs[2][KT * SMS];
    __shared__ int rtok[128];
    int tid = threadIdx.x;
    if (tid < 128) {
        int mm = m0 + tid;
        rtok[tid] = (z == 0) ? mm : ((mm < cnt) ? g_perm[abase + mm] : -1);
    }
    __syncthreads();
    int warp = tid >> 5, lane = tid & 31;
    int g = lane >> 2, tg = lane & 3;
    int wm = (warp >> 2) * 64, wn = (warp & 3) * 32;
    int arow = tid >> 1, acol = (tid & 1) * 8;
    int bk = tid >> 4, bn = (tid & 15) * 8;
    bool arow_ok = (m0 + arow) < cnt;
    float amask = arow_ok ? 1.f : 0.f;
    size_t aoff = (size_t)(abase + (arow_ok ? (m0 + arow) : 0)) * F + acol;
    const float* Apg = Agate + aoff;
    const float* Apu = Aup + aoff;
    const float* Bp = B + (size_t)bk * H + n0 + bn;
    float acc[4][4][4] = {};

    float4 gv0 = *(const float4*)Apg, gv1 = *(const float4*)(Apg + 4);
    float4 uv0 = *(const float4*)Apu, uv1 = *(const float4*)(Apu + 4);
    float4 bv0 = *(const float4*)Bp, bv1 = *(const float4*)(Bp + 4);
    FILL_A_SILU(As[0], gv0, gv1, uv0, uv1, amask);
    FILL_B(Bs[0], bv0, bv1);
    __syncthreads();
    int nt = F / KT;
    int buf = 0;
    for (int kt = 0; kt < nt; kt++) {
        if (kt + 1 < nt) {
            gv0 = *(const float4*)(Apg + (kt + 1) * KT);
            gv1 = *(const float4*)(Apg + (kt + 1) * KT + 4);
            uv0 = *(const float4*)(Apu + (kt + 1) * KT);
            uv1 = *(const float4*)(Apu + (kt + 1) * KT + 4);
            bv0 = *(const float4*)(Bp + (size_t)(kt + 1) * KT * H);
            bv1 = *(const float4*)(Bp + (size_t)(kt + 1) * KT * H + 4);
        }
        const unsigned* Asb = As[buf];
        const unsigned* Bsb = Bs[buf];
        MMA_TILE_COMPUTE(Asb, Bsb)
        if (kt + 1 < nt) {
            FILL_A_SILU(As[buf ^ 1], gv0, gv1, uv0, uv1, amask);
            FILL_B(Bs[buf ^ 1], bv0, bv1);
        }
        __syncthreads();
        buf ^= 1;
    }
#pragma unroll
    for (int mt = 0; mt < 4; mt++) {
#pragma unroll
        for (int nt2 = 0; nt2 < 4; nt2++) {
            int mi0 = wm + mt * 16 + g;
            int c = n0 + wn + nt2 * 8 + 2 * tg;
            if (m0 + mi0 < cnt) {
                int t = rtok[mi0];
                *(float2*)(Dst + (size_t)t * H + c) =
                    make_float2(acc[mt][nt2][0], acc[mt][nt2][1]);
            }
            if (m0 + mi0 + 8 < cnt) {
                int t = rtok[mi0 + 8];
                *(float2*)(Dst + (size_t)t * H + c) =
                    make_float2(acc[mt][nt2][2], acc[mt][nt2][3]);
            }
        }
    }
}

// ---------------- rope + rms + COALESCED transpose --------------------------
// grid (T/32, 24): y<20 → rope+rms for head y (q:0..15, k:16..19), 32 tokens/block
//                  y>=20 → V tf32 convert for kvh = y-20
__global__ void rope_rms_kernel() {
    int t0 = blockIdx.x * 32;
    int h = blockIdx.y;
    int tid = threadIdx.x;
    if (h >= NH + NKV) {
        int kh = h - NH - NKV;
        const float* src = g_qkv + NH * D + NKV * D + kh * D;  // offset within row
#pragma unroll
        for (int i = 0; i < 8; i++) {
            int e = tid + i * 256;               // 0..2047
            int tl = e >> 6, d = e & 63;
            float v = src[(size_t)(t0 + tl) * QKV_N + d];
            g_vT[((size_t)kh * T + t0 + tl) * D + d] = f2tf(v);
        }
        return;
    }
    const float* src;
    unsigned* dstT;
    if (h < NH) {
        src = g_qkv + h * D;
        dstT = g_qT + (size_t)h * D * T;
    } else {
        src = g_qkv + NH * D + (h - NH) * D;
        dstT = g_kT + (size_t)(h - NH) * D * T;
    }
    __shared__ float rows[32][65];
    __shared__ float psum[32][8];
    // load 32 tokens x 64 dims (coalesced)
#pragma unroll
    for (int i = 0; i < 8; i++) {
        int e = tid + i * 256;
        int tl = e >> 6, d = e & 63;
        rows[tl][d] = src[(size_t)(t0 + tl) * QKV_N + d];
    }
    __syncthreads();
    // compute: thread = (token tl = tid>>3, dims dbase..dbase+7)
    int tl = tid >> 3;
    int dbase = (tid & 7) * 8;
    float vals[8];
    float sq = 0.f;
#pragma unroll
    for (int j = 0; j < 8; j++) {
        int d = dbase + j;
        int i = d & 31;
        float2 cspair = g_cs[(t0 + tl) * 32 + i];
        float x1 = rows[tl][i], x2 = rows[tl][i + 32];
        float val = (d < 32) ? (x1 * cspair.x - x2 * cspair.y)
                             : (x2 * cspair.x + x1 * cspair.y);
        vals[j] = val;
        sq += val * val;
    }
    psum[tl][tid & 7] = sq;
    __syncthreads();
    float tot = 0.f;
#pragma unroll
    for (int k = 0; k < 8; k++) tot += psum[tl][k];
    float r = rsqrtf(tot / (float)D + EPS);
#pragma unroll
    for (int j = 0; j < 8; j++) rows[tl][dbase + j] = vals[j] * r;
    __syncthreads();
    // coalesced transposed write: lane covers consecutive t for fixed d
#pragma unroll
    for (int i = 0; i < 8; i++) {
        int e = tid + i * 256;
        int d = e >> 5, tcol = e & 31;
        dstT[(size_t)d * T + t0 + tcol] = f2tf(rows[tcol][d]);
    }
}

// ================= tensor-core flash attention (cp.async pipelined) ==========
#define AS 72
__global__ __launch_bounds__(128)
void attn_tc() {
    extern __shared__ unsigned usmem[];
    unsigned* Ks0 = usmem;
    unsigned* Ks1 = usmem + 64 * AS;
    unsigned* Vs0 = usmem + 2 * 64 * AS;
    unsigned* Vs1 = usmem + 3 * 64 * AS;
    unsigned* Ps  = usmem + 4 * 64 * AS;
    int qt = (int)gridDim.x - 1 - (int)blockIdx.x;
    int head = blockIdx.y;
    int kvh = head >> 2;
    int tid = threadIdx.x, warp = tid >> 5, lane = tid & 31;
    int g = lane >> 2, tg = lane & 3;
    int q0 = qt * 64;
    int wq = warp * 16;

    const unsigned* ksrc = g_kT + (size_t)kvh * D * T;
    const unsigned* vsrc = g_vT + (size_t)kvh * T * D;

    // stage Q tile [d][row] into Ks0, lift fragments, then reuse Ks0
    {
        const unsigned* qsrc = g_qT + (size_t)head * D * T + q0;
        for (int e4 = tid; e4 < 64 * 16; e4 += 128) {
            int d = e4 >> 4, r4 = (e4 & 15) * 4;
            uint4 v = *(const uint4*)(qsrc + (size_t)d * T + r4);
            *(uint4*)&Ks0[d * AS + r4] = v;
        }
    }
    __syncthreads();
    unsigned qf[8][4];
#pragma unroll
    for (int kc = 0; kc < 8; kc++) {
        qf[kc][0] = Ks0[(kc * 8 + tg) * AS + wq + g];
        qf[kc][1] = Ks0[(kc * 8 + tg) * AS + wq + g + 8];
        qf[kc][2] = Ks0[(kc * 8 + tg + 4) * AS + wq + g];
        qf[kc][3] = Ks0[(kc * 8 + tg + 4) * AS + wq + g + 8];
    }
    __syncthreads();   // all warps done reading Q from Ks0 before tile-0 copy lands

    int r0 = q0 + wq + g, r1 = r0 + 8;
    float m0 = -INFINITY, m1 = -INFINITY, l0 = 0.f, l1 = 0.f;
    float accO[8][4] = {};

    // issue tile 0 into buffer 0
    {
        for (int e4 = tid; e4 < 64 * 16; e4 += 128) {
            int d = e4 >> 4, c4 = (e4 & 15) * 4;
            cp16((unsigned)__cvta_generic_to_shared(&Ks0[d * AS + c4]),
                 ksrc + (size_t)d * T + c4);
        }
        for (int e4 = tid; e4 < 64 * 16; e4 += 128) {
            int c = e4 >> 4, d4 = (e4 & 15) * 4;
            cp16((unsigned)__cvta_generic_to_shared(&Vs0[c * AS + d4]),
                 vsrc + (size_t)c * D + d4);
        }
        CP_COMMIT();
    }

    int buf = 0;
    for (int j0 = 0; j0 <= qt; j0++) {
        int k0 = j0 * 64;
        CP_WAIT0();
        __syncthreads();
        // prefetch next tile into the other buffer (overlaps with compute)
        if (j0 < qt) {
            unsigned* Kn = buf ? Ks0 : Ks1;
            unsigned* Vn = buf ? Vs0 : Vs1;
            int kn = k0 + 64;
            for (int e4 = tid; e4 < 64 * 16; e4 += 128) {
                int d = e4 >> 4, c4 = (e4 & 15) * 4;
                cp16((unsigned)__cvta_generic_to_shared(&Kn[d * AS + c4]),
                     ksrc + (size_t)d * T + kn + c4);
            }
            for (int e4 = tid; e4 < 64 * 16; e4 += 128) {
                int c = e4 >> 4, d4 = (e4 & 15) * 4;
                cp16((unsigned)__cvta_generic_to_shared(&Vn[c * AS + d4]),
                     vsrc + (size_t)(kn + c) * D + d4);
            }
            CP_COMMIT();
        }
        const unsigned* Kb = buf ? Ks1 : Ks0;
        const unsigned* Vb = buf ? Vs1 : Vs0;
        // S = Q K^T
        float sc[8][4] = {};
#pragma unroll
        for (int kc = 0; kc < 8; kc++) {
            unsigned bfr[8][2];
#pragma unroll
            for (int n = 0; n < 8; n++) {
                bfr[n][0] = Kb[(kc * 8 + tg) * AS + n * 8 + g];
                bfr[n][1] = Kb[(kc * 8 + tg + 4) * AS + n * 8 + g];
            }
#pragma unroll
            for (int n = 0; n < 8; n++) mma_tf32(sc[n], qf[kc], bfr[n]);
        }
        // mask + online softmax
        float mx0 = -INFINITY, mx1 = -INFINITY;
#pragma unroll
        for (int n = 0; n < 8; n++) {
            int c0 = k0 + n * 8 + 2 * tg;
            float s0 = (c0 <= r0) ? sc[n][0] * ATT_SCALE : -INFINITY;
            float s1 = (c0 + 1 <= r0) ? sc[n][1] * ATT_SCALE : -INFINITY;
            float s2 = (c0 <= r1) ? sc[n][2] * ATT_SCALE : -INFINITY;
            float s3 = (c0 + 1 <= r1) ? sc[n][3] * ATT_SCALE : -INFINITY;
            sc[n][0] = s0; sc[n][1] = s1; sc[n][2] = s2; sc[n][3] = s3;
            mx0 = fmaxf(mx0, fmaxf(s0, s1));
            mx1 = fmaxf(mx1, fmaxf(s2, s3));
        }
        mx0 = fmaxf(mx0, __shfl_xor_sync(0xffffffffu, mx0, 1));
        mx0 = fmaxf(mx0, __shfl_xor_sync(0xffffffffu, mx0, 2));
        mx1 = fmaxf(mx1, __shfl_xor_sync(0xffffffffu, mx1, 1));
        mx1 = fmaxf(mx1, __shfl_xor_sync(0xffffffffu, mx1, 2));
        float nm0 = fmaxf(m0, mx0), nm1 = fmaxf(m1, mx1);
        float corr0 = __expf(m0 - nm0), corr1 = __expf(m1 - nm1);
        m0 = nm0; m1 = nm1;
        float rs0 = 0.f, rs1 = 0.f;
#pragma unroll
        for (int n = 0; n < 8; n++) {
            int cl = n * 8 + 2 * tg;
            float p0 = __expf(sc[n][0] - nm0);
            float p1 = __expf(sc[n][1] - nm0);
            float p2 = __expf(sc[n][2] - nm1);
            float p3 = __expf(sc[n][3] - nm1);
            rs0 += p0 + p1; rs1 += p2 + p3;
            Ps[cl * AS + wq + g] = f2tf(p0);
            Ps[(cl + 1) * AS + wq + g] = f2tf(p1);
            Ps[cl * AS + wq + g + 8] = f2tf(p2);
            Ps[(cl + 1) * AS + wq + g + 8] = f2tf(p3);
        }
        rs0 += __shfl_xor_sync(0xffffffffu, rs0, 1);
        rs0 += __shfl_xor_sync(0xffffffffu, rs0, 2);
        rs1 += __shfl_xor_sync(0xffffffffu, rs1, 1);
        rs1 += __shfl_xor_sync(0xffffffffu, rs1, 2);
        l0 = l0 * corr0 + rs0;
        l1 = l1 * corr1 + rs1;
#pragma unroll
        for (int n = 0; n < 8; n++) {
            accO[n][0] *= corr0; accO[n][1] *= corr0;
            accO[n][2] *= corr1; accO[n][3] *= corr1;
        }
        __syncwarp();   // Ps region is per-warp; warp-local fence suffices
        // O += P V
#pragma unroll
        for (int kc = 0; kc < 8; kc++) {
            unsigned af[4];
            af[0] = Ps[(kc * 8 + tg) * AS + wq + g];
            af[1] = Ps[(kc * 8 + tg) * AS + wq + g + 8];
            af[2] = Ps[(kc * 8 + tg + 4) * AS + wq + g];
            af[3] = Ps[(kc * 8 + tg + 4) * AS + wq + g + 8];
#pragma unroll
            for (int n = 0; n < 8; n++) {
                unsigned bfr2[2];
                bfr2[0] = Vb[(kc * 8 + tg) * AS + n * 8 + g];
                bfr2[1] = Vb[(kc * 8 + tg + 4) * AS + n * 8 + g];
                mma_tf32(accO[n], af, bfr2);
            }
        }
        buf ^= 1;
    }
    float inv0 = 1.f / l0, inv1 = 1.f / l1;
#pragma unroll
    for (int n = 0; n < 8; n++) {
        int c = head * D + n * 8 + 2 * tg;
        *(float2*)&g_ao[(size_t)r0 * (NH * D) + c] =
            make_float2(accO[n][0] * inv0, accO[n][1] * inv0);
        *(float2*)&g_ao[(size_t)r1 * (NH * D) + c] =
            make_float2(accO[n][2] * inv1, accO[n][3] * inv1);
    }
}

// ---------------- launch ------------------------------------------------------
extern "C" void kernel_launch(void* const* d_in, const int* in_sizes, int n_in,
                              void* d_out, int out_size) {
    const int* pos = (const int*)d_in[0];
    const float* hidden = (const float*)d_in[1];
    const float* ln1 = (const float*)d_in[2];
    const float* ln2 = (const float*)d_in[3];
    const float* wqkv = (const float*)d_in[4];
    const float* wo = (const float*)d_in[5];
    const float* rw = (const float*)d_in[6];
    const float* wgate = (const float*)d_in[7];
    const float* wup = (const float*)d_in[8];
    const float* wdown = (const float*)d_in[9];
    const float* shg = (const float*)d_in[10];
    const float* shu = (const float*)d_in[11];
    const float* shd = (const float*)d_in[12];
    float* out = (float*)d_out;
    float* resid = out + (size_t)T * H;

    float *p_h1, *p_h2, *p_qkv, *p_ao;
    cudaGetSymbolAddress((void**)&p_h1, g_h1);
    cudaGetSymbolAddress((void**)&p_h2, g_h2);
    cudaGetSymbolAddress((void**)&p_qkv, g_qkv);
    cudaGetSymbolAddress((void**)&p_ao, g_ao);

    static int attn_smem_set = 0;
    const int ATTN_SMEM = 5 * 64 * AS * 4;   // 92160 B (K x2, V x2, P)
    if (!attn_smem_set) {
        cudaFuncSetAttribute(attn_tc, cudaFuncAttributeMaxDynamicSharedMemorySize, ATTN_SMEM);
        attn_smem_set = 1;
    }

    rope_table_kernel<<<256, 256>>>(pos);   // also zeroes g_count
    rmsnorm_kernel<<<T, 256>>>(hidden, ln1, p_h1);
    gemm_tf32<<<dim3(QKV_N / 128, T / 128), 256>>>(p_h1, wqkv, p_qkv, T, QKV_N, H, nullptr);
    rope_rms_kernel<<<dim3(T / 32, NH + 2 * NKV), 256>>>();
    attn_tc<<<dim3(T / 64, NH), 128, ATTN_SMEM>>>();
    gemm_tf32<<<dim3(H / 128, T / 128), 256>>>(p_ao, wo, resid, T, H, NH * D, hidden);
    rmsnorm_router_kernel<<<T, 256>>>(resid, ln2, rw, p_h2);
    scan_scatter_kernel<<<1, 256>>>();
    // all 18 MoE up-projections in one launch
    moe_proj_tf32<<<dim3(F / 128, T / 128, 2 + 2 * E), 256>>>(shg, shu, wgate, wup);
    // both down projections (silu fused) in one launch
    moe_down_tf32<<<dim3(H / 128, T / 128, 1 + E), 256>>>(shd, wdown, out);
    add_routed_kernel<<<(T * H) / 256, 256>>>(out);
    (void)in_sizes; (void)n_in; (void)out_size;
}